// round 10
// baseline (speedup 1.0000x reference)
#include <cuda_runtime.h>
#include <cuda_bf16.h>
#include <cstdint>

// out = Wlat^T X  +  sigmoid(gate) * softmax(X Wa X^T) X Wb
//   Wa[k][n] = sum_e Wq[e,k] Wk[e,n] / 16    (bf16 fragment-packed, g_Wa4)
//   Wb[k][n] = sum_e Wo[n,e] Wv[e,k]         (bf16 fragment-packed, g_Wb4)
// Big GEMMs: bf16 m16n8k16, weight fragments shared across a token PAIR per
// warp. S=Y*X^T and Z=A*X: tf32 m16n8k8. Residual exact fp32.
// 4 warps/CTA, 2 tokens/warp -> 8 tokens/CTA, grid 2048, 1 CTA/SM.

#define THREADS 128
#define SXR 260        // X smem row stride (fp32)
#define XTOK 3380      // 13*260
#define SCB 72         // chunk buffer stride
#define CBTOK 1152     // 16*72
#define SAT 20         // attn stride
#define ATOK 320       // 16*20

#define SM_X 0                 // 8*3380 = 27040 floats
#define SM_P 27040             // 1024 uint4 = 4096 floats (2 panel buffers)
#define SM_C 31136             // 8*1152 = 9216
#define SM_A 40352             // 8*320 = 2560
#define SM_W 42912             // 320
#define SMEM_FLOATS 43232
#define SMEM_BYTES (SMEM_FLOATS * 4)   // 172928

// Wa: 32 panels (nc*8+kp), panel = 32K x 64N bf16 = 256 uint4
// Wb: 16 panels (nh*8+dc*2+kp2), panel = 32K x 128N bf16 = 512 uint4
__device__ uint4 g_Wa4[32 * 256];
__device__ uint4 g_Wb4[16 * 512];

__device__ __forceinline__ uint32_t f2tf(float x) {
    uint32_t r;
    asm("cvt.rna.tf32.f32 %0, %1;" : "=r"(r) : "f"(x));
    return r;
}
__device__ __forceinline__ float f2tff(float x) {
    return __uint_as_float(f2tf(x));
}
// pack two consecutive fp32 (smem) into bf16x2 {lo=p[0], hi=p[1]}
__device__ __forceinline__ uint32_t pk2(const float* p) {
    float2 v = *(const float2*)p;
    uint32_t r;
    asm("cvt.rn.bf16x2.f32 %0, %1, %2;" : "=r"(r) : "f"(v.y), "f"(v.x));
    return r;
}

__device__ __forceinline__ void mma8(float* d,
                                     uint32_t a0, uint32_t a1, uint32_t a2, uint32_t a3,
                                     uint32_t b0, uint32_t b1) {
    asm volatile(
        "mma.sync.aligned.m16n8k8.row.col.f32.tf32.tf32.f32 "
        "{%0,%1,%2,%3},{%4,%5,%6,%7},{%8,%9},{%0,%1,%2,%3};\n"
        : "+f"(d[0]), "+f"(d[1]), "+f"(d[2]), "+f"(d[3])
        : "r"(a0), "r"(a1), "r"(a2), "r"(a3), "r"(b0), "r"(b1));
}
__device__ __forceinline__ void mmab(float* d,
                                     uint32_t a0, uint32_t a1, uint32_t a2, uint32_t a3,
                                     uint32_t b0, uint32_t b1) {
    asm volatile(
        "mma.sync.aligned.m16n8k16.row.col.f32.bf16.bf16.f32 "
        "{%0,%1,%2,%3},{%4,%5,%6,%7},{%8,%9},{%0,%1,%2,%3};\n"
        : "+f"(d[0]), "+f"(d[1]), "+f"(d[2]), "+f"(d[3])
        : "r"(a0), "r"(a1), "r"(a2), "r"(a3), "r"(b0), "r"(b1));
}

// ------------------------------- setup --------------------------------------
__global__ void lc_setup(const float* __restrict__ Wq, const float* __restrict__ Wk,
                         const float* __restrict__ Wv, const float* __restrict__ Wo) {
    __shared__ float sA[16][17], sB[16][17];
    const int tx = threadIdx.x, ty = threadIdx.y;
    const int k0 = blockIdx.x * 16, n0 = blockIdx.y * 16;
    const bool isA = (blockIdx.z == 0);
    float acc = 0.f;
    for (int e0 = 0; e0 < 256; e0 += 16) {
        const float* Mp = isA ? Wq : Wv;
        sA[ty][tx] = Mp[(e0 + ty) * 256 + k0 + tx];
        if (isA) sB[ty][tx] = Wk[(e0 + ty) * 256 + n0 + tx];
        else     sB[tx][ty] = Wo[(n0 + ty) * 256 + e0 + tx];
        __syncthreads();
#pragma unroll
        for (int e = 0; e < 16; ++e) acc += sA[e][tx] * sB[e][ty];
        __syncthreads();
    }
    const int k = k0 + tx, n = n0 + ty;
    const int r = k & 31, s = r >> 4, rr = r & 15;
    const int half = rr >> 3, tg = (rr & 7) >> 1, j = rr & 1;
    if (isA) {
        acc *= (1.0f / 16.0f);
        int kp = k >> 5;
        int nc = n >> 6, nn = n & 63, nt = nn >> 3, g = nn & 7, q = nt >> 1;
        int u32idx = ((s * 4 + q) * 32 + g * 4 + tg) * 4 + (nt & 1) * 2 + half;
        ((__nv_bfloat16*)g_Wa4)[((nc * 8 + kp) * 1024 + u32idx) * 2 + j] =
            __float2bfloat16(acc);
    } else {
        int dc = k >> 6, kp2 = (k >> 5) & 1;
        int nh = n >> 7, nn = n & 127, nt = nn >> 3, g = nn & 7, q = nt >> 1;
        int u32idx = ((s * 8 + q) * 32 + g * 4 + tg) * 4 + (nt & 1) * 2 + half;
        ((__nv_bfloat16*)g_Wb4)[((nh * 8 + dc * 2 + kp2) * 2048 + u32idx) * 2 + j] =
            __float2bfloat16(acc);
    }
}

// ---------------------- softmax (sig folded) --------------------------------
__device__ __forceinline__ void softmax_sig(const float* s0, const float* s1,
                                            float* As, float sig, int g, int tg) {
    int c0 = 2 * tg, c1 = 2 * tg + 1, c2 = 8 + 2 * tg, c3 = 9 + 2 * tg;
    bool v0 = c0 < 13, v1 = c1 < 13, v2 = c2 < 13, v3 = c3 < 13;
    const float NEG = -1e30f;
    float m0 = fmaxf(fmaxf(v0 ? s0[0] : NEG, v1 ? s0[1] : NEG),
                     fmaxf(v2 ? s1[0] : NEG, v3 ? s1[1] : NEG));
    float m1 = fmaxf(fmaxf(v0 ? s0[2] : NEG, v1 ? s0[3] : NEG),
                     fmaxf(v2 ? s1[2] : NEG, v3 ? s1[3] : NEG));
    m0 = fmaxf(m0, __shfl_xor_sync(0xffffffffu, m0, 1));
    m0 = fmaxf(m0, __shfl_xor_sync(0xffffffffu, m0, 2));
    m1 = fmaxf(m1, __shfl_xor_sync(0xffffffffu, m1, 1));
    m1 = fmaxf(m1, __shfl_xor_sync(0xffffffffu, m1, 2));
    float e00 = v0 ? __expf(s0[0] - m0) : 0.f;
    float e01 = v1 ? __expf(s0[1] - m0) : 0.f;
    float e02 = v2 ? __expf(s1[0] - m0) : 0.f;
    float e03 = v3 ? __expf(s1[1] - m0) : 0.f;
    float e10 = v0 ? __expf(s0[2] - m1) : 0.f;
    float e11 = v1 ? __expf(s0[3] - m1) : 0.f;
    float e12 = v2 ? __expf(s1[2] - m1) : 0.f;
    float e13 = v3 ? __expf(s1[3] - m1) : 0.f;
    float d0 = e00 + e01 + e02 + e03;
    float d1 = e10 + e11 + e12 + e13;
    d0 += __shfl_xor_sync(0xffffffffu, d0, 1);
    d0 += __shfl_xor_sync(0xffffffffu, d0, 2);
    d1 += __shfl_xor_sync(0xffffffffu, d1, 1);
    d1 += __shfl_xor_sync(0xffffffffu, d1, 2);
    float r0 = sig / d0, r1 = sig / d1;
    As[g * SAT + c0]       = f2tff(e00 * r0);
    As[g * SAT + c1]       = f2tff(e01 * r0);
    As[g * SAT + c2]       = f2tff(e02 * r0);
    As[g * SAT + c3]       = f2tff(e03 * r0);
    As[(g + 8) * SAT + c0] = f2tff(e10 * r1);
    As[(g + 8) * SAT + c1] = f2tff(e11 * r1);
    As[(g + 8) * SAT + c2] = f2tff(e12 * r1);
    As[(g + 8) * SAT + c3] = f2tff(e13 * r1);
}

// -------------------------------- main --------------------------------------
__global__ void __launch_bounds__(THREADS, 1)
lc_main(const float* __restrict__ h, const float* __restrict__ Wlat,
        const float* __restrict__ gate, float* __restrict__ out) {
    extern __shared__ float smem[];
    const int tid = threadIdx.x;
    const int w = tid >> 5, lane = tid & 31;
    const int g = lane >> 2, tg = lane & 3;
    const long token0 = (long)blockIdx.x * 8 + 2 * w;
    const bool gok = (g < 5);

    float* Xs0 = smem + SM_X + w * 2 * XTOK;
    float* Xs1 = Xs0 + XTOK;
    float* Cb0 = smem + SM_C + w * 2 * CBTOK;
    float* Cb1 = Cb0 + CBTOK;
    float* As0 = smem + SM_A + w * 2 * ATOK;
    float* As1 = As0 + ATOK;
    float* Wls = smem + SM_W;
    uint4* panq = (uint4*)(smem + SM_P);

    // ---- load X for both tokens (13x256 fp32 each) ----
    const float* hx0 = h + token0 * 3328;
    for (int i = lane; i < 832; i += 32) {
        int row = i >> 6, c4 = (i & 63) << 2;
        *(float4*)(Xs0 + row * SXR + c4) = *(const float4*)(hx0 + row * 256 + c4);
        *(float4*)(Xs1 + row * SXR + c4) = *(const float4*)(hx0 + 3328 + row * 256 + c4);
    }
    for (int idx = tid; idx < 208; idx += THREADS) {
        int p = idx >> 4, r = idx & 15;
        Wls[p * 16 + r] = (r < 13) ? Wlat[p * 13 + r] : 0.f;
    }
    float sig;
    { float gv = gate[0]; sig = 1.f / (1.f + __expf(-gv)); }
    __syncthreads();

    // =========== phase 1: Y = X Wa (bf16), S = Y X^T (tf32) ===========
    float sa[4] = {0, 0, 0, 0}, sb[4] = {0, 0, 0, 0};   // token0 score tiles
    float sc[4] = {0, 0, 0, 0}, sd[4] = {0, 0, 0, 0};   // token1 score tiles

    for (int nc = 0; nc < 4; ++nc) {
        float ya0[8][4], ya1[8][4];
#pragma unroll
        for (int i = 0; i < 8; ++i)
#pragma unroll
            for (int j = 0; j < 4; ++j) { ya0[i][j] = 0.f; ya1[i][j] = 0.f; }

        {   // initial pair (panels kp=0,1) -> buf0 (512 uint4)
            const uint4* src = g_Wa4 + nc * 8 * 256;
#pragma unroll
            for (int t = 0; t < 4; ++t) panq[tid + t * THREADS] = src[tid + t * THREADS];
        }
        __syncthreads();

        for (int pr = 0; pr < 4; ++pr) {
            uint4 pf[4];
            if (pr < 3) {
                const uint4* src = g_Wa4 + (nc * 8 + (pr + 1) * 2) * 256;
#pragma unroll
                for (int t = 0; t < 4; ++t) pf[t] = src[tid + t * THREADS];
            }
            const uint4* bufq = panq + (pr & 1) * 512;
#pragma unroll
            for (int hf = 0; hf < 2; ++hf) {
                const uint4* c4p = bufq + hf * 256;
#pragma unroll
                for (int s = 0; s < 2; ++s) {
                    int kc = pr * 64 + hf * 32 + s * 16;
                    uint32_t a00 = pk2(Xs0 + g * SXR + kc + 2 * tg);
                    uint32_t a01 = gok ? pk2(Xs0 + (g + 8) * SXR + kc + 2 * tg) : 0u;
                    uint32_t a02 = pk2(Xs0 + g * SXR + kc + 8 + 2 * tg);
                    uint32_t a03 = gok ? pk2(Xs0 + (g + 8) * SXR + kc + 8 + 2 * tg) : 0u;
                    uint32_t a10 = pk2(Xs1 + g * SXR + kc + 2 * tg);
                    uint32_t a11 = gok ? pk2(Xs1 + (g + 8) * SXR + kc + 2 * tg) : 0u;
                    uint32_t a12 = pk2(Xs1 + g * SXR + kc + 8 + 2 * tg);
                    uint32_t a13 = gok ? pk2(Xs1 + (g + 8) * SXR + kc + 8 + 2 * tg) : 0u;
#pragma unroll
                    for (int q = 0; q < 4; ++q) {
                        uint4 v = c4p[(s * 4 + q) * 32 + lane];
                        mmab(ya0[2 * q],     a00, a01, a02, a03, v.x, v.y);
                        mmab(ya0[2 * q + 1], a00, a01, a02, a03, v.z, v.w);
                        mmab(ya1[2 * q],     a10, a11, a12, a13, v.x, v.y);
                        mmab(ya1[2 * q + 1], a10, a11, a12, a13, v.z, v.w);
                    }
                }
            }
            if (pr < 3) {
                uint4* nxt = panq + ((pr + 1) & 1) * 512;
#pragma unroll
                for (int t = 0; t < 4; ++t) nxt[tid + t * THREADS] = pf[t];
            }
            __syncthreads();
        }

        // Ychunk -> Cb (tf32), S += Ychunk * Xchunk^T  (both tokens)
        __syncwarp();
#pragma unroll
        for (int nt = 0; nt < 8; ++nt) {
            int c = nt * 8 + 2 * tg;
            *(float2*)(Cb0 + g * SCB + c) = make_float2(f2tff(ya0[nt][0]), f2tff(ya0[nt][1]));
            *(float2*)(Cb0 + (g + 8) * SCB + c) = make_float2(f2tff(ya0[nt][2]), f2tff(ya0[nt][3]));
            *(float2*)(Cb1 + g * SCB + c) = make_float2(f2tff(ya1[nt][0]), f2tff(ya1[nt][1]));
            *(float2*)(Cb1 + (g + 8) * SCB + c) = make_float2(f2tff(ya1[nt][2]), f2tff(ya1[nt][3]));
        }
        __syncwarp();
#pragma unroll
        for (int ks = 0; ks < 8; ++ks) {
            int xc = nc * 64 + ks * 8;
            {
                uint32_t a0 = __float_as_uint(Cb0[g * SCB + ks * 8 + tg]);
                uint32_t a1 = __float_as_uint(Cb0[(g + 8) * SCB + ks * 8 + tg]);
                uint32_t a2 = __float_as_uint(Cb0[g * SCB + ks * 8 + tg + 4]);
                uint32_t a3 = __float_as_uint(Cb0[(g + 8) * SCB + ks * 8 + tg + 4]);
                uint32_t b0 = f2tf(Xs0[g * SXR + xc + tg]);
                uint32_t b1 = f2tf(Xs0[g * SXR + xc + tg + 4]);
                mma8(sa, a0, a1, a2, a3, b0, b1);
                uint32_t c0 = gok ? f2tf(Xs0[(g + 8) * SXR + xc + tg]) : 0u;
                uint32_t c1 = gok ? f2tf(Xs0[(g + 8) * SXR + xc + tg + 4]) : 0u;
                mma8(sb, a0, a1, a2, a3, c0, c1);
            }
            {
                uint32_t a0 = __float_as_uint(Cb1[g * SCB + ks * 8 + tg]);
                uint32_t a1 = __float_as_uint(Cb1[(g + 8) * SCB + ks * 8 + tg]);
                uint32_t a2 = __float_as_uint(Cb1[g * SCB + ks * 8 + tg + 4]);
                uint32_t a3 = __float_as_uint(Cb1[(g + 8) * SCB + ks * 8 + tg + 4]);
                uint32_t b0 = f2tf(Xs1[g * SXR + xc + tg]);
                uint32_t b1 = f2tf(Xs1[g * SXR + xc + tg + 4]);
                mma8(sc, a0, a1, a2, a3, b0, b1);
                uint32_t c0 = gok ? f2tf(Xs1[(g + 8) * SXR + xc + tg]) : 0u;
                uint32_t c1 = gok ? f2tf(Xs1[(g + 8) * SXR + xc + tg + 4]) : 0u;
                mma8(sd, a0, a1, a2, a3, c0, c1);
            }
        }
        __syncwarp();
    }

    // softmax both tokens
    softmax_sig(sa, sb, As0, sig, g, tg);
    softmax_sig(sc, sd, As1, sig, g, tg);
    __syncwarp();

    // ===== phase 2: Z = (sig*A) X (tf32), R = Z Wb (bf16), epilogue =====
    const long obase0 = token0 * 3328;
    for (int nh = 0; nh < 2; ++nh) {
        float ra0[16][4], ra1[16][4];
#pragma unroll
        for (int i = 0; i < 16; ++i)
#pragma unroll
            for (int j = 0; j < 4; ++j) { ra0[i][j] = 0.f; ra1[i][j] = 0.f; }

        {   // initial panel (ip=0) -> buf0 (512 uint4)
            const uint4* src = g_Wb4 + nh * 8 * 512;
#pragma unroll
            for (int t = 0; t < 4; ++t) panq[tid + t * THREADS] = src[tid + t * THREADS];
        }
        __syncthreads();

        int ip = 0;
        for (int dc = 0; dc < 4; ++dc) {
            // Zchunk per token -> Cb (fp32)
#pragma unroll
            for (int tok = 0; tok < 2; ++tok) {
                const float* Asx = tok ? As1 : As0;
                const float* Xsx = tok ? Xs1 : Xs0;
                float* Cbx = tok ? Cb1 : Cb0;
                float za[8][4];
#pragma unroll
                for (int i = 0; i < 8; ++i)
#pragma unroll
                    for (int j = 0; j < 4; ++j) za[i][j] = 0.f;
#pragma unroll
                for (int ks = 0; ks < 2; ++ks) {
                    uint32_t a0 = __float_as_uint(Asx[g * SAT + ks * 8 + tg]);
                    uint32_t a1 = __float_as_uint(Asx[(g + 8) * SAT + ks * 8 + tg]);
                    uint32_t a2 = __float_as_uint(Asx[g * SAT + ks * 8 + tg + 4]);
                    uint32_t a3 = __float_as_uint(Asx[(g + 8) * SAT + ks * 8 + tg + 4]);
                    int r0w = ks * 8 + tg;
                    int r1w = ks * 8 + tg + 4;
                    bool rok = r1w < 13;
#pragma unroll
                    for (int nt = 0; nt < 8; ++nt) {
                        int xc = dc * 64 + nt * 8 + g;
                        uint32_t b0 = f2tf(Xsx[r0w * SXR + xc]);
                        uint32_t b1 = rok ? f2tf(Xsx[r1w * SXR + xc]) : 0u;
                        mma8(za[nt], a0, a1, a2, a3, b0, b1);
                    }
                }
                __syncwarp();
#pragma unroll
                for (int nt = 0; nt < 8; ++nt) {
                    int c = nt * 8 + 2 * tg;
                    *(float2*)(Cbx + g * SCB + c) = make_float2(za[nt][0], za[nt][1]);
                    *(float2*)(Cbx + (g + 8) * SCB + c) = make_float2(za[nt][2], za[nt][3]);
                }
                __syncwarp();
            }

            for (int kp2 = 0; kp2 < 2; ++kp2, ++ip) {
                uint4 pf[4];
                if (ip < 7) {
                    const uint4* src = g_Wb4 + (nh * 8 + ip + 1) * 512;
#pragma unroll
                    for (int t = 0; t < 4; ++t) pf[t] = src[tid + t * THREADS];
                }
                const uint4* c4p = panq + (ip & 1) * 512;
#pragma unroll
                for (int s = 0; s < 2; ++s) {
                    int kc = kp2 * 32 + s * 16;
                    uint32_t a00 = pk2(Cb0 + g * SCB + kc + 2 * tg);
                    uint32_t a01 = pk2(Cb0 + (g + 8) * SCB + kc + 2 * tg);
                    uint32_t a02 = pk2(Cb0 + g * SCB + kc + 8 + 2 * tg);
                    uint32_t a03 = pk2(Cb0 + (g + 8) * SCB + kc + 8 + 2 * tg);
                    uint32_t a10 = pk2(Cb1 + g * SCB + kc + 2 * tg);
                    uint32_t a11 = pk2(Cb1 + (g + 8) * SCB + kc + 2 * tg);
                    uint32_t a12 = pk2(Cb1 + g * SCB + kc + 8 + 2 * tg);
                    uint32_t a13 = pk2(Cb1 + (g + 8) * SCB + kc + 8 + 2 * tg);
#pragma unroll
                    for (int q = 0; q < 8; ++q) {
                        uint4 v = c4p[(s * 8 + q) * 32 + lane];
                        mmab(ra0[2 * q],     a00, a01, a02, a03, v.x, v.y);
                        mmab(ra0[2 * q + 1], a00, a01, a02, a03, v.z, v.w);
                        mmab(ra1[2 * q],     a10, a11, a12, a13, v.x, v.y);
                        mmab(ra1[2 * q + 1], a10, a11, a12, a13, v.z, v.w);
                    }
                }
                if (ip < 7) {
                    uint4* nxt = panq + ((ip + 1) & 1) * 512;
#pragma unroll
                    for (int t = 0; t < 4; ++t) nxt[tid + t * THREADS] = pf[t];
                }
                __syncthreads();
            }
        }

        // ---- epilogue: exact fp32 residual into ra, then store (per token) ----
        {
#pragma unroll 1
            for (int p = 0; p < 13; ++p) {
                float wg = Wls[p * 16 + g];
                float wg8 = Wls[p * 16 + g + 8];
#pragma unroll
                for (int nt = 0; nt < 16; ++nt) {
                    int c = nh * 128 + nt * 8 + 2 * tg;
                    float2 x = *(float2*)(Xs0 + p * SXR + c);
                    ra0[nt][0] += wg * x.x;
                    ra0[nt][1] += wg * x.y;
                    ra0[nt][2] += wg8 * x.x;
                    ra0[nt][3] += wg8 * x.y;
                }
            }
#pragma unroll
            for (int nt = 0; nt < 16; ++nt) {
                int c = nh * 128 + nt * 8 + 2 * tg;
                *(float2*)(out + obase0 + g * 256 + c) = make_float2(ra0[nt][0], ra0[nt][1]);
                if (gok)
                    *(float2*)(out + obase0 + (g + 8) * 256 + c) = make_float2(ra0[nt][2], ra0[nt][3]);
            }
        }
        {
#pragma unroll 1
            for (int p = 0; p < 13; ++p) {
                float wg = Wls[p * 16 + g];
                float wg8 = Wls[p * 16 + g + 8];
#pragma unroll
                for (int nt = 0; nt < 16; ++nt) {
                    int c = nh * 128 + nt * 8 + 2 * tg;
                    float2 x = *(float2*)(Xs1 + p * SXR + c);
                    ra1[nt][0] += wg * x.x;
                    ra1[nt][1] += wg * x.y;
                    ra1[nt][2] += wg8 * x.x;
                    ra1[nt][3] += wg8 * x.y;
                }
            }
#pragma unroll
            for (int nt = 0; nt < 16; ++nt) {
                int c = nh * 128 + nt * 8 + 2 * tg;
                *(float2*)(out + obase0 + 3328 + g * 256 + c) = make_float2(ra1[nt][0], ra1[nt][1]);
                if (gok)
                    *(float2*)(out + obase0 + 3328 + (g + 8) * 256 + c) = make_float2(ra1[nt][2], ra1[nt][3]);
            }
        }
    }
}

// ------------------------------ launch --------------------------------------
extern "C" void kernel_launch(void* const* d_in, const int* in_sizes, int n_in,
                              void* d_out, int out_size) {
    const float* h    = (const float*)d_in[0];
    const float* Wq   = (const float*)d_in[1];
    const float* Wk   = (const float*)d_in[2];
    const float* Wv   = (const float*)d_in[3];
    const float* Wo   = (const float*)d_in[4];
    const float* Wlat = (const float*)d_in[5];
    const float* gate = (const float*)d_in[6];
    float* out = (float*)d_out;

    static bool attr_done = false;
    if (!attr_done) {
        cudaFuncSetAttribute(lc_main, cudaFuncAttributeMaxDynamicSharedMemorySize, SMEM_BYTES);
        attr_done = true;
    }

    lc_setup<<<dim3(16, 16, 2), dim3(16, 16)>>>(Wq, Wk, Wv, Wo);
    lc_main<<<2048, THREADS, SMEM_BYTES>>>(h, Wlat, gate, out);
}

// round 11
// speedup vs baseline: 1.2162x; 1.2162x over previous
#include <cuda_runtime.h>
#include <cuda_bf16.h>
#include <cstdint>

// out = Wlat^T X  +  sigmoid(gate) * softmax(X Wa X^T) X Wb
//   Wa[k][n] = sum_e Wq[e,k] Wk[e,n] / 16    (bf16 fragment-packed, g_Wa4)
//   Wb[k][n] = sum_e Wo[n,e] Wv[e,k]         (bf16 fragment-packed, g_Wb4)
// 256 thr/CTA, 8 tokens/CTA. Warp = (token-pair tp, N-half nhf):
//   phase 1: half owns nc = {2*nhf, 2*nhf+1}; S partials reduced via smem.
//   phase 2: half owns output cols [nhf*128, +128); Z kept in registers.
// Big GEMMs bf16 m16n8k16 (B frags shared across the token pair);
// S=Y*X^T and Z=A*X tf32 m16n8k8; residual exact fp32.

#define THREADS 256
#define SXR 260        // X smem row stride (fp32)
#define XTOK 3380      // 13*260
#define SCB 68         // phase-1 chunk buffer stride
#define CBTOK 1088     // 16*68
#define SAT 20         // attn stride
#define ATOK 320       // 16*20

#define SM_X 0                 // 8*3380 = 27040 floats
#define SM_P 27040             // 2048 uint4 = 8192 floats (2 bufs x 2 streams)
#define SM_C 35232             // 16*1088 = 17408 (per warp-token; S-reduce scratch)
#define SM_A 52640             // 8*320 = 2560
#define SM_W 55200             // 320
#define SMEM_FLOATS 55520
#define SMEM_BYTES (SMEM_FLOATS * 4)   // 222080

// Wa: 32 panels (nc*8+kp), panel = 32K x 64N bf16 = 256 uint4
// Wb: 16 panels (nh*8+dc*2+kp2), panel = 32K x 128N bf16 = 512 uint4
__device__ uint4 g_Wa4[32 * 256];
__device__ uint4 g_Wb4[16 * 512];

__device__ __forceinline__ uint32_t f2tf(float x) {
    uint32_t r;
    asm("cvt.rna.tf32.f32 %0, %1;" : "=r"(r) : "f"(x));
    return r;
}
__device__ __forceinline__ float f2tff(float x) {
    return __uint_as_float(f2tf(x));
}
// pack two consecutive fp32 (mem) into bf16x2 {lo=p[0], hi=p[1]}
__device__ __forceinline__ uint32_t pk2(const float* p) {
    float2 v = *(const float2*)p;
    uint32_t r;
    asm("cvt.rn.bf16x2.f32 %0, %1, %2;" : "=r"(r) : "f"(v.y), "f"(v.x));
    return r;
}
// pack two register fp32 into bf16x2 {lo, hi}
__device__ __forceinline__ uint32_t pkr(float lo, float hi) {
    uint32_t r;
    asm("cvt.rn.bf16x2.f32 %0, %1, %2;" : "=r"(r) : "f"(hi), "f"(lo));
    return r;
}

__device__ __forceinline__ void mma8(float* d,
                                     uint32_t a0, uint32_t a1, uint32_t a2, uint32_t a3,
                                     uint32_t b0, uint32_t b1) {
    asm volatile(
        "mma.sync.aligned.m16n8k8.row.col.f32.tf32.tf32.f32 "
        "{%0,%1,%2,%3},{%4,%5,%6,%7},{%8,%9},{%0,%1,%2,%3};\n"
        : "+f"(d[0]), "+f"(d[1]), "+f"(d[2]), "+f"(d[3])
        : "r"(a0), "r"(a1), "r"(a2), "r"(a3), "r"(b0), "r"(b1));
}
__device__ __forceinline__ void mmab(float* d,
                                     uint32_t a0, uint32_t a1, uint32_t a2, uint32_t a3,
                                     uint32_t b0, uint32_t b1) {
    asm volatile(
        "mma.sync.aligned.m16n8k16.row.col.f32.bf16.bf16.f32 "
        "{%0,%1,%2,%3},{%4,%5,%6,%7},{%8,%9},{%0,%1,%2,%3};\n"
        : "+f"(d[0]), "+f"(d[1]), "+f"(d[2]), "+f"(d[3])
        : "r"(a0), "r"(a1), "r"(a2), "r"(a3), "r"(b0), "r"(b1));
}

// ------------------------------- setup --------------------------------------
__global__ void lc_setup(const float* __restrict__ Wq, const float* __restrict__ Wk,
                         const float* __restrict__ Wv, const float* __restrict__ Wo) {
    __shared__ float sA[16][17], sB[16][17];
    const int tx = threadIdx.x, ty = threadIdx.y;
    const int k0 = blockIdx.x * 16, n0 = blockIdx.y * 16;
    const bool isA = (blockIdx.z == 0);
    float acc = 0.f;
    for (int e0 = 0; e0 < 256; e0 += 16) {
        const float* Mp = isA ? Wq : Wv;
        sA[ty][tx] = Mp[(e0 + ty) * 256 + k0 + tx];
        if (isA) sB[ty][tx] = Wk[(e0 + ty) * 256 + n0 + tx];
        else     sB[tx][ty] = Wo[(n0 + ty) * 256 + e0 + tx];
        __syncthreads();
#pragma unroll
        for (int e = 0; e < 16; ++e) acc += sA[e][tx] * sB[e][ty];
        __syncthreads();
    }
    const int k = k0 + tx, n = n0 + ty;
    const int r = k & 31, s = r >> 4, rr = r & 15;
    const int half = rr >> 3, tg = (rr & 7) >> 1, j = rr & 1;
    if (isA) {
        acc *= (1.0f / 16.0f);
        int kp = k >> 5;
        int nc = n >> 6, nn = n & 63, nt = nn >> 3, g = nn & 7, q = nt >> 1;
        int u32idx = ((s * 4 + q) * 32 + g * 4 + tg) * 4 + (nt & 1) * 2 + half;
        ((__nv_bfloat16*)g_Wa4)[((nc * 8 + kp) * 1024 + u32idx) * 2 + j] =
            __float2bfloat16(acc);
    } else {
        int dc = k >> 6, kp2 = (k >> 5) & 1;
        int nh = n >> 7, nn = n & 127, nt = nn >> 3, g = nn & 7, q = nt >> 1;
        int u32idx = ((s * 8 + q) * 32 + g * 4 + tg) * 4 + (nt & 1) * 2 + half;
        ((__nv_bfloat16*)g_Wb4)[((nh * 8 + dc * 2 + kp2) * 2048 + u32idx) * 2 + j] =
            __float2bfloat16(acc);
    }
}

// ---------------------- softmax (sig folded) --------------------------------
__device__ __forceinline__ void softmax_sig(const float* s0, const float* s1,
                                            float* As, float sig, int g, int tg) {
    int c0 = 2 * tg, c1 = 2 * tg + 1, c2 = 8 + 2 * tg, c3 = 9 + 2 * tg;
    bool v0 = c0 < 13, v1 = c1 < 13, v2 = c2 < 13, v3 = c3 < 13;
    const float NEG = -1e30f;
    float m0 = fmaxf(fmaxf(v0 ? s0[0] : NEG, v1 ? s0[1] : NEG),
                     fmaxf(v2 ? s1[0] : NEG, v3 ? s1[1] : NEG));
    float m1 = fmaxf(fmaxf(v0 ? s0[2] : NEG, v1 ? s0[3] : NEG),
                     fmaxf(v2 ? s1[2] : NEG, v3 ? s1[3] : NEG));
    m0 = fmaxf(m0, __shfl_xor_sync(0xffffffffu, m0, 1));
    m0 = fmaxf(m0, __shfl_xor_sync(0xffffffffu, m0, 2));
    m1 = fmaxf(m1, __shfl_xor_sync(0xffffffffu, m1, 1));
    m1 = fmaxf(m1, __shfl_xor_sync(0xffffffffu, m1, 2));
    float e00 = v0 ? __expf(s0[0] - m0) : 0.f;
    float e01 = v1 ? __expf(s0[1] - m0) : 0.f;
    float e02 = v2 ? __expf(s1[0] - m0) : 0.f;
    float e03 = v3 ? __expf(s1[1] - m0) : 0.f;
    float e10 = v0 ? __expf(s0[2] - m1) : 0.f;
    float e11 = v1 ? __expf(s0[3] - m1) : 0.f;
    float e12 = v2 ? __expf(s1[2] - m1) : 0.f;
    float e13 = v3 ? __expf(s1[3] - m1) : 0.f;
    float d0 = e00 + e01 + e02 + e03;
    float d1 = e10 + e11 + e12 + e13;
    d0 += __shfl_xor_sync(0xffffffffu, d0, 1);
    d0 += __shfl_xor_sync(0xffffffffu, d0, 2);
    d1 += __shfl_xor_sync(0xffffffffu, d1, 1);
    d1 += __shfl_xor_sync(0xffffffffu, d1, 2);
    float r0 = sig / d0, r1 = sig / d1;
    As[g * SAT + c0]       = f2tff(e00 * r0);
    As[g * SAT + c1]       = f2tff(e01 * r0);
    As[g * SAT + c2]       = f2tff(e02 * r0);
    As[g * SAT + c3]       = f2tff(e03 * r0);
    As[(g + 8) * SAT + c0] = f2tff(e10 * r1);
    As[(g + 8) * SAT + c1] = f2tff(e11 * r1);
    As[(g + 8) * SAT + c2] = f2tff(e12 * r1);
    As[(g + 8) * SAT + c3] = f2tff(e13 * r1);
}

// -------------------------------- main --------------------------------------
__global__ void __launch_bounds__(THREADS, 1)
lc_main(const float* __restrict__ hsrc, const float* __restrict__ Wlat,
        const float* __restrict__ gate, float* __restrict__ out) {
    extern __shared__ float smem[];
    const int tid = threadIdx.x;
    const int w = tid >> 5, lane = tid & 31;
    const int g = lane >> 2, tg = lane & 3;
    const int tp = w >> 1, nhf = w & 1;
    const long tokbase = (long)blockIdx.x * 8;
    const bool gok = (g < 5);

    float* Xs0 = smem + SM_X + (2 * tp) * XTOK;
    float* Xs1 = Xs0 + XTOK;
    float* Cb0 = smem + SM_C + (2 * w) * CBTOK;   // per-warp private
    float* Cb1 = Cb0 + CBTOK;
    float* As0 = smem + SM_A + (2 * tp) * ATOK;
    float* As1 = As0 + ATOK;
    float* Wls = smem + SM_W;
    uint4* panq = (uint4*)(smem + SM_P);

    // ---- load X: warp w loads token w (13x256 fp32) ----
    {
        const float* src = hsrc + (tokbase + w) * 3328;
        float* dst = smem + SM_X + w * XTOK;
        for (int i = lane; i < 832; i += 32) {
            int row = i >> 6, c4 = (i & 63) << 2;
            *(float4*)(dst + row * SXR + c4) = *(const float4*)(src + row * 256 + c4);
        }
    }
    if (tid < 208) {
        int p = tid >> 4, r = tid & 15;
        Wls[p * 16 + r] = (r < 13) ? Wlat[p * 13 + r] : 0.f;
    }
    float sig;
    { float gv = gate[0]; sig = 1.f / (1.f + __expf(-gv)); }

    // initial phase-1 panel stage 0 (both streams) -> buf0
    {
#pragma unroll
        for (int t = 0; t < 4; ++t) {
            int idx = tid + t * THREADS;
            int s_ = idx >> 9, off = idx & 511;
            panq[idx] = g_Wa4[(2 * s_ * 8) * 256 + off];
        }
    }
    __syncthreads();

    // =========== phase 1: Y = X Wa (bf16, half's nc), S partial ===========
    float sa[4] = {0, 0, 0, 0}, sb[4] = {0, 0, 0, 0};
    float sc[4] = {0, 0, 0, 0}, sd[4] = {0, 0, 0, 0};

    for (int ncl = 0; ncl < 2; ++ncl) {
        const int nc = 2 * nhf + ncl;
        float ya0[8][4], ya1[8][4];
#pragma unroll
        for (int i = 0; i < 8; ++i)
#pragma unroll
            for (int j = 0; j < 4; ++j) { ya0[i][j] = 0.f; ya1[i][j] = 0.f; }

        for (int pr = 0; pr < 4; ++pr) {
            const int st = ncl * 4 + pr;
            uint4 pf[4];
            if (st < 7) {
                const int nst = st + 1;
#pragma unroll
                for (int t = 0; t < 4; ++t) {
                    int idx = tid + t * THREADS;
                    int s_ = idx >> 9, off = idx & 511;
                    pf[t] = g_Wa4[((2 * s_ + (nst >> 2)) * 8 + (nst & 3) * 2) * 256 + off];
                }
            }
            const uint4* bufq = panq + (st & 1) * 1024 + nhf * 512;
#pragma unroll
            for (int hf = 0; hf < 2; ++hf) {
                const uint4* c4p = bufq + hf * 256;
#pragma unroll
                for (int s = 0; s < 2; ++s) {
                    int kc = pr * 64 + hf * 32 + s * 16;
                    uint32_t a00 = pk2(Xs0 + g * SXR + kc + 2 * tg);
                    uint32_t a01 = gok ? pk2(Xs0 + (g + 8) * SXR + kc + 2 * tg) : 0u;
                    uint32_t a02 = pk2(Xs0 + g * SXR + kc + 8 + 2 * tg);
                    uint32_t a03 = gok ? pk2(Xs0 + (g + 8) * SXR + kc + 8 + 2 * tg) : 0u;
                    uint32_t a10 = pk2(Xs1 + g * SXR + kc + 2 * tg);
                    uint32_t a11 = gok ? pk2(Xs1 + (g + 8) * SXR + kc + 2 * tg) : 0u;
                    uint32_t a12 = pk2(Xs1 + g * SXR + kc + 8 + 2 * tg);
                    uint32_t a13 = gok ? pk2(Xs1 + (g + 8) * SXR + kc + 8 + 2 * tg) : 0u;
#pragma unroll
                    for (int q = 0; q < 4; ++q) {
                        uint4 v = c4p[(s * 4 + q) * 32 + lane];
                        mmab(ya0[2 * q],     a00, a01, a02, a03, v.x, v.y);
                        mmab(ya0[2 * q + 1], a00, a01, a02, a03, v.z, v.w);
                        mmab(ya1[2 * q],     a10, a11, a12, a13, v.x, v.y);
                        mmab(ya1[2 * q + 1], a10, a11, a12, a13, v.z, v.w);
                    }
                }
            }
            if (st < 7) {
                uint4* nxt = panq + ((st + 1) & 1) * 1024;
#pragma unroll
                for (int t = 0; t < 4; ++t) nxt[tid + t * THREADS] = pf[t];
            }
            __syncthreads();
        }

        // flush: Ychunk -> Cb (tf32), S += Ychunk * Xchunk^T
        __syncwarp();
#pragma unroll
        for (int nt = 0; nt < 8; ++nt) {
            int c = nt * 8 + 2 * tg;
            *(float2*)(Cb0 + g * SCB + c) = make_float2(f2tff(ya0[nt][0]), f2tff(ya0[nt][1]));
            *(float2*)(Cb0 + (g + 8) * SCB + c) = make_float2(f2tff(ya0[nt][2]), f2tff(ya0[nt][3]));
            *(float2*)(Cb1 + g * SCB + c) = make_float2(f2tff(ya1[nt][0]), f2tff(ya1[nt][1]));
            *(float2*)(Cb1 + (g + 8) * SCB + c) = make_float2(f2tff(ya1[nt][2]), f2tff(ya1[nt][3]));
        }
        __syncwarp();
#pragma unroll
        for (int ks = 0; ks < 8; ++ks) {
            int xc = nc * 64 + ks * 8;
            {
                uint32_t a0 = __float_as_uint(Cb0[g * SCB + ks * 8 + tg]);
                uint32_t a1 = __float_as_uint(Cb0[(g + 8) * SCB + ks * 8 + tg]);
                uint32_t a2 = __float_as_uint(Cb0[g * SCB + ks * 8 + tg + 4]);
                uint32_t a3 = __float_as_uint(Cb0[(g + 8) * SCB + ks * 8 + tg + 4]);
                uint32_t b0 = f2tf(Xs0[g * SXR + xc + tg]);
                uint32_t b1 = f2tf(Xs0[g * SXR + xc + tg + 4]);
                mma8(sa, a0, a1, a2, a3, b0, b1);
                uint32_t c0 = gok ? f2tf(Xs0[(g + 8) * SXR + xc + tg]) : 0u;
                uint32_t c1 = gok ? f2tf(Xs0[(g + 8) * SXR + xc + tg + 4]) : 0u;
                mma8(sb, a0, a1, a2, a3, c0, c1);
            }
            {
                uint32_t a0 = __float_as_uint(Cb1[g * SCB + ks * 8 + tg]);
                uint32_t a1 = __float_as_uint(Cb1[(g + 8) * SCB + ks * 8 + tg]);
                uint32_t a2 = __float_as_uint(Cb1[g * SCB + ks * 8 + tg + 4]);
                uint32_t a3 = __float_as_uint(Cb1[(g + 8) * SCB + ks * 8 + tg + 4]);
                uint32_t b0 = f2tf(Xs1[g * SXR + xc + tg]);
                uint32_t b1 = f2tf(Xs1[g * SXR + xc + tg + 4]);
                mma8(sc, a0, a1, a2, a3, b0, b1);
                uint32_t c0 = gok ? f2tf(Xs1[(g + 8) * SXR + xc + tg]) : 0u;
                uint32_t c1 = gok ? f2tf(Xs1[(g + 8) * SXR + xc + tg + 4]) : 0u;
                mma8(sd, a0, a1, a2, a3, c0, c1);
            }
        }
        __syncwarp();
    }

    // ---------- S cross-half reduction + softmax ----------
    __syncthreads();   // protect partner's Cb region before scratch writes
    {
        float* my = smem + SM_C + (w * 32 + lane) * 16;
#pragma unroll
        for (int i = 0; i < 4; ++i) {
            my[i] = sa[i]; my[4 + i] = sb[i]; my[8 + i] = sc[i]; my[12 + i] = sd[i];
        }
    }
    __syncthreads();
    if (nhf == 0) {
        const float* ot = smem + SM_C + ((w ^ 1) * 32 + lane) * 16;
#pragma unroll
        for (int i = 0; i < 4; ++i) {
            sa[i] += ot[i]; sb[i] += ot[4 + i]; sc[i] += ot[8 + i]; sd[i] += ot[12 + i];
        }
        softmax_sig(sa, sb, As0, sig, g, tg);
        softmax_sig(sc, sd, As1, sig, g, tg);
    }

    // initial phase-2 panel stage 0 (both streams) -> buf0
    {
#pragma unroll
        for (int t = 0; t < 4; ++t) {
            int idx = tid + t * THREADS;
            int s_ = idx >> 9, off = idx & 511;
            panq[idx] = g_Wb4[(s_ * 8) * 512 + off];
        }
    }
    __syncthreads();

    // ===== phase 2: Z = (sig*A) X (tf32, regs), R_half = Z Wb (bf16) =====
    float ra0[16][4], ra1[16][4];
#pragma unroll
    for (int i = 0; i < 16; ++i)
#pragma unroll
        for (int j = 0; j < 4; ++j) { ra0[i][j] = 0.f; ra1[i][j] = 0.f; }

    float za0[8][4], za1[8][4];
    for (int dc = 0; dc < 4; ++dc) {
        // Zchunk per token (kept in registers)
#pragma unroll
        for (int tok = 0; tok < 2; ++tok) {
            const float* Asx = tok ? As1 : As0;
            const float* Xsx = tok ? Xs1 : Xs0;
            float (*za)[4] = tok ? za1 : za0;
#pragma unroll
            for (int i = 0; i < 8; ++i)
#pragma unroll
                for (int j = 0; j < 4; ++j) za[i][j] = 0.f;
#pragma unroll
            for (int ks = 0; ks < 2; ++ks) {
                uint32_t a0 = __float_as_uint(Asx[g * SAT + ks * 8 + tg]);
                uint32_t a1 = __float_as_uint(Asx[(g + 8) * SAT + ks * 8 + tg]);
                uint32_t a2 = __float_as_uint(Asx[g * SAT + ks * 8 + tg + 4]);
                uint32_t a3 = __float_as_uint(Asx[(g + 8) * SAT + ks * 8 + tg + 4]);
                int r0w = ks * 8 + tg;
                int r1w = ks * 8 + tg + 4;
                bool rok = r1w < 13;
#pragma unroll
                for (int nt = 0; nt < 8; ++nt) {
                    int xc = dc * 64 + nt * 8 + g;
                    uint32_t b0 = f2tf(Xsx[r0w * SXR + xc]);
                    uint32_t b1 = rok ? f2tf(Xsx[r1w * SXR + xc]) : 0u;
                    mma8(za[nt], a0, a1, a2, a3, b0, b1);
                }
            }
        }

        for (int kp2 = 0; kp2 < 2; ++kp2) {
            const int st = dc * 2 + kp2;
            uint4 pf[4];
            if (st < 7) {
#pragma unroll
                for (int t = 0; t < 4; ++t) {
                    int idx = tid + t * THREADS;
                    int s_ = idx >> 9, off = idx & 511;
                    pf[t] = g_Wb4[(s_ * 8 + st + 1) * 512 + off];
                }
            }
            const uint4* c4p = panq + (st & 1) * 1024 + nhf * 512;
#pragma unroll
            for (int s = 0; s < 2; ++s) {
                int t0 = kp2 * 4 + 2 * s;
                uint32_t a00 = pkr(za0[t0][0], za0[t0][1]);
                uint32_t a01 = pkr(za0[t0][2], za0[t0][3]);
                uint32_t a02 = pkr(za0[t0 + 1][0], za0[t0 + 1][1]);
                uint32_t a03 = pkr(za0[t0 + 1][2], za0[t0 + 1][3]);
                uint32_t a10 = pkr(za1[t0][0], za1[t0][1]);
                uint32_t a11 = pkr(za1[t0][2], za1[t0][3]);
                uint32_t a12 = pkr(za1[t0 + 1][0], za1[t0 + 1][1]);
                uint32_t a13 = pkr(za1[t0 + 1][2], za1[t0 + 1][3]);
#pragma unroll
                for (int q = 0; q < 8; ++q) {
                    uint4 v = c4p[(s * 8 + q) * 32 + lane];
                    mmab(ra0[2 * q],     a00, a01, a02, a03, v.x, v.y);
                    mmab(ra0[2 * q + 1], a00, a01, a02, a03, v.z, v.w);
                    mmab(ra1[2 * q],     a10, a11, a12, a13, v.x, v.y);
                    mmab(ra1[2 * q + 1], a10, a11, a12, a13, v.z, v.w);
                }
            }
            if (st < 7) {
                uint4* nxt = panq + ((st + 1) & 1) * 1024;
#pragma unroll
                for (int t = 0; t < 4; ++t) nxt[tid + t * THREADS] = pf[t];
            }
            __syncthreads();
        }
    }

    // ---- epilogue: exact fp32 residual into ra, then store (cols of half) ----
    const long obase0 = (tokbase + 2 * tp) * 3328;
    {
#pragma unroll 1
        for (int p = 0; p < 13; ++p) {
            float wg = Wls[p * 16 + g];
            float wg8 = Wls[p * 16 + g + 8];
#pragma unroll
            for (int nt = 0; nt < 16; ++nt) {
                int c = nhf * 128 + nt * 8 + 2 * tg;
                float2 x0 = *(float2*)(Xs0 + p * SXR + c);
                ra0[nt][0] += wg * x0.x;
                ra0[nt][1] += wg * x0.y;
                ra0[nt][2] += wg8 * x0.x;
                ra0[nt][3] += wg8 * x0.y;
                float2 x1 = *(float2*)(Xs1 + p * SXR + c);
                ra1[nt][0] += wg * x1.x;
                ra1[nt][1] += wg * x1.y;
                ra1[nt][2] += wg8 * x1.x;
                ra1[nt][3] += wg8 * x1.y;
            }
        }
#pragma unroll
        for (int nt = 0; nt < 16; ++nt) {
            int c = nhf * 128 + nt * 8 + 2 * tg;
            *(float2*)(out + obase0 + g * 256 + c) = make_float2(ra0[nt][0], ra0[nt][1]);
            *(float2*)(out + obase0 + 3328 + g * 256 + c) = make_float2(ra1[nt][0], ra1[nt][1]);
            if (gok) {
                *(float2*)(out + obase0 + (g + 8) * 256 + c) = make_float2(ra0[nt][2], ra0[nt][3]);
                *(float2*)(out + obase0 + 3328 + (g + 8) * 256 + c) = make_float2(ra1[nt][2], ra1[nt][3]);
            }
        }
    }
}

// ------------------------------ launch --------------------------------------
extern "C" void kernel_launch(void* const* d_in, const int* in_sizes, int n_in,
                              void* d_out, int out_size) {
    const float* h    = (const float*)d_in[0];
    const float* Wq   = (const float*)d_in[1];
    const float* Wk   = (const float*)d_in[2];
    const float* Wv   = (const float*)d_in[3];
    const float* Wo   = (const float*)d_in[4];
    const float* Wlat = (const float*)d_in[5];
    const float* gate = (const float*)d_in[6];
    float* out = (float*)d_out;

    static bool attr_done = false;
    if (!attr_done) {
        cudaFuncSetAttribute(lc_main, cudaFuncAttributeMaxDynamicSharedMemorySize, SMEM_BYTES);
        attr_done = true;
    }

    lc_setup<<<dim3(16, 16, 2), dim3(16, 16)>>>(Wq, Wk, Wv, Wo);
    lc_main<<<2048, THREADS, SMEM_BYTES>>>(h, Wlat, gate, out);
}

// round 12
// speedup vs baseline: 1.4126x; 1.1615x over previous
#include <cuda_runtime.h>
#include <cuda_bf16.h>
#include <cstdint>

// out = Wlat^T X  +  sigmoid(gate) * softmax(X Wa X^T) X Wb
//   Wa[k][n] = sum_e Wq[e,k] Wk[e,n] / 16    (bf16 fragment-packed, g_Wa4)
//   Wb[k][n] = sum_e Wo[n,e] Wv[e,k]         (bf16 fragment-packed, g_Wb4)
// 128 thr/CTA, 2 CTA/SM, 4 tokens/CTA. Warp = (token-pair tp, N-half nhf).
// Weight panels stream GMEM->SMEM via cp.async double-buffer.
// Big GEMMs bf16 m16n8k16 (B frags shared across token pair);
// S=Y*X^T and Z=A*X tf32 m16n8k8; residual exact fp32.

#define THREADS 128
#define SXR 260        // X smem row stride (fp32)
#define XTOK 3380      // 13*260
#define SCB 68         // phase-1 chunk buffer stride (single per warp)
#define SAT 20         // attn stride
#define ATOK 320       // 16*20

#define SM_X 0                 // 4*3380 = 13520 floats
#define SM_P 13520             // 2048 uint4 = 8192 floats (2 bufs x 2 streams)
#define SM_C 21712             // 4*1088 = 4352 (per-warp Cb; also S-reduce scratch)
#define SM_A 26064             // 4*320 = 1280
#define SM_W 27344             // 320
#define SMEM_FLOATS 27664
#define SMEM_BYTES (SMEM_FLOATS * 4)   // 110656 -> 2 CTAs/SM

// Wa: 32 panels (nc*8+kp), panel = 32K x 64N bf16 = 256 uint4
// Wb: 16 panels (nh*8+dc*2+kp2), panel = 32K x 128N bf16 = 512 uint4
__device__ uint4 g_Wa4[32 * 256];
__device__ uint4 g_Wb4[16 * 512];

__device__ __forceinline__ uint32_t f2tf(float x) {
    uint32_t r;
    asm("cvt.rna.tf32.f32 %0, %1;" : "=r"(r) : "f"(x));
    return r;
}
__device__ __forceinline__ float f2tff(float x) {
    return __uint_as_float(f2tf(x));
}
__device__ __forceinline__ uint32_t pk2(const float* p) {
    float2 v = *(const float2*)p;
    uint32_t r;
    asm("cvt.rn.bf16x2.f32 %0, %1, %2;" : "=r"(r) : "f"(v.y), "f"(v.x));
    return r;
}
__device__ __forceinline__ uint32_t pkr(float lo, float hi) {
    uint32_t r;
    asm("cvt.rn.bf16x2.f32 %0, %1, %2;" : "=r"(r) : "f"(hi), "f"(lo));
    return r;
}

__device__ __forceinline__ void mma8(float* d,
                                     uint32_t a0, uint32_t a1, uint32_t a2, uint32_t a3,
                                     uint32_t b0, uint32_t b1) {
    asm volatile(
        "mma.sync.aligned.m16n8k8.row.col.f32.tf32.tf32.f32 "
        "{%0,%1,%2,%3},{%4,%5,%6,%7},{%8,%9},{%0,%1,%2,%3};\n"
        : "+f"(d[0]), "+f"(d[1]), "+f"(d[2]), "+f"(d[3])
        : "r"(a0), "r"(a1), "r"(a2), "r"(a3), "r"(b0), "r"(b1));
}
__device__ __forceinline__ void mmab(float* d,
                                     uint32_t a0, uint32_t a1, uint32_t a2, uint32_t a3,
                                     uint32_t b0, uint32_t b1) {
    asm volatile(
        "mma.sync.aligned.m16n8k16.row.col.f32.bf16.bf16.f32 "
        "{%0,%1,%2,%3},{%4,%5,%6,%7},{%8,%9},{%0,%1,%2,%3};\n"
        : "+f"(d[0]), "+f"(d[1]), "+f"(d[2]), "+f"(d[3])
        : "r"(a0), "r"(a1), "r"(a2), "r"(a3), "r"(b0), "r"(b1));
}

__device__ __forceinline__ void cpa16(uint4* sdst, const uint4* gsrc) {
    uint32_t s = (uint32_t)__cvta_generic_to_shared(sdst);
    asm volatile("cp.async.cg.shared.global [%0], [%1], 16;" :: "r"(s), "l"(gsrc));
}
#define CP_COMMIT() asm volatile("cp.async.commit_group;")
#define CP_WAIT0()  asm volatile("cp.async.wait_group 0;" ::: "memory")

// panel stage issuers: 1024 uint4 per stage, 8 per thread at 128 threads
__device__ __forceinline__ void issue_p1(uint4* panq, int st, int tid) {
    uint4* dst = panq + (st & 1) * 1024;
#pragma unroll
    for (int t = 0; t < 8; ++t) {
        int idx = tid + t * THREADS;
        int s_ = idx >> 9, off = idx & 511;
        cpa16(dst + idx, g_Wa4 + ((2 * s_ + (st >> 2)) * 8 + (st & 3) * 2) * 256 + off);
    }
}
__device__ __forceinline__ void issue_p2(uint4* panq, int st, int tid) {
    uint4* dst = panq + (st & 1) * 1024;
#pragma unroll
    for (int t = 0; t < 8; ++t) {
        int idx = tid + t * THREADS;
        int s_ = idx >> 9, off = idx & 511;
        cpa16(dst + idx, g_Wb4 + (s_ * 8 + st) * 512 + off);
    }
}

// ------------------------------- setup --------------------------------------
__global__ void lc_setup(const float* __restrict__ Wq, const float* __restrict__ Wk,
                         const float* __restrict__ Wv, const float* __restrict__ Wo) {
    __shared__ float sA[16][17], sB[16][17];
    const int tx = threadIdx.x, ty = threadIdx.y;
    const int k0 = blockIdx.x * 16, n0 = blockIdx.y * 16;
    const bool isA = (blockIdx.z == 0);
    float acc = 0.f;
    for (int e0 = 0; e0 < 256; e0 += 16) {
        const float* Mp = isA ? Wq : Wv;
        sA[ty][tx] = Mp[(e0 + ty) * 256 + k0 + tx];
        if (isA) sB[ty][tx] = Wk[(e0 + ty) * 256 + n0 + tx];
        else     sB[tx][ty] = Wo[(n0 + ty) * 256 + e0 + tx];
        __syncthreads();
#pragma unroll
        for (int e = 0; e < 16; ++e) acc += sA[e][tx] * sB[e][ty];
        __syncthreads();
    }
    const int k = k0 + tx, n = n0 + ty;
    const int r = k & 31, s = r >> 4, rr = r & 15;
    const int half = rr >> 3, tg = (rr & 7) >> 1, j = rr & 1;
    if (isA) {
        acc *= (1.0f / 16.0f);
        int kp = k >> 5;
        int nc = n >> 6, nn = n & 63, nt = nn >> 3, g = nn & 7, q = nt >> 1;
        int u32idx = ((s * 4 + q) * 32 + g * 4 + tg) * 4 + (nt & 1) * 2 + half;
        ((__nv_bfloat16*)g_Wa4)[((nc * 8 + kp) * 1024 + u32idx) * 2 + j] =
            __float2bfloat16(acc);
    } else {
        int dc = k >> 6, kp2 = (k >> 5) & 1;
        int nh = n >> 7, nn = n & 127, nt = nn >> 3, g = nn & 7, q = nt >> 1;
        int u32idx = ((s * 8 + q) * 32 + g * 4 + tg) * 4 + (nt & 1) * 2 + half;
        ((__nv_bfloat16*)g_Wb4)[((nh * 8 + dc * 2 + kp2) * 2048 + u32idx) * 2 + j] =
            __float2bfloat16(acc);
    }
}

// ---------------------- softmax (sig folded) --------------------------------
__device__ __forceinline__ void softmax_sig(const float* s0, const float* s1,
                                            float* As, float sig, int g, int tg) {
    int c0 = 2 * tg, c1 = 2 * tg + 1, c2 = 8 + 2 * tg, c3 = 9 + 2 * tg;
    bool v0 = c0 < 13, v1 = c1 < 13, v2 = c2 < 13, v3 = c3 < 13;
    const float NEG = -1e30f;
    float m0 = fmaxf(fmaxf(v0 ? s0[0] : NEG, v1 ? s0[1] : NEG),
                     fmaxf(v2 ? s1[0] : NEG, v3 ? s1[1] : NEG));
    float m1 = fmaxf(fmaxf(v0 ? s0[2] : NEG, v1 ? s0[3] : NEG),
                     fmaxf(v2 ? s1[2] : NEG, v3 ? s1[3] : NEG));
    m0 = fmaxf(m0, __shfl_xor_sync(0xffffffffu, m0, 1));
    m0 = fmaxf(m0, __shfl_xor_sync(0xffffffffu, m0, 2));
    m1 = fmaxf(m1, __shfl_xor_sync(0xffffffffu, m1, 1));
    m1 = fmaxf(m1, __shfl_xor_sync(0xffffffffu, m1, 2));
    float e00 = v0 ? __expf(s0[0] - m0) : 0.f;
    float e01 = v1 ? __expf(s0[1] - m0) : 0.f;
    float e02 = v2 ? __expf(s1[0] - m0) : 0.f;
    float e03 = v3 ? __expf(s1[1] - m0) : 0.f;
    float e10 = v0 ? __expf(s0[2] - m1) : 0.f;
    float e11 = v1 ? __expf(s0[3] - m1) : 0.f;
    float e12 = v2 ? __expf(s1[2] - m1) : 0.f;
    float e13 = v3 ? __expf(s1[3] - m1) : 0.f;
    float d0 = e00 + e01 + e02 + e03;
    float d1 = e10 + e11 + e12 + e13;
    d0 += __shfl_xor_sync(0xffffffffu, d0, 1);
    d0 += __shfl_xor_sync(0xffffffffu, d0, 2);
    d1 += __shfl_xor_sync(0xffffffffu, d1, 1);
    d1 += __shfl_xor_sync(0xffffffffu, d1, 2);
    float r0 = sig / d0, r1 = sig / d1;
    As[g * SAT + c0]       = f2tff(e00 * r0);
    As[g * SAT + c1]       = f2tff(e01 * r0);
    As[g * SAT + c2]       = f2tff(e02 * r0);
    As[g * SAT + c3]       = f2tff(e03 * r0);
    As[(g + 8) * SAT + c0] = f2tff(e10 * r1);
    As[(g + 8) * SAT + c1] = f2tff(e11 * r1);
    As[(g + 8) * SAT + c2] = f2tff(e12 * r1);
    As[(g + 8) * SAT + c3] = f2tff(e13 * r1);
}

// -------------------------------- main --------------------------------------
__global__ void __launch_bounds__(THREADS, 2)
lc_main(const float* __restrict__ hsrc, const float* __restrict__ Wlat,
        const float* __restrict__ gate, float* __restrict__ out) {
    extern __shared__ float smem[];
    const int tid = threadIdx.x;
    const int w = tid >> 5, lane = tid & 31;
    const int g = lane >> 2, tg = lane & 3;
    const int tp = w >> 1, nhf = w & 1;
    const long tokbase = (long)blockIdx.x * 4;
    const bool gok = (g < 5);

    float* Xs0 = smem + SM_X + (2 * tp) * XTOK;
    float* Xs1 = Xs0 + XTOK;
    float* Cb = smem + SM_C + w * 1088;          // per-warp, single buffer
    float* As0 = smem + SM_A + (2 * tp) * ATOK;
    float* As1 = As0 + ATOK;
    float* Wls = smem + SM_W;
    uint4* panq = (uint4*)(smem + SM_P);

    // issue phase-1 stage 0 copies first (overlap with X load)
    issue_p1(panq, 0, tid);
    CP_COMMIT();

    // ---- load X: warp w loads token w (13x256 fp32) ----
    {
        const float* src = hsrc + (tokbase + w) * 3328;
        float* dst = smem + SM_X + w * XTOK;
        for (int i = lane; i < 832; i += 32) {
            int row = i >> 6, c4 = (i & 63) << 2;
            *(float4*)(dst + row * SXR + c4) = *(const float4*)(src + row * 256 + c4);
        }
    }
    for (int idx = tid; idx < 208; idx += THREADS) {
        int p = idx >> 4, r = idx & 15;
        Wls[p * 16 + r] = (r < 13) ? Wlat[p * 13 + r] : 0.f;
    }
    float sig;
    { float gv = gate[0]; sig = 1.f / (1.f + __expf(-gv)); }

    // =========== phase 1: Y = X Wa (bf16, half's nc), S partial ===========
    float sa[4] = {0, 0, 0, 0}, sb[4] = {0, 0, 0, 0};
    float sc[4] = {0, 0, 0, 0}, sd[4] = {0, 0, 0, 0};

    for (int ncl = 0; ncl < 2; ++ncl) {
        const int nc = 2 * nhf + ncl;
        float ya0[8][4], ya1[8][4];
#pragma unroll
        for (int i = 0; i < 8; ++i)
#pragma unroll
            for (int j = 0; j < 4; ++j) { ya0[i][j] = 0.f; ya1[i][j] = 0.f; }

        for (int pr = 0; pr < 4; ++pr) {
            const int st = ncl * 4 + pr;
            CP_WAIT0();                 // stage st copies done (issued last)
            __syncthreads();            // visible to all; prior compute done
            if (st < 7) { issue_p1(panq, st + 1, tid); CP_COMMIT(); }
            else        { issue_p2(panq, 0, tid);      CP_COMMIT(); }

            const uint4* bufq = panq + (st & 1) * 1024 + nhf * 512;
#pragma unroll
            for (int hf = 0; hf < 2; ++hf) {
                const uint4* c4p = bufq + hf * 256;
#pragma unroll
                for (int s = 0; s < 2; ++s) {
                    int kc = pr * 64 + hf * 32 + s * 16;
                    uint32_t a00 = pk2(Xs0 + g * SXR + kc + 2 * tg);
                    uint32_t a01 = gok ? pk2(Xs0 + (g + 8) * SXR + kc + 2 * tg) : 0u;
                    uint32_t a02 = pk2(Xs0 + g * SXR + kc + 8 + 2 * tg);
                    uint32_t a03 = gok ? pk2(Xs0 + (g + 8) * SXR + kc + 8 + 2 * tg) : 0u;
                    uint32_t a10 = pk2(Xs1 + g * SXR + kc + 2 * tg);
                    uint32_t a11 = gok ? pk2(Xs1 + (g + 8) * SXR + kc + 2 * tg) : 0u;
                    uint32_t a12 = pk2(Xs1 + g * SXR + kc + 8 + 2 * tg);
                    uint32_t a13 = gok ? pk2(Xs1 + (g + 8) * SXR + kc + 8 + 2 * tg) : 0u;
#pragma unroll
                    for (int q = 0; q < 4; ++q) {
                        uint4 v = c4p[(s * 4 + q) * 32 + lane];
                        mmab(ya0[2 * q],     a00, a01, a02, a03, v.x, v.y);
                        mmab(ya0[2 * q + 1], a00, a01, a02, a03, v.z, v.w);
                        mmab(ya1[2 * q],     a10, a11, a12, a13, v.x, v.y);
                        mmab(ya1[2 * q + 1], a10, a11, a12, a13, v.z, v.w);
                    }
                }
            }
        }

        // flush: Y -> Cb (tf32), S += Y * X^T  (sequential tokens, single Cb)
        __syncwarp();
#pragma unroll
        for (int nt = 0; nt < 8; ++nt) {
            int c = nt * 8 + 2 * tg;
            *(float2*)(Cb + g * SCB + c) = make_float2(f2tff(ya0[nt][0]), f2tff(ya0[nt][1]));
            *(float2*)(Cb + (g + 8) * SCB + c) = make_float2(f2tff(ya0[nt][2]), f2tff(ya0[nt][3]));
        }
        __syncwarp();
#pragma unroll
        for (int ks = 0; ks < 8; ++ks) {
            int xc = nc * 64 + ks * 8;
            uint32_t a0 = __float_as_uint(Cb[g * SCB + ks * 8 + tg]);
            uint32_t a1 = __float_as_uint(Cb[(g + 8) * SCB + ks * 8 + tg]);
            uint32_t a2 = __float_as_uint(Cb[g * SCB + ks * 8 + tg + 4]);
            uint32_t a3 = __float_as_uint(Cb[(g + 8) * SCB + ks * 8 + tg + 4]);
            uint32_t b0 = f2tf(Xs0[g * SXR + xc + tg]);
            uint32_t b1 = f2tf(Xs0[g * SXR + xc + tg + 4]);
            mma8(sa, a0, a1, a2, a3, b0, b1);
            uint32_t c0 = gok ? f2tf(Xs0[(g + 8) * SXR + xc + tg]) : 0u;
            uint32_t c1 = gok ? f2tf(Xs0[(g + 8) * SXR + xc + tg + 4]) : 0u;
            mma8(sb, a0, a1, a2, a3, c0, c1);
        }
        __syncwarp();
#pragma unroll
        for (int nt = 0; nt < 8; ++nt) {
            int c = nt * 8 + 2 * tg;
            *(float2*)(Cb + g * SCB + c) = make_float2(f2tff(ya1[nt][0]), f2tff(ya1[nt][1]));
            *(float2*)(Cb + (g + 8) * SCB + c) = make_float2(f2tff(ya1[nt][2]), f2tff(ya1[nt][3]));
        }
        __syncwarp();
#pragma unroll
        for (int ks = 0; ks < 8; ++ks) {
            int xc = nc * 64 + ks * 8;
            uint32_t a0 = __float_as_uint(Cb[g * SCB + ks * 8 + tg]);
            uint32_t a1 = __float_as_uint(Cb[(g + 8) * SCB + ks * 8 + tg]);
            uint32_t a2 = __float_as_uint(Cb[g * SCB + ks * 8 + tg + 4]);
            uint32_t a3 = __float_as_uint(Cb[(g + 8) * SCB + ks * 8 + tg + 4]);
            uint32_t b0 = f2tf(Xs1[g * SXR + xc + tg]);
            uint32_t b1 = f2tf(Xs1[g * SXR + xc + tg + 4]);
            mma8(sc, a0, a1, a2, a3, b0, b1);
            uint32_t c0 = gok ? f2tf(Xs1[(g + 8) * SXR + xc + tg]) : 0u;
            uint32_t c1 = gok ? f2tf(Xs1[(g + 8) * SXR + xc + tg + 4]) : 0u;
            mma8(sd, a0, a1, a2, a3, c0, c1);
        }
        __syncwarp();
    }

    // ---------- S cross-half reduction + softmax ----------
    __syncthreads();
    {
        float* my = smem + SM_C + (w * 32 + lane) * 16;
#pragma unroll
        for (int i = 0; i < 4; ++i) {
            my[i] = sa[i]; my[4 + i] = sb[i]; my[8 + i] = sc[i]; my[12 + i] = sd[i];
        }
    }
    __syncthreads();
    if (nhf == 0) {
        const float* ot = smem + SM_C + ((w ^ 1) * 32 + lane) * 16;
#pragma unroll
        for (int i = 0; i < 4; ++i) {
            sa[i] += ot[i]; sb[i] += ot[4 + i]; sc[i] += ot[8 + i]; sd[i] += ot[12 + i];
        }
        softmax_sig(sa, sb, As0, sig, g, tg);
        softmax_sig(sc, sd, As1, sig, g, tg);
    }
    __syncthreads();   // As visible to both halves

    // ===== phase 2: Z = (sig*A) X (tf32, regs), R_half = Z Wb (bf16) =====
    float ra0[16][4], ra1[16][4];
#pragma unroll
    for (int i = 0; i < 16; ++i)
#pragma unroll
        for (int j = 0; j < 4; ++j) { ra0[i][j] = 0.f; ra1[i][j] = 0.f; }

    float za0[8][4], za1[8][4];
    for (int dc = 0; dc < 4; ++dc) {
        // Zchunk per token (registers only)
#pragma unroll
        for (int tok = 0; tok < 2; ++tok) {
            const float* Asx = tok ? As1 : As0;
            const float* Xsx = tok ? Xs1 : Xs0;
            float (*za)[4] = tok ? za1 : za0;
#pragma unroll
            for (int i = 0; i < 8; ++i)
#pragma unroll
                for (int j = 0; j < 4; ++j) za[i][j] = 0.f;
#pragma unroll
            for (int ks = 0; ks < 2; ++ks) {
                uint32_t a0 = __float_as_uint(Asx[g * SAT + ks * 8 + tg]);
                uint32_t a1 = __float_as_uint(Asx[(g + 8) * SAT + ks * 8 + tg]);
                uint32_t a2 = __float_as_uint(Asx[g * SAT + ks * 8 + tg + 4]);
                uint32_t a3 = __float_as_uint(Asx[(g + 8) * SAT + ks * 8 + tg + 4]);
                int r0w = ks * 8 + tg;
                int r1w = ks * 8 + tg + 4;
                bool rok = r1w < 13;
#pragma unroll
                for (int nt = 0; nt < 8; ++nt) {
                    int xc = dc * 64 + nt * 8 + g;
                    uint32_t b0 = f2tf(Xsx[r0w * SXR + xc]);
                    uint32_t b1 = rok ? f2tf(Xsx[r1w * SXR + xc]) : 0u;
                    mma8(za[nt], a0, a1, a2, a3, b0, b1);
                }
            }
        }

        for (int kp2 = 0; kp2 < 2; ++kp2) {
            const int st = dc * 2 + kp2;
            CP_WAIT0();
            __syncthreads();
            if (st < 7) { issue_p2(panq, st + 1, tid); CP_COMMIT(); }

            const uint4* c4p = panq + (st & 1) * 1024 + nhf * 512;
#pragma unroll
            for (int s = 0; s < 2; ++s) {
                int t0 = kp2 * 4 + 2 * s;
                uint32_t a00 = pkr(za0[t0][0], za0[t0][1]);
                uint32_t a01 = pkr(za0[t0][2], za0[t0][3]);
                uint32_t a02 = pkr(za0[t0 + 1][0], za0[t0 + 1][1]);
                uint32_t a03 = pkr(za0[t0 + 1][2], za0[t0 + 1][3]);
                uint32_t a10 = pkr(za1[t0][0], za1[t0][1]);
                uint32_t a11 = pkr(za1[t0][2], za1[t0][3]);
                uint32_t a12 = pkr(za1[t0 + 1][0], za1[t0 + 1][1]);
                uint32_t a13 = pkr(za1[t0 + 1][2], za1[t0 + 1][3]);
#pragma unroll
                for (int q = 0; q < 8; ++q) {
                    uint4 v = c4p[(s * 8 + q) * 32 + lane];
                    mmab(ra0[2 * q],     a00, a01, a02, a03, v.x, v.y);
                    mmab(ra0[2 * q + 1], a00, a01, a02, a03, v.z, v.w);
                    mmab(ra1[2 * q],     a10, a11, a12, a13, v.x, v.y);
                    mmab(ra1[2 * q + 1], a10, a11, a12, a13, v.z, v.w);
                }
            }
        }
    }

    // ---- epilogue: exact fp32 residual into ra, then store (cols of half) ----
    const long obase0 = (tokbase + 2 * tp) * 3328;
    {
#pragma unroll 1
        for (int p = 0; p < 13; ++p) {
            float wg = Wls[p * 16 + g];
            float wg8 = Wls[p * 16 + g + 8];
#pragma unroll
            for (int nt = 0; nt < 16; ++nt) {
                int c = nhf * 128 + nt * 8 + 2 * tg;
                float2 x0 = *(float2*)(Xs0 + p * SXR + c);
                ra0[nt][0] += wg * x0.x;
                ra0[nt][1] += wg * x0.y;
                ra0[nt][2] += wg8 * x0.x;
                ra0[nt][3] += wg8 * x0.y;
                float2 x1 = *(float2*)(Xs1 + p * SXR + c);
                ra1[nt][0] += wg * x1.x;
                ra1[nt][1] += wg * x1.y;
                ra1[nt][2] += wg8 * x1.x;
                ra1[nt][3] += wg8 * x1.y;
            }
        }
#pragma unroll
        for (int nt = 0; nt < 16; ++nt) {
            int c = nhf * 128 + nt * 8 + 2 * tg;
            *(float2*)(out + obase0 + g * 256 + c) = make_float2(ra0[nt][0], ra0[nt][1]);
            *(float2*)(out + obase0 + 3328 + g * 256 + c) = make_float2(ra1[nt][0], ra1[nt][1]);
            if (gok) {
                *(float2*)(out + obase0 + (g + 8) * 256 + c) = make_float2(ra0[nt][2], ra0[nt][3]);
                *(float2*)(out + obase0 + 3328 + (g + 8) * 256 + c) = make_float2(ra1[nt][2], ra1[nt][3]);
            }
        }
    }
}

// ------------------------------ launch --------------------------------------
extern "C" void kernel_launch(void* const* d_in, const int* in_sizes, int n_in,
                              void* d_out, int out_size) {
    const float* h    = (const float*)d_in[0];
    const float* Wq   = (const float*)d_in[1];
    const float* Wk   = (const float*)d_in[2];
    const float* Wv   = (const float*)d_in[3];
    const float* Wo   = (const float*)d_in[4];
    const float* Wlat = (const float*)d_in[5];
    const float* gate = (const float*)d_in[6];
    float* out = (float*)d_out;

    static bool attr_done = false;
    if (!attr_done) {
        cudaFuncSetAttribute(lc_main, cudaFuncAttributeMaxDynamicSharedMemorySize, SMEM_BYTES);
        attr_done = true;
    }

    lc_setup<<<dim3(16, 16, 2), dim3(16, 16)>>>(Wq, Wk, Wv, Wo);
    lc_main<<<4096, THREADS, SMEM_BYTES>>>(h, Wlat, gate, out);
}

// round 13
// speedup vs baseline: 1.6524x; 1.1697x over previous
#include <cuda_runtime.h>
#include <cuda_bf16.h>
#include <cstdint>

// out = Wlat^T X  +  sigmoid(gate) * softmax(X Wa X^T) X Wb
//   Wa[k][n] = sum_e Wq[e,k] Wk[e,n] / 16    (bf16 fragment-packed, g_Wa4)
//   Wb[k][n] = sum_e Wo[n,e] Wv[e,k]         (bf16 fragment-packed, g_Wb4)
// 128 thr/CTA, 2 CTA/SM, 4 tokens/CTA. Warp = (token-pair tp, N-half nhf).
// Weight fragments read DIRECTLY from GMEM (L2/L1-resident) via LDG.128 —
// no smem staging, no cp.async, no per-stage barriers.
// Big GEMMs bf16 m16n8k16 (B frags shared across token pair);
// S=Y*X^T, Z=A*X and the Wlat residual: tf32 m16n8k8.

#define THREADS 128
#define SXR 260        // X smem row stride (fp32)
#define XTOK 3380      // 13*260
#define SCB 68         // phase-1 chunk buffer stride (per-warp)
#define SAT 20         // attn stride
#define ATOK 320       // 16*20

#define SM_X 0                 // 4*3380 = 13520 floats
#define SM_C 13520             // 4*1088 = 4352 (per-warp Cb; S-reduce scratch)
#define SM_A 17872             // 4*320 = 1280
#define SM_W 19152             // 256 (Wls 16x16, zero-padded)
#define SMEM_FLOATS 19408
#define SMEM_BYTES (SMEM_FLOATS * 4)   // 77632 -> 2 CTAs/SM

// Wa: 32 panels (nc*8+kp), panel = 32K x 64N bf16 = 256 uint4
// Wb: 16 panels (nh*8+dc*2+kp2), panel = 32K x 128N bf16 = 512 uint4
__device__ uint4 g_Wa4[32 * 256];
__device__ uint4 g_Wb4[16 * 512];

__device__ __forceinline__ uint32_t f2tf(float x) {
    uint32_t r;
    asm("cvt.rna.tf32.f32 %0, %1;" : "=r"(r) : "f"(x));
    return r;
}
__device__ __forceinline__ float f2tff(float x) {
    return __uint_as_float(f2tf(x));
}
__device__ __forceinline__ uint32_t pk2(const float* p) {
    float2 v = *(const float2*)p;
    uint32_t r;
    asm("cvt.rn.bf16x2.f32 %0, %1, %2;" : "=r"(r) : "f"(v.y), "f"(v.x));
    return r;
}
__device__ __forceinline__ uint32_t pkr(float lo, float hi) {
    uint32_t r;
    asm("cvt.rn.bf16x2.f32 %0, %1, %2;" : "=r"(r) : "f"(hi), "f"(lo));
    return r;
}

__device__ __forceinline__ void mma8(float* d,
                                     uint32_t a0, uint32_t a1, uint32_t a2, uint32_t a3,
                                     uint32_t b0, uint32_t b1) {
    asm volatile(
        "mma.sync.aligned.m16n8k8.row.col.f32.tf32.tf32.f32 "
        "{%0,%1,%2,%3},{%4,%5,%6,%7},{%8,%9},{%0,%1,%2,%3};\n"
        : "+f"(d[0]), "+f"(d[1]), "+f"(d[2]), "+f"(d[3])
        : "r"(a0), "r"(a1), "r"(a2), "r"(a3), "r"(b0), "r"(b1));
}
__device__ __forceinline__ void mmab(float* d,
                                     uint32_t a0, uint32_t a1, uint32_t a2, uint32_t a3,
                                     uint32_t b0, uint32_t b1) {
    asm volatile(
        "mma.sync.aligned.m16n8k16.row.col.f32.bf16.bf16.f32 "
        "{%0,%1,%2,%3},{%4,%5,%6,%7},{%8,%9},{%0,%1,%2,%3};\n"
        : "+f"(d[0]), "+f"(d[1]), "+f"(d[2]), "+f"(d[3])
        : "r"(a0), "r"(a1), "r"(a2), "r"(a3), "r"(b0), "r"(b1));
}

// ------------------------------- setup --------------------------------------
__global__ void lc_setup(const float* __restrict__ Wq, const float* __restrict__ Wk,
                         const float* __restrict__ Wv, const float* __restrict__ Wo) {
    __shared__ float sA[16][17], sB[16][17];
    const int tx = threadIdx.x, ty = threadIdx.y;
    const int k0 = blockIdx.x * 16, n0 = blockIdx.y * 16;
    const bool isA = (blockIdx.z == 0);
    float acc = 0.f;
    for (int e0 = 0; e0 < 256; e0 += 16) {
        const float* Mp = isA ? Wq : Wv;
        sA[ty][tx] = Mp[(e0 + ty) * 256 + k0 + tx];
        if (isA) sB[ty][tx] = Wk[(e0 + ty) * 256 + n0 + tx];
        else     sB[tx][ty] = Wo[(n0 + ty) * 256 + e0 + tx];
        __syncthreads();
#pragma unroll
        for (int e = 0; e < 16; ++e) acc += sA[e][tx] * sB[e][ty];
        __syncthreads();
    }
    const int k = k0 + tx, n = n0 + ty;
    const int r = k & 31, s = r >> 4, rr = r & 15;
    const int half = rr >> 3, tg = (rr & 7) >> 1, j = rr & 1;
    if (isA) {
        acc *= (1.0f / 16.0f);
        int kp = k >> 5;
        int nc = n >> 6, nn = n & 63, nt = nn >> 3, g = nn & 7, q = nt >> 1;
        int u32idx = ((s * 4 + q) * 32 + g * 4 + tg) * 4 + (nt & 1) * 2 + half;
        ((__nv_bfloat16*)g_Wa4)[((nc * 8 + kp) * 1024 + u32idx) * 2 + j] =
            __float2bfloat16(acc);
    } else {
        int dc = k >> 6, kp2 = (k >> 5) & 1;
        int nh = n >> 7, nn = n & 127, nt = nn >> 3, g = nn & 7, q = nt >> 1;
        int u32idx = ((s * 8 + q) * 32 + g * 4 + tg) * 4 + (nt & 1) * 2 + half;
        ((__nv_bfloat16*)g_Wb4)[((nh * 8 + dc * 2 + kp2) * 2048 + u32idx) * 2 + j] =
            __float2bfloat16(acc);
    }
}

// ---------------------- softmax (sig folded) --------------------------------
__device__ __forceinline__ void softmax_sig(const float* s0, const float* s1,
                                            float* As, float sig, int g, int tg) {
    int c0 = 2 * tg, c1 = 2 * tg + 1, c2 = 8 + 2 * tg, c3 = 9 + 2 * tg;
    bool v0 = c0 < 13, v1 = c1 < 13, v2 = c2 < 13, v3 = c3 < 13;
    const float NEG = -1e30f;
    float m0 = fmaxf(fmaxf(v0 ? s0[0] : NEG, v1 ? s0[1] : NEG),
                     fmaxf(v2 ? s1[0] : NEG, v3 ? s1[1] : NEG));
    float m1 = fmaxf(fmaxf(v0 ? s0[2] : NEG, v1 ? s0[3] : NEG),
                     fmaxf(v2 ? s1[2] : NEG, v3 ? s1[3] : NEG));
    m0 = fmaxf(m0, __shfl_xor_sync(0xffffffffu, m0, 1));
    m0 = fmaxf(m0, __shfl_xor_sync(0xffffffffu, m0, 2));
    m1 = fmaxf(m1, __shfl_xor_sync(0xffffffffu, m1, 1));
    m1 = fmaxf(m1, __shfl_xor_sync(0xffffffffu, m1, 2));
    float e00 = v0 ? __expf(s0[0] - m0) : 0.f;
    float e01 = v1 ? __expf(s0[1] - m0) : 0.f;
    float e02 = v2 ? __expf(s1[0] - m0) : 0.f;
    float e03 = v3 ? __expf(s1[1] - m0) : 0.f;
    float e10 = v0 ? __expf(s0[2] - m1) : 0.f;
    float e11 = v1 ? __expf(s0[3] - m1) : 0.f;
    float e12 = v2 ? __expf(s1[2] - m1) : 0.f;
    float e13 = v3 ? __expf(s1[3] - m1) : 0.f;
    float d0 = e00 + e01 + e02 + e03;
    float d1 = e10 + e11 + e12 + e13;
    d0 += __shfl_xor_sync(0xffffffffu, d0, 1);
    d0 += __shfl_xor_sync(0xffffffffu, d0, 2);
    d1 += __shfl_xor_sync(0xffffffffu, d1, 1);
    d1 += __shfl_xor_sync(0xffffffffu, d1, 2);
    float r0 = sig / d0, r1 = sig / d1;
    As[g * SAT + c0]       = f2tff(e00 * r0);
    As[g * SAT + c1]       = f2tff(e01 * r0);
    As[g * SAT + c2]       = f2tff(e02 * r0);
    As[g * SAT + c3]       = f2tff(e03 * r0);
    As[(g + 8) * SAT + c0] = f2tff(e10 * r1);
    As[(g + 8) * SAT + c1] = f2tff(e11 * r1);
    As[(g + 8) * SAT + c2] = f2tff(e12 * r1);
    As[(g + 8) * SAT + c3] = f2tff(e13 * r1);
}

// -------------------------------- main --------------------------------------
__global__ void __launch_bounds__(THREADS, 2)
lc_main(const float* __restrict__ hsrc, const float* __restrict__ Wlat,
        const float* __restrict__ gate, float* __restrict__ out) {
    extern __shared__ float smem[];
    const int tid = threadIdx.x;
    const int w = tid >> 5, lane = tid & 31;
    const int g = lane >> 2, tg = lane & 3;
    const int tp = w >> 1, nhf = w & 1;
    const long tokbase = (long)blockIdx.x * 4;
    const bool gok = (g < 5);

    float* Xs0 = smem + SM_X + (2 * tp) * XTOK;
    float* Xs1 = Xs0 + XTOK;
    float* Cb = smem + SM_C + w * 1088;
    float* As0 = smem + SM_A + (2 * tp) * ATOK;
    float* As1 = As0 + ATOK;
    float* Wls = smem + SM_W;

    // ---- load X: warp w loads token w (13x256 fp32) ----
    {
        const float* src = hsrc + (tokbase + w) * 3328;
        float* dst = smem + SM_X + w * XTOK;
        for (int i = lane; i < 832; i += 32) {
            int row = i >> 6, c4 = (i & 63) << 2;
            *(float4*)(dst + row * SXR + c4) = *(const float4*)(src + row * 256 + c4);
        }
    }
    // Wls 16x16, rows/cols >=13 zero
    for (int idx = tid; idx < 256; idx += THREADS) {
        int p = idx >> 4, r = idx & 15;
        Wls[idx] = (p < 13 && r < 13) ? Wlat[p * 13 + r] : 0.f;
    }
    float sig;
    { float gv = gate[0]; sig = 1.f / (1.f + __expf(-gv)); }
    __syncthreads();

    // =========== phase 1: Y = X Wa (bf16, half's nc), S partial ===========
    float sa[4] = {0, 0, 0, 0}, sb[4] = {0, 0, 0, 0};
    float sc[4] = {0, 0, 0, 0}, sd[4] = {0, 0, 0, 0};

    for (int ncl = 0; ncl < 2; ++ncl) {
        const int nc = 2 * nhf + ncl;
        float ya0[8][4], ya1[8][4];
#pragma unroll
        for (int i = 0; i < 8; ++i)
#pragma unroll
            for (int j = 0; j < 4; ++j) { ya0[i][j] = 0.f; ya1[i][j] = 0.f; }

        for (int kp = 0; kp < 8; ++kp) {
            const uint4* gp = g_Wa4 + (nc * 8 + kp) * 256;
            uint4 v[8];
#pragma unroll
            for (int i = 0; i < 8; ++i) v[i] = __ldg(gp + i * 32 + lane);
#pragma unroll
            for (int s = 0; s < 2; ++s) {
                int kc = kp * 32 + s * 16;
                uint32_t a00 = pk2(Xs0 + g * SXR + kc + 2 * tg);
                uint32_t a01 = gok ? pk2(Xs0 + (g + 8) * SXR + kc + 2 * tg) : 0u;
                uint32_t a02 = pk2(Xs0 + g * SXR + kc + 8 + 2 * tg);
                uint32_t a03 = gok ? pk2(Xs0 + (g + 8) * SXR + kc + 8 + 2 * tg) : 0u;
                uint32_t a10 = pk2(Xs1 + g * SXR + kc + 2 * tg);
                uint32_t a11 = gok ? pk2(Xs1 + (g + 8) * SXR + kc + 2 * tg) : 0u;
                uint32_t a12 = pk2(Xs1 + g * SXR + kc + 8 + 2 * tg);
                uint32_t a13 = gok ? pk2(Xs1 + (g + 8) * SXR + kc + 8 + 2 * tg) : 0u;
#pragma unroll
                for (int q = 0; q < 4; ++q) {
                    uint4 vv = v[s * 4 + q];
                    mmab(ya0[2 * q],     a00, a01, a02, a03, vv.x, vv.y);
                    mmab(ya0[2 * q + 1], a00, a01, a02, a03, vv.z, vv.w);
                    mmab(ya1[2 * q],     a10, a11, a12, a13, vv.x, vv.y);
                    mmab(ya1[2 * q + 1], a10, a11, a12, a13, vv.z, vv.w);
                }
            }
        }

        // flush: Y -> Cb (tf32), S += Y * X^T  (sequential tokens, warp-private Cb)
        __syncwarp();
#pragma unroll
        for (int nt = 0; nt < 8; ++nt) {
            int c = nt * 8 + 2 * tg;
            *(float2*)(Cb + g * SCB + c) = make_float2(f2tff(ya0[nt][0]), f2tff(ya0[nt][1]));
            *(float2*)(Cb + (g + 8) * SCB + c) = make_float2(f2tff(ya0[nt][2]), f2tff(ya0[nt][3]));
        }
        __syncwarp();
#pragma unroll
        for (int ks = 0; ks < 8; ++ks) {
            int xc = nc * 64 + ks * 8;
            uint32_t a0 = __float_as_uint(Cb[g * SCB + ks * 8 + tg]);
            uint32_t a1 = __float_as_uint(Cb[(g + 8) * SCB + ks * 8 + tg]);
            uint32_t a2 = __float_as_uint(Cb[g * SCB + ks * 8 + tg + 4]);
            uint32_t a3 = __float_as_uint(Cb[(g + 8) * SCB + ks * 8 + tg + 4]);
            uint32_t b0 = f2tf(Xs0[g * SXR + xc + tg]);
            uint32_t b1 = f2tf(Xs0[g * SXR + xc + tg + 4]);
            mma8(sa, a0, a1, a2, a3, b0, b1);
            uint32_t c0 = gok ? f2tf(Xs0[(g + 8) * SXR + xc + tg]) : 0u;
            uint32_t c1 = gok ? f2tf(Xs0[(g + 8) * SXR + xc + tg + 4]) : 0u;
            mma8(sb, a0, a1, a2, a3, c0, c1);
        }
        __syncwarp();
#pragma unroll
        for (int nt = 0; nt < 8; ++nt) {
            int c = nt * 8 + 2 * tg;
            *(float2*)(Cb + g * SCB + c) = make_float2(f2tff(ya1[nt][0]), f2tff(ya1[nt][1]));
            *(float2*)(Cb + (g + 8) * SCB + c) = make_float2(f2tff(ya1[nt][2]), f2tff(ya1[nt][3]));
        }
        __syncwarp();
#pragma unroll
        for (int ks = 0; ks < 8; ++ks) {
            int xc = nc * 64 + ks * 8;
            uint32_t a0 = __float_as_uint(Cb[g * SCB + ks * 8 + tg]);
            uint32_t a1 = __float_as_uint(Cb[(g + 8) * SCB + ks * 8 + tg]);
            uint32_t a2 = __float_as_uint(Cb[g * SCB + ks * 8 + tg + 4]);
            uint32_t a3 = __float_as_uint(Cb[(g + 8) * SCB + ks * 8 + tg + 4]);
            uint32_t b0 = f2tf(Xs1[g * SXR + xc + tg]);
            uint32_t b1 = f2tf(Xs1[g * SXR + xc + tg + 4]);
            mma8(sc, a0, a1, a2, a3, b0, b1);
            uint32_t c0 = gok ? f2tf(Xs1[(g + 8) * SXR + xc + tg]) : 0u;
            uint32_t c1 = gok ? f2tf(Xs1[(g + 8) * SXR + xc + tg + 4]) : 0u;
            mma8(sd, a0, a1, a2, a3, c0, c1);
        }
        __syncwarp();
    }

    // ---------- S cross-half reduction + softmax ----------
    __syncthreads();
    {
        float* my = smem + SM_C + (w * 32 + lane) * 16;
#pragma unroll
        for (int i = 0; i < 4; ++i) {
            my[i] = sa[i]; my[4 + i] = sb[i]; my[8 + i] = sc[i]; my[12 + i] = sd[i];
        }
    }
    __syncthreads();
    if (nhf == 0) {
        const float* ot = smem + SM_C + ((w ^ 1) * 32 + lane) * 16;
#pragma unroll
        for (int i = 0; i < 4; ++i) {
            sa[i] += ot[i]; sb[i] += ot[4 + i]; sc[i] += ot[8 + i]; sd[i] += ot[12 + i];
        }
        softmax_sig(sa, sb, As0, sig, g, tg);
        softmax_sig(sc, sd, As1, sig, g, tg);
    }
    __syncthreads();   // As visible to both halves

    // ===== phase 2: Z = (sig*A) X (tf32, regs), R_half = Z Wb (bf16) =====
    float ra0[16][4], ra1[16][4];
#pragma unroll
    for (int i = 0; i < 16; ++i)
#pragma unroll
        for (int j = 0; j < 4; ++j) { ra0[i][j] = 0.f; ra1[i][j] = 0.f; }

    float za0[8][4], za1[8][4];
    for (int dc = 0; dc < 4; ++dc) {
        // Zchunk per token (registers only)
#pragma unroll
        for (int tok = 0; tok < 2; ++tok) {
            const float* Asx = tok ? As1 : As0;
            const float* Xsx = tok ? Xs1 : Xs0;
            float (*za)[4] = tok ? za1 : za0;
#pragma unroll
            for (int i = 0; i < 8; ++i)
#pragma unroll
                for (int j = 0; j < 4; ++j) za[i][j] = 0.f;
#pragma unroll
            for (int ks = 0; ks < 2; ++ks) {
                uint32_t a0 = __float_as_uint(Asx[g * SAT + ks * 8 + tg]);
                uint32_t a1 = __float_as_uint(Asx[(g + 8) * SAT + ks * 8 + tg]);
                uint32_t a2 = __float_as_uint(Asx[g * SAT + ks * 8 + tg + 4]);
                uint32_t a3 = __float_as_uint(Asx[(g + 8) * SAT + ks * 8 + tg + 4]);
                int r0w = ks * 8 + tg;
                int r1w = ks * 8 + tg + 4;
                bool rok = r1w < 13;
#pragma unroll
                for (int nt = 0; nt < 8; ++nt) {
                    int xc = dc * 64 + nt * 8 + g;
                    uint32_t b0 = f2tf(Xsx[r0w * SXR + xc]);
                    uint32_t b1 = rok ? f2tf(Xsx[r1w * SXR + xc]) : 0u;
                    mma8(za[nt], a0, a1, a2, a3, b0, b1);
                }
            }
        }

        for (int kp2 = 0; kp2 < 2; ++kp2) {
            const int st = dc * 2 + kp2;
            const uint4* gp = g_Wb4 + (nhf * 8 + st) * 512;
#pragma unroll
            for (int s = 0; s < 2; ++s) {
                uint4 v[8];
#pragma unroll
                for (int i = 0; i < 8; ++i) v[i] = __ldg(gp + (s * 8 + i) * 32 + lane);
                int t0 = kp2 * 4 + 2 * s;
                uint32_t a00 = pkr(za0[t0][0], za0[t0][1]);
                uint32_t a01 = pkr(za0[t0][2], za0[t0][3]);
                uint32_t a02 = pkr(za0[t0 + 1][0], za0[t0 + 1][1]);
                uint32_t a03 = pkr(za0[t0 + 1][2], za0[t0 + 1][3]);
                uint32_t a10 = pkr(za1[t0][0], za1[t0][1]);
                uint32_t a11 = pkr(za1[t0][2], za1[t0][3]);
                uint32_t a12 = pkr(za1[t0 + 1][0], za1[t0 + 1][1]);
                uint32_t a13 = pkr(za1[t0 + 1][2], za1[t0 + 1][3]);
#pragma unroll
                for (int q = 0; q < 8; ++q) {
                    uint4 vv = v[q];
                    mmab(ra0[2 * q],     a00, a01, a02, a03, vv.x, vv.y);
                    mmab(ra0[2 * q + 1], a00, a01, a02, a03, vv.z, vv.w);
                    mmab(ra1[2 * q],     a10, a11, a12, a13, vv.x, vv.y);
                    mmab(ra1[2 * q + 1], a10, a11, a12, a13, vv.z, vv.w);
                }
            }
        }
    }

    // ---- epilogue: residual via tf32 mma folded into ra, then store ----
    {
        uint32_t wl[2][4];
#pragma unroll
        for (int ks = 0; ks < 2; ++ks) {
            int k0 = ks * 8 + tg, k1 = ks * 8 + tg + 4;
            wl[ks][0] = f2tf(Wls[k0 * 16 + g]);
            wl[ks][1] = f2tf(Wls[k0 * 16 + g + 8]);
            wl[ks][2] = f2tf(Wls[k1 * 16 + g]);
            wl[ks][3] = f2tf(Wls[k1 * 16 + g + 8]);
        }
#pragma unroll
        for (int nt = 0; nt < 16; ++nt) {
            int cn = nhf * 128 + nt * 8 + g;
#pragma unroll
            for (int ks = 0; ks < 2; ++ks) {
                int r0w = ks * 8 + tg;
                int r1w = ks * 8 + tg + 4;
                bool rok = r1w < 13;
                uint32_t b0 = f2tf(Xs0[r0w * SXR + cn]);
                uint32_t b1 = rok ? f2tf(Xs0[r1w * SXR + cn]) : 0u;
                mma8(ra0[nt], wl[ks][0], wl[ks][1], wl[ks][2], wl[ks][3], b0, b1);
                b0 = f2tf(Xs1[r0w * SXR + cn]);
                b1 = rok ? f2tf(Xs1[r1w * SXR + cn]) : 0u;
                mma8(ra1[nt], wl[ks][0], wl[ks][1], wl[ks][2], wl[ks][3], b0, b1);
            }
        }
    }
    const long obase0 = (tokbase + 2 * tp) * 3328;
#pragma unroll
    for (int nt = 0; nt < 16; ++nt) {
        int c = nhf * 128 + nt * 8 + 2 * tg;
        *(float2*)(out + obase0 + g * 256 + c) = make_float2(ra0[nt][0], ra0[nt][1]);
        *(float2*)(out + obase0 + 3328 + g * 256 + c) = make_float2(ra1[nt][0], ra1[nt][1]);
        if (gok) {
            *(float2*)(out + obase0 + (g + 8) * 256 + c) = make_float2(ra0[nt][2], ra0[nt][3]);
            *(float2*)(out + obase0 + 3328 + (g + 8) * 256 + c) = make_float2(ra1[nt][2], ra1[nt][3]);
        }
    }
}

// ------------------------------ launch --------------------------------------
extern "C" void kernel_launch(void* const* d_in, const int* in_sizes, int n_in,
                              void* d_out, int out_size) {
    const float* h    = (const float*)d_in[0];
    const float* Wq   = (const float*)d_in[1];
    const float* Wk   = (const float*)d_in[2];
    const float* Wv   = (const float*)d_in[3];
    const float* Wo   = (const float*)d_in[4];
    const float* Wlat = (const float*)d_in[5];
    const float* gate = (const float*)d_in[6];
    float* out = (float*)d_out;

    static bool attr_done = false;
    if (!attr_done) {
        cudaFuncSetAttribute(lc_main, cudaFuncAttributeMaxDynamicSharedMemorySize, SMEM_BYTES);
        attr_done = true;
    }

    lc_setup<<<dim3(16, 16, 2), dim3(16, 16)>>>(Wq, Wk, Wv, Wo);
    lc_main<<<4096, THREADS, SMEM_BYTES>>>(h, Wlat, gate, out);
}

// round 14
// speedup vs baseline: 1.6747x; 1.0135x over previous
#include <cuda_runtime.h>
#include <cuda_bf16.h>
#include <cstdint>

// out = Wlat^T X  +  sigmoid(gate) * softmax(X Wa X^T) X Wb
//   Wa[k][n] = sum_e Wq[e,k] Wk[e,n] / 16    (bf16 fragment-packed, g_Wa4)
//   Wb[k][n] = sum_e Wo[n,e] Wv[e,k]         (bf16 fragment-packed, g_Wb4)
// 128 thr/CTA, 2 CTA/SM, 4 tokens/CTA. Warp = (token-pair tp, N-half nhf).
// Weight fragments read DIRECTLY from GMEM (L2/L1-resident) via LDG.128.
// X kept in smem twice: fp32 (S/Z/residual, tf32 mma) and pre-packed bf16x2
// (phase-1 A operands -> one LDS.32 per fragment, no cvt in the hot loop).
// Big GEMMs bf16 m16n8k16; S=Y*X^T, Z=A*X, residual: tf32 m16n8k8.

#define THREADS 128
#define SXR 260        // X fp32 smem row stride
#define XTOK 3380      // 13*260
#define XBR 132        // X bf16 copy row stride in uint32 (264 bf16)
#define XBTOK 1716     // 13*132 uint32 per token
#define SCB 68         // phase-1 chunk buffer stride (per-warp)
#define SAT 20         // attn stride
#define ATOK 320       // 16*20

#define SM_X 0                 // 4*3380 = 13520 floats
#define SM_C 13520             // 4*1088 = 4352
#define SM_A 17872             // 4*320 = 1280
#define SM_W 19152             // 256 (Wls 16x16 zero-padded)
#define SM_XB 19408            // 4*1716 = 6864 floats (bf16 X copies)
#define SMEM_FLOATS 26272
#define SMEM_BYTES (SMEM_FLOATS * 4)   // 105088 -> 2 CTAs/SM

// Wa: 32 panels (nc*8+kp), panel = 32K x 64N bf16 = 256 uint4
// Wb: 16 panels (nh*8+dc*2+kp2), panel = 32K x 128N bf16 = 512 uint4
__device__ uint4 g_Wa4[32 * 256];
__device__ uint4 g_Wb4[16 * 512];

__device__ __forceinline__ uint32_t f2tf(float x) {
    uint32_t r;
    asm("cvt.rna.tf32.f32 %0, %1;" : "=r"(r) : "f"(x));
    return r;
}
__device__ __forceinline__ float f2tff(float x) {
    return __uint_as_float(f2tf(x));
}
__device__ __forceinline__ uint32_t pkr(float lo, float hi) {
    uint32_t r;
    asm("cvt.rn.bf16x2.f32 %0, %1, %2;" : "=r"(r) : "f"(hi), "f"(lo));
    return r;
}

__device__ __forceinline__ void mma8(float* d,
                                     uint32_t a0, uint32_t a1, uint32_t a2, uint32_t a3,
                                     uint32_t b0, uint32_t b1) {
    asm volatile(
        "mma.sync.aligned.m16n8k8.row.col.f32.tf32.tf32.f32 "
        "{%0,%1,%2,%3},{%4,%5,%6,%7},{%8,%9},{%0,%1,%2,%3};\n"
        : "+f"(d[0]), "+f"(d[1]), "+f"(d[2]), "+f"(d[3])
        : "r"(a0), "r"(a1), "r"(a2), "r"(a3), "r"(b0), "r"(b1));
}
__device__ __forceinline__ void mmab(float* d,
                                     uint32_t a0, uint32_t a1, uint32_t a2, uint32_t a3,
                                     uint32_t b0, uint32_t b1) {
    asm volatile(
        "mma.sync.aligned.m16n8k16.row.col.f32.bf16.bf16.f32 "
        "{%0,%1,%2,%3},{%4,%5,%6,%7},{%8,%9},{%0,%1,%2,%3};\n"
        : "+f"(d[0]), "+f"(d[1]), "+f"(d[2]), "+f"(d[3])
        : "r"(a0), "r"(a1), "r"(a2), "r"(a3), "r"(b0), "r"(b1));
}

// ------------------------------- setup --------------------------------------
__global__ void lc_setup(const float* __restrict__ Wq, const float* __restrict__ Wk,
                         const float* __restrict__ Wv, const float* __restrict__ Wo) {
    __shared__ float sA[16][17], sB[16][17];
    const int tx = threadIdx.x, ty = threadIdx.y;
    const int k0 = blockIdx.x * 16, n0 = blockIdx.y * 16;
    const bool isA = (blockIdx.z == 0);
    float acc = 0.f;
    for (int e0 = 0; e0 < 256; e0 += 16) {
        const float* Mp = isA ? Wq : Wv;
        sA[ty][tx] = Mp[(e0 + ty) * 256 + k0 + tx];
        if (isA) sB[ty][tx] = Wk[(e0 + ty) * 256 + n0 + tx];
        else     sB[tx][ty] = Wo[(n0 + ty) * 256 + e0 + tx];
        __syncthreads();
#pragma unroll
        for (int e = 0; e < 16; ++e) acc += sA[e][tx] * sB[e][ty];
        __syncthreads();
    }
    const int k = k0 + tx, n = n0 + ty;
    const int r = k & 31, s = r >> 4, rr = r & 15;
    const int half = rr >> 3, tg = (rr & 7) >> 1, j = rr & 1;
    if (isA) {
        acc *= (1.0f / 16.0f);
        int kp = k >> 5;
        int nc = n >> 6, nn = n & 63, nt = nn >> 3, g = nn & 7, q = nt >> 1;
        int u32idx = ((s * 4 + q) * 32 + g * 4 + tg) * 4 + (nt & 1) * 2 + half;
        ((__nv_bfloat16*)g_Wa4)[((nc * 8 + kp) * 1024 + u32idx) * 2 + j] =
            __float2bfloat16(acc);
    } else {
        int dc = k >> 6, kp2 = (k >> 5) & 1;
        int nh = n >> 7, nn = n & 127, nt = nn >> 3, g = nn & 7, q = nt >> 1;
        int u32idx = ((s * 8 + q) * 32 + g * 4 + tg) * 4 + (nt & 1) * 2 + half;
        ((__nv_bfloat16*)g_Wb4)[((nh * 8 + dc * 2 + kp2) * 2048 + u32idx) * 2 + j] =
            __float2bfloat16(acc);
    }
}

// ---------------------- softmax (sig folded) --------------------------------
__device__ __forceinline__ void softmax_sig(const float* s0, const float* s1,
                                            float* As, float sig, int g, int tg) {
    int c0 = 2 * tg, c1 = 2 * tg + 1, c2 = 8 + 2 * tg, c3 = 9 + 2 * tg;
    bool v0 = c0 < 13, v1 = c1 < 13, v2 = c2 < 13, v3 = c3 < 13;
    const float NEG = -1e30f;
    float m0 = fmaxf(fmaxf(v0 ? s0[0] : NEG, v1 ? s0[1] : NEG),
                     fmaxf(v2 ? s1[0] : NEG, v3 ? s1[1] : NEG));
    float m1 = fmaxf(fmaxf(v0 ? s0[2] : NEG, v1 ? s0[3] : NEG),
                     fmaxf(v2 ? s1[2] : NEG, v3 ? s1[3] : NEG));
    m0 = fmaxf(m0, __shfl_xor_sync(0xffffffffu, m0, 1));
    m0 = fmaxf(m0, __shfl_xor_sync(0xffffffffu, m0, 2));
    m1 = fmaxf(m1, __shfl_xor_sync(0xffffffffu, m1, 1));
    m1 = fmaxf(m1, __shfl_xor_sync(0xffffffffu, m1, 2));
    float e00 = v0 ? __expf(s0[0] - m0) : 0.f;
    float e01 = v1 ? __expf(s0[1] - m0) : 0.f;
    float e02 = v2 ? __expf(s1[0] - m0) : 0.f;
    float e03 = v3 ? __expf(s1[1] - m0) : 0.f;
    float e10 = v0 ? __expf(s0[2] - m1) : 0.f;
    float e11 = v1 ? __expf(s0[3] - m1) : 0.f;
    float e12 = v2 ? __expf(s1[2] - m1) : 0.f;
    float e13 = v3 ? __expf(s1[3] - m1) : 0.f;
    float d0 = e00 + e01 + e02 + e03;
    float d1 = e10 + e11 + e12 + e13;
    d0 += __shfl_xor_sync(0xffffffffu, d0, 1);
    d0 += __shfl_xor_sync(0xffffffffu, d0, 2);
    d1 += __shfl_xor_sync(0xffffffffu, d1, 1);
    d1 += __shfl_xor_sync(0xffffffffu, d1, 2);
    float r0 = sig / d0, r1 = sig / d1;
    As[g * SAT + c0]       = f2tff(e00 * r0);
    As[g * SAT + c1]       = f2tff(e01 * r0);
    As[g * SAT + c2]       = f2tff(e02 * r0);
    As[g * SAT + c3]       = f2tff(e03 * r0);
    As[(g + 8) * SAT + c0] = f2tff(e10 * r1);
    As[(g + 8) * SAT + c1] = f2tff(e11 * r1);
    As[(g + 8) * SAT + c2] = f2tff(e12 * r1);
    As[(g + 8) * SAT + c3] = f2tff(e13 * r1);
}

// -------------------------------- main --------------------------------------
__global__ void __launch_bounds__(THREADS, 2)
lc_main(const float* __restrict__ hsrc, const float* __restrict__ Wlat,
        const float* __restrict__ gate, float* __restrict__ out) {
    extern __shared__ float smem[];
    const int tid = threadIdx.x;
    const int w = tid >> 5, lane = tid & 31;
    const int g = lane >> 2, tg = lane & 3;
    const int tp = w >> 1, nhf = w & 1;
    const long tokbase = (long)blockIdx.x * 4;
    const bool gok = (g < 5);

    float* Xs0 = smem + SM_X + (2 * tp) * XTOK;
    float* Xs1 = Xs0 + XTOK;
    float* Cb = smem + SM_C + w * 1088;
    float* As0 = smem + SM_A + (2 * tp) * ATOK;
    float* As1 = As0 + ATOK;
    float* Wls = smem + SM_W;
    uint32_t* XbBase = (uint32_t*)(smem + SM_XB);
    const uint32_t* Xb0 = XbBase + (2 * tp) * XBTOK;
    const uint32_t* Xb1 = Xb0 + XBTOK;

    // ---- load X: warp w loads token w; writes fp32 + packed-bf16 copies ----
    {
        const float* src = hsrc + (tokbase + w) * 3328;
        float* dst = smem + SM_X + w * XTOK;
        uint32_t* bdst = XbBase + w * XBTOK;
        for (int i = lane; i < 832; i += 32) {
            int row = i >> 6, c4 = (i & 63) << 2;
            float4 v = *(const float4*)(src + row * 256 + c4);
            *(float4*)(dst + row * SXR + c4) = v;
            uint2 bp;
            bp.x = pkr(v.x, v.y);
            bp.y = pkr(v.z, v.w);
            *(uint2*)(bdst + row * XBR + (c4 >> 1)) = bp;
        }
    }
    // Wls 16x16, rows/cols >=13 zero
    for (int idx = tid; idx < 256; idx += THREADS) {
        int p = idx >> 4, r = idx & 15;
        Wls[idx] = (p < 13 && r < 13) ? Wlat[p * 13 + r] : 0.f;
    }
    float sig;
    { float gv = gate[0]; sig = 1.f / (1.f + __expf(-gv)); }
    __syncthreads();

    // =========== phase 1: Y = X Wa (bf16, half's nc), S partial ===========
    float sa[4] = {0, 0, 0, 0}, sb[4] = {0, 0, 0, 0};
    float sc[4] = {0, 0, 0, 0}, sd[4] = {0, 0, 0, 0};

    for (int ncl = 0; ncl < 2; ++ncl) {
        const int nc = 2 * nhf + ncl;
        float ya0[8][4], ya1[8][4];
#pragma unroll
        for (int i = 0; i < 8; ++i)
#pragma unroll
            for (int j = 0; j < 4; ++j) { ya0[i][j] = 0.f; ya1[i][j] = 0.f; }

        for (int kp = 0; kp < 8; ++kp) {
            const uint4* gp = g_Wa4 + (nc * 8 + kp) * 256;
            uint4 v[8];
#pragma unroll
            for (int i = 0; i < 8; ++i) v[i] = __ldg(gp + i * 32 + lane);
#pragma unroll
            for (int s = 0; s < 2; ++s) {
                int kc2 = kp * 16 + s * 8;   // uint32 index of k-chunk start
                uint32_t a00 = Xb0[g * XBR + kc2 + tg];
                uint32_t a01 = gok ? Xb0[(g + 8) * XBR + kc2 + tg] : 0u;
                uint32_t a02 = Xb0[g * XBR + kc2 + 4 + tg];
                uint32_t a03 = gok ? Xb0[(g + 8) * XBR + kc2 + 4 + tg] : 0u;
                uint32_t a10 = Xb1[g * XBR + kc2 + tg];
                uint32_t a11 = gok ? Xb1[(g + 8) * XBR + kc2 + tg] : 0u;
                uint32_t a12 = Xb1[g * XBR + kc2 + 4 + tg];
                uint32_t a13 = gok ? Xb1[(g + 8) * XBR + kc2 + 4 + tg] : 0u;
#pragma unroll
                for (int q = 0; q < 4; ++q) {
                    uint4 vv = v[s * 4 + q];
                    mmab(ya0[2 * q],     a00, a01, a02, a03, vv.x, vv.y);
                    mmab(ya0[2 * q + 1], a00, a01, a02, a03, vv.z, vv.w);
                    mmab(ya1[2 * q],     a10, a11, a12, a13, vv.x, vv.y);
                    mmab(ya1[2 * q + 1], a10, a11, a12, a13, vv.z, vv.w);
                }
            }
        }

        // flush: Y -> Cb (tf32), S += Y * X^T  (sequential tokens, warp-private Cb)
        __syncwarp();
#pragma unroll
        for (int nt = 0; nt < 8; ++nt) {
            int c = nt * 8 + 2 * tg;
            *(float2*)(Cb + g * SCB + c) = make_float2(f2tff(ya0[nt][0]), f2tff(ya0[nt][1]));
            *(float2*)(Cb + (g + 8) * SCB + c) = make_float2(f2tff(ya0[nt][2]), f2tff(ya0[nt][3]));
        }
        __syncwarp();
#pragma unroll
        for (int ks = 0; ks < 8; ++ks) {
            int xc = nc * 64 + ks * 8;
            uint32_t a0 = __float_as_uint(Cb[g * SCB + ks * 8 + tg]);
            uint32_t a1 = __float_as_uint(Cb[(g + 8) * SCB + ks * 8 + tg]);
            uint32_t a2 = __float_as_uint(Cb[g * SCB + ks * 8 + tg + 4]);
            uint32_t a3 = __float_as_uint(Cb[(g + 8) * SCB + ks * 8 + tg + 4]);
            uint32_t b0 = f2tf(Xs0[g * SXR + xc + tg]);
            uint32_t b1 = f2tf(Xs0[g * SXR + xc + tg + 4]);
            mma8(sa, a0, a1, a2, a3, b0, b1);
            uint32_t c0 = gok ? f2tf(Xs0[(g + 8) * SXR + xc + tg]) : 0u;
            uint32_t c1 = gok ? f2tf(Xs0[(g + 8) * SXR + xc + tg + 4]) : 0u;
            mma8(sb, a0, a1, a2, a3, c0, c1);
        }
        __syncwarp();
#pragma unroll
        for (int nt = 0; nt < 8; ++nt) {
            int c = nt * 8 + 2 * tg;
            *(float2*)(Cb + g * SCB + c) = make_float2(f2tff(ya1[nt][0]), f2tff(ya1[nt][1]));
            *(float2*)(Cb + (g + 8) * SCB + c) = make_float2(f2tff(ya1[nt][2]), f2tff(ya1[nt][3]));
        }
        __syncwarp();
#pragma unroll
        for (int ks = 0; ks < 8; ++ks) {
            int xc = nc * 64 + ks * 8;
            uint32_t a0 = __float_as_uint(Cb[g * SCB + ks * 8 + tg]);
            uint32_t a1 = __float_as_uint(Cb[(g + 8) * SCB + ks * 8 + tg]);
            uint32_t a2 = __float_as_uint(Cb[g * SCB + ks * 8 + tg + 4]);
            uint32_t a3 = __float_as_uint(Cb[(g + 8) * SCB + ks * 8 + tg + 4]);
            uint32_t b0 = f2tf(Xs1[g * SXR + xc + tg]);
            uint32_t b1 = f2tf(Xs1[g * SXR + xc + tg + 4]);
            mma8(sc, a0, a1, a2, a3, b0, b1);
            uint32_t c0 = gok ? f2tf(Xs1[(g + 8) * SXR + xc + tg]) : 0u;
            uint32_t c1 = gok ? f2tf(Xs1[(g + 8) * SXR + xc + tg + 4]) : 0u;
            mma8(sd, a0, a1, a2, a3, c0, c1);
        }
        __syncwarp();
    }

    // ---------- S cross-half reduction + softmax ----------
    __syncthreads();
    {
        float* my = smem + SM_C + (w * 32 + lane) * 16;
#pragma unroll
        for (int i = 0; i < 4; ++i) {
            my[i] = sa[i]; my[4 + i] = sb[i]; my[8 + i] = sc[i]; my[12 + i] = sd[i];
        }
    }
    __syncthreads();
    if (nhf == 0) {
        const float* ot = smem + SM_C + ((w ^ 1) * 32 + lane) * 16;
#pragma unroll
        for (int i = 0; i < 4; ++i) {
            sa[i] += ot[i]; sb[i] += ot[4 + i]; sc[i] += ot[8 + i]; sd[i] += ot[12 + i];
        }
        softmax_sig(sa, sb, As0, sig, g, tg);
        softmax_sig(sc, sd, As1, sig, g, tg);
    }
    __syncthreads();   // As visible to both halves

    // ===== phase 2: Z = (sig*A) X (tf32, regs), R_half = Z Wb (bf16) =====
    float ra0[16][4], ra1[16][4];
#pragma unroll
    for (int i = 0; i < 16; ++i)
#pragma unroll
        for (int j = 0; j < 4; ++j) { ra0[i][j] = 0.f; ra1[i][j] = 0.f; }

    float za0[8][4], za1[8][4];
    for (int dc = 0; dc < 4; ++dc) {
        // Zchunk per token (registers only)
#pragma unroll
        for (int tok = 0; tok < 2; ++tok) {
            const float* Asx = tok ? As1 : As0;
            const float* Xsx = tok ? Xs1 : Xs0;
            float (*za)[4] = tok ? za1 : za0;
#pragma unroll
            for (int i = 0; i < 8; ++i)
#pragma unroll
                for (int j = 0; j < 4; ++j) za[i][j] = 0.f;
#pragma unroll
            for (int ks = 0; ks < 2; ++ks) {
                uint32_t a0 = __float_as_uint(Asx[g * SAT + ks * 8 + tg]);
                uint32_t a1 = __float_as_uint(Asx[(g + 8) * SAT + ks * 8 + tg]);
                uint32_t a2 = __float_as_uint(Asx[g * SAT + ks * 8 + tg + 4]);
                uint32_t a3 = __float_as_uint(Asx[(g + 8) * SAT + ks * 8 + tg + 4]);
                int r0w = ks * 8 + tg;
                int r1w = ks * 8 + tg + 4;
                bool rok = r1w < 13;
#pragma unroll
                for (int nt = 0; nt < 8; ++nt) {
                    int xc = dc * 64 + nt * 8 + g;
                    uint32_t b0 = f2tf(Xsx[r0w * SXR + xc]);
                    uint32_t b1 = rok ? f2tf(Xsx[r1w * SXR + xc]) : 0u;
                    mma8(za[nt], a0, a1, a2, a3, b0, b1);
                }
            }
        }

        for (int kp2 = 0; kp2 < 2; ++kp2) {
            const int st = dc * 2 + kp2;
            const uint4* gp = g_Wb4 + (nhf * 8 + st) * 512;
#pragma unroll
            for (int s = 0; s < 2; ++s) {
                uint4 v[8];
#pragma unroll
                for (int i = 0; i < 8; ++i) v[i] = __ldg(gp + (s * 8 + i) * 32 + lane);
                int t0 = kp2 * 4 + 2 * s;
                uint32_t a00 = pkr(za0[t0][0], za0[t0][1]);
                uint32_t a01 = pkr(za0[t0][2], za0[t0][3]);
                uint32_t a02 = pkr(za0[t0 + 1][0], za0[t0 + 1][1]);
                uint32_t a03 = pkr(za0[t0 + 1][2], za0[t0 + 1][3]);
                uint32_t a10 = pkr(za1[t0][0], za1[t0][1]);
                uint32_t a11 = pkr(za1[t0][2], za1[t0][3]);
                uint32_t a12 = pkr(za1[t0 + 1][0], za1[t0 + 1][1]);
                uint32_t a13 = pkr(za1[t0 + 1][2], za1[t0 + 1][3]);
#pragma unroll
                for (int q = 0; q < 8; ++q) {
                    uint4 vv = v[q];
                    mmab(ra0[2 * q],     a00, a01, a02, a03, vv.x, vv.y);
                    mmab(ra0[2 * q + 1], a00, a01, a02, a03, vv.z, vv.w);
                    mmab(ra1[2 * q],     a10, a11, a12, a13, vv.x, vv.y);
                    mmab(ra1[2 * q + 1], a10, a11, a12, a13, vv.z, vv.w);
                }
            }
        }
    }

    // ---- epilogue: residual via tf32 mma folded into ra, then store ----
    {
        uint32_t wl[2][4];
#pragma unroll
        for (int ks = 0; ks < 2; ++ks) {
            int k0 = ks * 8 + tg, k1 = ks * 8 + tg + 4;
            wl[ks][0] = f2tf(Wls[k0 * 16 + g]);
            wl[ks][1] = f2tf(Wls[k0 * 16 + g + 8]);
            wl[ks][2] = f2tf(Wls[k1 * 16 + g]);
            wl[ks][3] = f2tf(Wls[k1 * 16 + g + 8]);
        }
#pragma unroll
        for (int nt = 0; nt < 16; ++nt) {
            int cn = nhf * 128 + nt * 8 + g;
#pragma unroll
            for (int ks = 0; ks < 2; ++ks) {
                int r0w = ks * 8 + tg;
                int r1w = ks * 8 + tg + 4;
                bool rok = r1w < 13;
                uint32_t b0 = f2tf(Xs0[r0w * SXR + cn]);
                uint32_t b1 = rok ? f2tf(Xs0[r1w * SXR + cn]) : 0u;
                mma8(ra0[nt], wl[ks][0], wl[ks][1], wl[ks][2], wl[ks][3], b0, b1);
                b0 = f2tf(Xs1[r0w * SXR + cn]);
                b1 = rok ? f2tf(Xs1[r1w * SXR + cn]) : 0u;
                mma8(ra1[nt], wl[ks][0], wl[ks][1], wl[ks][2], wl[ks][3], b0, b1);
            }
        }
    }
    const long obase0 = (tokbase + 2 * tp) * 3328;
#pragma unroll
    for (int nt = 0; nt < 16; ++nt) {
        int c = nhf * 128 + nt * 8 + 2 * tg;
        *(float2*)(out + obase0 + g * 256 + c) = make_float2(ra0[nt][0], ra0[nt][1]);
        *(float2*)(out + obase0 + 3328 + g * 256 + c) = make_float2(ra1[nt][0], ra1[nt][1]);
        if (gok) {
            *(float2*)(out + obase0 + (g + 8) * 256 + c) = make_float2(ra0[nt][2], ra0[nt][3]);
            *(float2*)(out + obase0 + 3328 + (g + 8) * 256 + c) = make_float2(ra1[nt][2], ra1[nt][3]);
        }
    }
}

// ------------------------------ launch --------------------------------------
extern "C" void kernel_launch(void* const* d_in, const int* in_sizes, int n_in,
                              void* d_out, int out_size) {
    const float* h    = (const float*)d_in[0];
    const float* Wq   = (const float*)d_in[1];
    const float* Wk   = (const float*)d_in[2];
    const float* Wv   = (const float*)d_in[3];
    const float* Wo   = (const float*)d_in[4];
    const float* Wlat = (const float*)d_in[5];
    const float* gate = (const float*)d_in[6];
    float* out = (float*)d_out;

    static bool attr_done = false;
    if (!attr_done) {
        cudaFuncSetAttribute(lc_main, cudaFuncAttributeMaxDynamicSharedMemorySize, SMEM_BYTES);
        attr_done = true;
    }

    lc_setup<<<dim3(16, 16, 2), dim3(16, 16)>>>(Wq, Wk, Wv, Wo);
    lc_main<<<4096, THREADS, SMEM_BYTES>>>(h, Wlat, gate, out);
}

// round 15
// speedup vs baseline: 1.7603x; 1.0511x over previous
#include <cuda_runtime.h>
#include <cuda_bf16.h>
#include <cstdint>

// out = Wlat^T X  +  sigmoid(gate) * softmax(X Wa X^T) X Wb
//   Wa[k][n] = sum_e Wq[e,k] Wk[e,n] / 16    (bf16 fragment-packed, g_Wa4)
//   Wb[k][n] = sum_e Wo[n,e] Wv[e,k]         (bf16 fragment-packed, g_Wb4)
// 128 thr/CTA, 2 CTA/SM, 4 tokens/CTA. Warp = (token-pair tp, N-half nhf).
// Weight fragments read from GMEM (L2) via LDG.128 with explicit register
// double-buffer prefetch (phase1: v/vn per kp-pair; phase2: vA/vB per
// half-panel, Z accumulators packed to bf16x2 early to free registers).
// Big GEMMs bf16 m16n8k16; S=Y*X^T, Z=A*X, residual: tf32 m16n8k8.

#define THREADS 128
#define SXR 260        // X fp32 smem row stride
#define XTOK 3380      // 13*260
#define XBR 132        // X bf16 copy row stride in uint32
#define XBTOK 1716     // 13*132 uint32 per token
#define SCB 68         // phase-1 chunk buffer stride (per-warp)
#define SAT 20         // attn stride
#define ATOK 320       // 16*20

#define SM_X 0                 // 4*3380 = 13520 floats
#define SM_C 13520             // 4*1088 = 4352
#define SM_A 17872             // 4*320 = 1280
#define SM_W 19152             // 256
#define SM_XB 19408            // 4*1716 = 6864
#define SMEM_FLOATS 26272
#define SMEM_BYTES (SMEM_FLOATS * 4)   // 105088 -> 2 CTAs/SM

__device__ uint4 g_Wa4[32 * 256];
__device__ uint4 g_Wb4[16 * 512];

__device__ __forceinline__ uint32_t f2tf(float x) {
    uint32_t r;
    asm("cvt.rna.tf32.f32 %0, %1;" : "=r"(r) : "f"(x));
    return r;
}
__device__ __forceinline__ float f2tff(float x) {
    return __uint_as_float(f2tf(x));
}
__device__ __forceinline__ uint32_t pkr(float lo, float hi) {
    uint32_t r;
    asm("cvt.rn.bf16x2.f32 %0, %1, %2;" : "=r"(r) : "f"(hi), "f"(lo));
    return r;
}

__device__ __forceinline__ void mma8(float* d,
                                     uint32_t a0, uint32_t a1, uint32_t a2, uint32_t a3,
                                     uint32_t b0, uint32_t b1) {
    asm volatile(
        "mma.sync.aligned.m16n8k8.row.col.f32.tf32.tf32.f32 "
        "{%0,%1,%2,%3},{%4,%5,%6,%7},{%8,%9},{%0,%1,%2,%3};\n"
        : "+f"(d[0]), "+f"(d[1]), "+f"(d[2]), "+f"(d[3])
        : "r"(a0), "r"(a1), "r"(a2), "r"(a3), "r"(b0), "r"(b1));
}
__device__ __forceinline__ void mmab(float* d,
                                     uint32_t a0, uint32_t a1, uint32_t a2, uint32_t a3,
                                     uint32_t b0, uint32_t b1) {
    asm volatile(
        "mma.sync.aligned.m16n8k16.row.col.f32.bf16.bf16.f32 "
        "{%0,%1,%2,%3},{%4,%5,%6,%7},{%8,%9},{%0,%1,%2,%3};\n"
        : "+f"(d[0]), "+f"(d[1]), "+f"(d[2]), "+f"(d[3])
        : "r"(a0), "r"(a1), "r"(a2), "r"(a3), "r"(b0), "r"(b1));
}

// ------------------------------- setup --------------------------------------
__global__ void lc_setup(const float* __restrict__ Wq, const float* __restrict__ Wk,
                         const float* __restrict__ Wv, const float* __restrict__ Wo) {
    __shared__ float sA[16][17], sB[16][17];
    const int tx = threadIdx.x, ty = threadIdx.y;
    const int k0 = blockIdx.x * 16, n0 = blockIdx.y * 16;
    const bool isA = (blockIdx.z == 0);
    float acc = 0.f;
    for (int e0 = 0; e0 < 256; e0 += 16) {
        const float* Mp = isA ? Wq : Wv;
        sA[ty][tx] = Mp[(e0 + ty) * 256 + k0 + tx];
        if (isA) sB[ty][tx] = Wk[(e0 + ty) * 256 + n0 + tx];
        else     sB[tx][ty] = Wo[(n0 + ty) * 256 + e0 + tx];
        __syncthreads();
#pragma unroll
        for (int e = 0; e < 16; ++e) acc += sA[e][tx] * sB[e][ty];
        __syncthreads();
    }
    const int k = k0 + tx, n = n0 + ty;
    const int r = k & 31, s = r >> 4, rr = r & 15;
    const int half = rr >> 3, tg = (rr & 7) >> 1, j = rr & 1;
    if (isA) {
        acc *= (1.0f / 16.0f);
        int kp = k >> 5;
        int nc = n >> 6, nn = n & 63, nt = nn >> 3, g = nn & 7, q = nt >> 1;
        int u32idx = ((s * 4 + q) * 32 + g * 4 + tg) * 4 + (nt & 1) * 2 + half;
        ((__nv_bfloat16*)g_Wa4)[((nc * 8 + kp) * 1024 + u32idx) * 2 + j] =
            __float2bfloat16(acc);
    } else {
        int dc = k >> 6, kp2 = (k >> 5) & 1;
        int nh = n >> 7, nn = n & 127, nt = nn >> 3, g = nn & 7, q = nt >> 1;
        int u32idx = ((s * 8 + q) * 32 + g * 4 + tg) * 4 + (nt & 1) * 2 + half;
        ((__nv_bfloat16*)g_Wb4)[((nh * 8 + dc * 2 + kp2) * 2048 + u32idx) * 2 + j] =
            __float2bfloat16(acc);
    }
}

// ---------------------- softmax (sig folded) --------------------------------
__device__ __forceinline__ void softmax_sig(const float* s0, const float* s1,
                                            float* As, float sig, int g, int tg) {
    int c0 = 2 * tg, c1 = 2 * tg + 1, c2 = 8 + 2 * tg, c3 = 9 + 2 * tg;
    bool v0 = c0 < 13, v1 = c1 < 13, v2 = c2 < 13, v3 = c3 < 13;
    const float NEG = -1e30f;
    float m0 = fmaxf(fmaxf(v0 ? s0[0] : NEG, v1 ? s0[1] : NEG),
                     fmaxf(v2 ? s1[0] : NEG, v3 ? s1[1] : NEG));
    float m1 = fmaxf(fmaxf(v0 ? s0[2] : NEG, v1 ? s0[3] : NEG),
                     fmaxf(v2 ? s1[2] : NEG, v3 ? s1[3] : NEG));
    m0 = fmaxf(m0, __shfl_xor_sync(0xffffffffu, m0, 1));
    m0 = fmaxf(m0, __shfl_xor_sync(0xffffffffu, m0, 2));
    m1 = fmaxf(m1, __shfl_xor_sync(0xffffffffu, m1, 1));
    m1 = fmaxf(m1, __shfl_xor_sync(0xffffffffu, m1, 2));
    float e00 = v0 ? __expf(s0[0] - m0) : 0.f;
    float e01 = v1 ? __expf(s0[1] - m0) : 0.f;
    float e02 = v2 ? __expf(s1[0] - m0) : 0.f;
    float e03 = v3 ? __expf(s1[1] - m0) : 0.f;
    float e10 = v0 ? __expf(s0[2] - m1) : 0.f;
    float e11 = v1 ? __expf(s0[3] - m1) : 0.f;
    float e12 = v2 ? __expf(s1[2] - m1) : 0.f;
    float e13 = v3 ? __expf(s1[3] - m1) : 0.f;
    float d0 = e00 + e01 + e02 + e03;
    float d1 = e10 + e11 + e12 + e13;
    d0 += __shfl_xor_sync(0xffffffffu, d0, 1);
    d0 += __shfl_xor_sync(0xffffffffu, d0, 2);
    d1 += __shfl_xor_sync(0xffffffffu, d1, 1);
    d1 += __shfl_xor_sync(0xffffffffu, d1, 2);
    float r0 = sig / d0, r1 = sig / d1;
    As[g * SAT + c0]       = f2tff(e00 * r0);
    As[g * SAT + c1]       = f2tff(e01 * r0);
    As[g * SAT + c2]       = f2tff(e02 * r0);
    As[g * SAT + c3]       = f2tff(e03 * r0);
    As[(g + 8) * SAT + c0] = f2tff(e10 * r1);
    As[(g + 8) * SAT + c1] = f2tff(e11 * r1);
    As[(g + 8) * SAT + c2] = f2tff(e12 * r1);
    As[(g + 8) * SAT + c3] = f2tff(e13 * r1);
}

// phase-1 mma block: one 32-row K panel against both tokens' bf16 X
__device__ __forceinline__ void p1_block(float (*ya0)[4], float (*ya1)[4],
                                         const uint32_t* Xb0, const uint32_t* Xb1,
                                         const uint4* v, int kp,
                                         int g, int tg, bool gok) {
#pragma unroll
    for (int s = 0; s < 2; ++s) {
        int kc2 = kp * 16 + s * 8;
        uint32_t a00 = Xb0[g * XBR + kc2 + tg];
        uint32_t a01 = gok ? Xb0[(g + 8) * XBR + kc2 + tg] : 0u;
        uint32_t a02 = Xb0[g * XBR + kc2 + 4 + tg];
        uint32_t a03 = gok ? Xb0[(g + 8) * XBR + kc2 + 4 + tg] : 0u;
        uint32_t a10 = Xb1[g * XBR + kc2 + tg];
        uint32_t a11 = gok ? Xb1[(g + 8) * XBR + kc2 + tg] : 0u;
        uint32_t a12 = Xb1[g * XBR + kc2 + 4 + tg];
        uint32_t a13 = gok ? Xb1[(g + 8) * XBR + kc2 + 4 + tg] : 0u;
#pragma unroll
        for (int q = 0; q < 4; ++q) {
            uint4 vv = v[s * 4 + q];
            mmab(ya0[2 * q],     a00, a01, a02, a03, vv.x, vv.y);
            mmab(ya0[2 * q + 1], a00, a01, a02, a03, vv.z, vv.w);
            mmab(ya1[2 * q],     a10, a11, a12, a13, vv.x, vv.y);
            mmab(ya1[2 * q + 1], a10, a11, a12, a13, vv.z, vv.w);
        }
    }
}

// phase-2 mma half-panel: 8 weight frag vectors vs packed Z frags at t0
__device__ __forceinline__ void p2_block(float (*ra0)[4], float (*ra1)[4],
                                         const uint32_t* zp0, const uint32_t* zp1,
                                         const uint4* v, int t0) {
    uint32_t a00 = zp0[2 * t0], a01 = zp0[2 * t0 + 1];
    uint32_t a02 = zp0[2 * t0 + 2], a03 = zp0[2 * t0 + 3];
    uint32_t a10 = zp1[2 * t0], a11 = zp1[2 * t0 + 1];
    uint32_t a12 = zp1[2 * t0 + 2], a13 = zp1[2 * t0 + 3];
#pragma unroll
    for (int q = 0; q < 8; ++q) {
        uint4 vv = v[q];
        mmab(ra0[2 * q],     a00, a01, a02, a03, vv.x, vv.y);
        mmab(ra0[2 * q + 1], a00, a01, a02, a03, vv.z, vv.w);
        mmab(ra1[2 * q],     a10, a11, a12, a13, vv.x, vv.y);
        mmab(ra1[2 * q + 1], a10, a11, a12, a13, vv.z, vv.w);
    }
}

__device__ __forceinline__ void pf_wb(uint4* dst, int st, int s, int nhf, int lane) {
    const uint4* gp = g_Wb4 + (nhf * 8 + st) * 512 + s * 256;
#pragma unroll
    for (int i = 0; i < 8; ++i) dst[i] = __ldg(gp + i * 32 + lane);
}

// -------------------------------- main --------------------------------------
__global__ void __launch_bounds__(THREADS, 2)
lc_main(const float* __restrict__ hsrc, const float* __restrict__ Wlat,
        const float* __restrict__ gate, float* __restrict__ out) {
    extern __shared__ float smem[];
    const int tid = threadIdx.x;
    const int w = tid >> 5, lane = tid & 31;
    const int g = lane >> 2, tg = lane & 3;
    const int tp = w >> 1, nhf = w & 1;
    const long tokbase = (long)blockIdx.x * 4;
    const bool gok = (g < 5);

    float* Xs0 = smem + SM_X + (2 * tp) * XTOK;
    float* Xs1 = Xs0 + XTOK;
    float* Cb = smem + SM_C + w * 1088;
    float* As0 = smem + SM_A + (2 * tp) * ATOK;
    float* As1 = As0 + ATOK;
    float* Wls = smem + SM_W;
    uint32_t* XbBase = (uint32_t*)(smem + SM_XB);
    const uint32_t* Xb0 = XbBase + (2 * tp) * XBTOK;
    const uint32_t* Xb1 = Xb0 + XBTOK;

    uint4 v[8], vn[8];        // phase-1 prefetch buffers
    uint4 vA[8], vB[8];       // phase-2 prefetch buffers

    // preload first phase-1 panel (independent of smem; hidden by X load+barrier)
    {
        const uint4* gp0 = g_Wa4 + (2 * nhf * 8) * 256;
#pragma unroll
        for (int i = 0; i < 8; ++i) v[i] = __ldg(gp0 + i * 32 + lane);
    }

    // ---- load X: warp w loads token w; writes fp32 + packed-bf16 copies ----
    {
        const float* src = hsrc + (tokbase + w) * 3328;
        float* dst = smem + SM_X + w * XTOK;
        uint32_t* bdst = XbBase + w * XBTOK;
        for (int i = lane; i < 832; i += 32) {
            int row = i >> 6, c4 = (i & 63) << 2;
            float4 vv = *(const float4*)(src + row * 256 + c4);
            *(float4*)(dst + row * SXR + c4) = vv;
            uint2 bp;
            bp.x = pkr(vv.x, vv.y);
            bp.y = pkr(vv.z, vv.w);
            *(uint2*)(bdst + row * XBR + (c4 >> 1)) = bp;
        }
    }
    for (int idx = tid; idx < 256; idx += THREADS) {
        int p = idx >> 4, r = idx & 15;
        Wls[idx] = (p < 13 && r < 13) ? Wlat[p * 13 + r] : 0.f;
    }
    float sig;
    { float gv = gate[0]; sig = 1.f / (1.f + __expf(-gv)); }
    __syncthreads();

    // =========== phase 1: Y = X Wa (bf16, half's nc), S partial ===========
    float sa[4] = {0, 0, 0, 0}, sb[4] = {0, 0, 0, 0};
    float sc[4] = {0, 0, 0, 0}, sd[4] = {0, 0, 0, 0};

    for (int ncl = 0; ncl < 2; ++ncl) {
        const int nc = 2 * nhf + ncl;
        const uint4* gp = g_Wa4 + (nc * 8) * 256;
        float ya0[8][4], ya1[8][4];
#pragma unroll
        for (int i = 0; i < 8; ++i)
#pragma unroll
            for (int j = 0; j < 4; ++j) { ya0[i][j] = 0.f; ya1[i][j] = 0.f; }

#pragma unroll
        for (int kpp = 0; kpp < 4; ++kpp) {
            const int kpA = 2 * kpp, kpB = 2 * kpp + 1;
            // prefetch kpB
#pragma unroll
            for (int i = 0; i < 8; ++i) vn[i] = __ldg(gp + kpB * 256 + i * 32 + lane);
            p1_block(ya0, ya1, Xb0, Xb1, v, kpA, g, tg, gok);
            // prefetch kpB+1 / next chunk / phase-2 half0
            if (kpp < 3) {
#pragma unroll
                for (int i = 0; i < 8; ++i)
                    v[i] = __ldg(gp + (kpB + 1) * 256 + i * 32 + lane);
            } else if (ncl == 0) {
                const uint4* gpn = g_Wa4 + ((2 * nhf + 1) * 8) * 256;
#pragma unroll
                for (int i = 0; i < 8; ++i) v[i] = __ldg(gpn + i * 32 + lane);
            } else {
                pf_wb(vA, 0, 0, nhf, lane);   // phase-2 (st=0, s=0)
            }
            p1_block(ya0, ya1, Xb0, Xb1, vn, kpB, g, tg, gok);
        }

        // flush: Y -> Cb (tf32), S += Y * X^T  (sequential tokens, warp-private Cb)
        __syncwarp();
#pragma unroll
        for (int nt = 0; nt < 8; ++nt) {
            int c = nt * 8 + 2 * tg;
            *(float2*)(Cb + g * SCB + c) = make_float2(f2tff(ya0[nt][0]), f2tff(ya0[nt][1]));
            *(float2*)(Cb + (g + 8) * SCB + c) = make_float2(f2tff(ya0[nt][2]), f2tff(ya0[nt][3]));
        }
        __syncwarp();
#pragma unroll
        for (int ks = 0; ks < 8; ++ks) {
            int xc = nc * 64 + ks * 8;
            uint32_t a0 = __float_as_uint(Cb[g * SCB + ks * 8 + tg]);
            uint32_t a1 = __float_as_uint(Cb[(g + 8) * SCB + ks * 8 + tg]);
            uint32_t a2 = __float_as_uint(Cb[g * SCB + ks * 8 + tg + 4]);
            uint32_t a3 = __float_as_uint(Cb[(g + 8) * SCB + ks * 8 + tg + 4]);
            uint32_t b0 = f2tf(Xs0[g * SXR + xc + tg]);
            uint32_t b1 = f2tf(Xs0[g * SXR + xc + tg + 4]);
            mma8(sa, a0, a1, a2, a3, b0, b1);
            uint32_t c0 = gok ? f2tf(Xs0[(g + 8) * SXR + xc + tg]) : 0u;
            uint32_t c1 = gok ? f2tf(Xs0[(g + 8) * SXR + xc + tg + 4]) : 0u;
            mma8(sb, a0, a1, a2, a3, c0, c1);
        }
        __syncwarp();
#pragma unroll
        for (int nt = 0; nt < 8; ++nt) {
            int c = nt * 8 + 2 * tg;
            *(float2*)(Cb + g * SCB + c) = make_float2(f2tff(ya1[nt][0]), f2tff(ya1[nt][1]));
            *(float2*)(Cb + (g + 8) * SCB + c) = make_float2(f2tff(ya1[nt][2]), f2tff(ya1[nt][3]));
        }
        __syncwarp();
#pragma unroll
        for (int ks = 0; ks < 8; ++ks) {
            int xc = nc * 64 + ks * 8;
            uint32_t a0 = __float_as_uint(Cb[g * SCB + ks * 8 + tg]);
            uint32_t a1 = __float_as_uint(Cb[(g + 8) * SCB + ks * 8 + tg]);
            uint32_t a2 = __float_as_uint(Cb[g * SCB + ks * 8 + tg + 4]);
            uint32_t a3 = __float_as_uint(Cb[(g + 8) * SCB + ks * 8 + tg + 4]);
            uint32_t b0 = f2tf(Xs1[g * SXR + xc + tg]);
            uint32_t b1 = f2tf(Xs1[g * SXR + xc + tg + 4]);
            mma8(sc, a0, a1, a2, a3, b0, b1);
            uint32_t c0 = gok ? f2tf(Xs1[(g + 8) * SXR + xc + tg]) : 0u;
            uint32_t c1 = gok ? f2tf(Xs1[(g + 8) * SXR + xc + tg + 4]) : 0u;
            mma8(sd, a0, a1, a2, a3, c0, c1);
        }
        __syncwarp();
    }

    // ---------- S cross-half reduction + softmax (vA load in flight) --------
    __syncthreads();
    {
        float* my = smem + SM_C + (w * 32 + lane) * 16;
#pragma unroll
        for (int i = 0; i < 4; ++i) {
            my[i] = sa[i]; my[4 + i] = sb[i]; my[8 + i] = sc[i]; my[12 + i] = sd[i];
        }
    }
    __syncthreads();
    if (nhf == 0) {
        const float* ot = smem + SM_C + ((w ^ 1) * 32 + lane) * 16;
#pragma unroll
        for (int i = 0; i < 4; ++i) {
            sa[i] += ot[i]; sb[i] += ot[4 + i]; sc[i] += ot[8 + i]; sd[i] += ot[12 + i];
        }
        softmax_sig(sa, sb, As0, sig, g, tg);
        softmax_sig(sc, sd, As1, sig, g, tg);
    }
    __syncthreads();   // As visible to both halves

    // ===== phase 2: Z = (sig*A) X (tf32, regs), R_half = Z Wb (bf16) =====
    float ra0[16][4], ra1[16][4];
#pragma unroll
    for (int i = 0; i < 16; ++i)
#pragma unroll
        for (int j = 0; j < 4; ++j) { ra0[i][j] = 0.f; ra1[i][j] = 0.f; }

    for (int dc = 0; dc < 4; ++dc) {
        // Zchunk per token (registers), then pack to bf16x2 frags
        uint32_t zp0[16], zp1[16];
        {
            float za0[8][4], za1[8][4];
#pragma unroll
            for (int tok = 0; tok < 2; ++tok) {
                const float* Asx = tok ? As1 : As0;
                const float* Xsx = tok ? Xs1 : Xs0;
                float (*za)[4] = tok ? za1 : za0;
#pragma unroll
                for (int i = 0; i < 8; ++i)
#pragma unroll
                    for (int j = 0; j < 4; ++j) za[i][j] = 0.f;
#pragma unroll
                for (int ks = 0; ks < 2; ++ks) {
                    uint32_t a0 = __float_as_uint(Asx[g * SAT + ks * 8 + tg]);
                    uint32_t a1 = __float_as_uint(Asx[(g + 8) * SAT + ks * 8 + tg]);
                    uint32_t a2 = __float_as_uint(Asx[g * SAT + ks * 8 + tg + 4]);
                    uint32_t a3 = __float_as_uint(Asx[(g + 8) * SAT + ks * 8 + tg + 4]);
                    int r0w = ks * 8 + tg;
                    int r1w = ks * 8 + tg + 4;
                    bool rok = r1w < 13;
#pragma unroll
                    for (int nt = 0; nt < 8; ++nt) {
                        int xc = dc * 64 + nt * 8 + g;
                        uint32_t b0 = f2tf(Xsx[r0w * SXR + xc]);
                        uint32_t b1 = rok ? f2tf(Xsx[r1w * SXR + xc]) : 0u;
                        mma8(za[nt], a0, a1, a2, a3, b0, b1);
                    }
                }
            }
#pragma unroll
            for (int t = 0; t < 8; ++t) {
                zp0[2 * t]     = pkr(za0[t][0], za0[t][1]);
                zp0[2 * t + 1] = pkr(za0[t][2], za0[t][3]);
                zp1[2 * t]     = pkr(za1[t][0], za1[t][1]);
                zp1[2 * t + 1] = pkr(za1[t][2], za1[t][3]);
            }
        }

        const int st0 = dc * 2;
        pf_wb(vB, st0, 1, nhf, lane);
        p2_block(ra0, ra1, zp0, zp1, vA, 0);         // (kp2=0, s=0)
        pf_wb(vA, st0 + 1, 0, nhf, lane);
        p2_block(ra0, ra1, zp0, zp1, vB, 2);         // (0, 1)
        pf_wb(vB, st0 + 1, 1, nhf, lane);
        p2_block(ra0, ra1, zp0, zp1, vA, 4);         // (1, 0)
        if (dc < 3) pf_wb(vA, st0 + 2, 0, nhf, lane);
        p2_block(ra0, ra1, zp0, zp1, vB, 6);         // (1, 1)
    }

    // ---- epilogue: residual via tf32 mma folded into ra, then store ----
    {
        uint32_t wl[2][4];
#pragma unroll
        for (int ks = 0; ks < 2; ++ks) {
            int k0 = ks * 8 + tg, k1 = ks * 8 + tg + 4;
            wl[ks][0] = f2tf(Wls[k0 * 16 + g]);
            wl[ks][1] = f2tf(Wls[k0 * 16 + g + 8]);
            wl[ks][2] = f2tf(Wls[k1 * 16 + g]);
            wl[ks][3] = f2tf(Wls[k1 * 16 + g + 8]);
        }
#pragma unroll
        for (int nt = 0; nt < 16; ++nt) {
            int cn = nhf * 128 + nt * 8 + g;
#pragma unroll
            for (int ks = 0; ks < 2; ++ks) {
                int r0w = ks * 8 + tg;
                int r1w = ks * 8 + tg + 4;
                bool rok = r1w < 13;
                uint32_t b0 = f2tf(Xs0[r0w * SXR + cn]);
                uint32_t b1 = rok ? f2tf(Xs0[r1w * SXR + cn]) : 0u;
                mma8(ra0[nt], wl[ks][0], wl[ks][1], wl[ks][2], wl[ks][3], b0, b1);
                b0 = f2tf(Xs1[r0w * SXR + cn]);
                b1 = rok ? f2tf(Xs1[r1w * SXR + cn]) : 0u;
                mma8(ra1[nt], wl[ks][0], wl[ks][1], wl[ks][2], wl[ks][3], b0, b1);
            }
        }
    }
    const long obase0 = (tokbase + 2 * tp) * 3328;
#pragma unroll
    for (int nt = 0; nt < 16; ++nt) {
        int c = nhf * 128 + nt * 8 + 2 * tg;
        *(float2*)(out + obase0 + g * 256 + c) = make_float2(ra0[nt][0], ra0[nt][1]);
        *(float2*)(out + obase0 + 3328 + g * 256 + c) = make_float2(ra1[nt][0], ra1[nt][1]);
        if (gok) {
            *(float2*)(out + obase0 + (g + 8) * 256 + c) = make_float2(ra0[nt][2], ra0[nt][3]);
            *(float2*)(out + obase0 + 3328 + (g + 8) * 256 + c) = make_float2(ra1[nt][2], ra1[nt][3]);
        }
    }
}

// ------------------------------ launch --------------------------------------
extern "C" void kernel_launch(void* const* d_in, const int* in_sizes, int n_in,
                              void* d_out, int out_size) {
    const float* h    = (const float*)d_in[0];
    const float* Wq   = (const float*)d_in[1];
    const float* Wk   = (const float*)d_in[2];
    const float* Wv   = (const float*)d_in[3];
    const float* Wo   = (const float*)d_in[4];
    const float* Wlat = (const float*)d_in[5];
    const float* gate = (const float*)d_in[6];
    float* out = (float*)d_out;

    static bool attr_done = false;
    if (!attr_done) {
        cudaFuncSetAttribute(lc_main, cudaFuncAttributeMaxDynamicSharedMemorySize, SMEM_BYTES);
        attr_done = true;
    }

    lc_setup<<<dim3(16, 16, 2), dim3(16, 16)>>>(Wq, Wk, Wv, Wo);
    lc_main<<<4096, THREADS, SMEM_BYTES>>>(h, Wlat, gate, out);
}

// round 16
// speedup vs baseline: 1.9240x; 1.0930x over previous
#include <cuda_runtime.h>
#include <cuda_bf16.h>
#include <cstdint>

// out = Wlat^T X  +  sigmoid(gate) * softmax(X Wa X^T) X Wb
//   Wa[k][n] = sum_e Wq[e,k] Wk[e,n] / 16    (bf16 fragment-packed, g_Wa4)
//   Wb[k][n] = sum_e Wo[n,e] Wv[e,k]         (bf16 fragment-packed, g_Wb4)
// 128 thr/CTA, 2 CTA/SM, 4 tokens/CTA. Warp = (token-pair tp, N-half nhf).
// Weight fragments read from GMEM (L2) via LDG.128 with register double-buffer
// prefetch. X stored in smem TWICE, both pre-converted at load time:
//   - tf32 copy (Xs): feeds S/Z/residual mma8 with NO cvt in hot loops
//   - bf16x2 copy (Xb): feeds phase-1 A fragments with one LDS.32 each
// Big GEMMs bf16 m16n8k16; S=Y*X^T, Z=A*X, residual: tf32 m16n8k8.

#define THREADS 128
#define SXR 260        // X tf32 smem row stride
#define XTOK 3380      // 13*260
#define XBR 132        // X bf16 copy row stride in uint32
#define XBTOK 1716     // 13*132 uint32 per token
#define SCB 68         // phase-1 chunk buffer stride (per-warp)
#define SAT 20         // attn stride
#define ATOK 320       // 16*20

#define SM_X 0                 // 4*3380 = 13520 floats
#define SM_C 13520             // 4*1088 = 4352
#define SM_A 17872             // 4*320 = 1280
#define SM_W 19152             // 256
#define SM_XB 19408            // 4*1716 = 6864
#define SMEM_FLOATS 26272
#define SMEM_BYTES (SMEM_FLOATS * 4)   // 105088 -> 2 CTAs/SM

__device__ uint4 g_Wa4[32 * 256];
__device__ uint4 g_Wb4[16 * 512];

__device__ __forceinline__ uint32_t f2tf(float x) {
    uint32_t r;
    asm("cvt.rna.tf32.f32 %0, %1;" : "=r"(r) : "f"(x));
    return r;
}
__device__ __forceinline__ float f2tff(float x) {
    return __uint_as_float(f2tf(x));
}
__device__ __forceinline__ uint32_t pkr(float lo, float hi) {
    uint32_t r;
    asm("cvt.rn.bf16x2.f32 %0, %1, %2;" : "=r"(r) : "f"(hi), "f"(lo));
    return r;
}

__device__ __forceinline__ void mma8(float* d,
                                     uint32_t a0, uint32_t a1, uint32_t a2, uint32_t a3,
                                     uint32_t b0, uint32_t b1) {
    asm volatile(
        "mma.sync.aligned.m16n8k8.row.col.f32.tf32.tf32.f32 "
        "{%0,%1,%2,%3},{%4,%5,%6,%7},{%8,%9},{%0,%1,%2,%3};\n"
        : "+f"(d[0]), "+f"(d[1]), "+f"(d[2]), "+f"(d[3])
        : "r"(a0), "r"(a1), "r"(a2), "r"(a3), "r"(b0), "r"(b1));
}
__device__ __forceinline__ void mmab(float* d,
                                     uint32_t a0, uint32_t a1, uint32_t a2, uint32_t a3,
                                     uint32_t b0, uint32_t b1) {
    asm volatile(
        "mma.sync.aligned.m16n8k16.row.col.f32.bf16.bf16.f32 "
        "{%0,%1,%2,%3},{%4,%5,%6,%7},{%8,%9},{%0,%1,%2,%3};\n"
        : "+f"(d[0]), "+f"(d[1]), "+f"(d[2]), "+f"(d[3])
        : "r"(a0), "r"(a1), "r"(a2), "r"(a3), "r"(b0), "r"(b1));
}

// ------------------------------- setup --------------------------------------
__global__ void lc_setup(const float* __restrict__ Wq, const float* __restrict__ Wk,
                         const float* __restrict__ Wv, const float* __restrict__ Wo) {
    __shared__ float sA[16][17], sB[16][17];
    const int tx = threadIdx.x, ty = threadIdx.y;
    const int k0 = blockIdx.x * 16, n0 = blockIdx.y * 16;
    const bool isA = (blockIdx.z == 0);
    float acc = 0.f;
    for (int e0 = 0; e0 < 256; e0 += 16) {
        const float* Mp = isA ? Wq : Wv;
        sA[ty][tx] = Mp[(e0 + ty) * 256 + k0 + tx];
        if (isA) sB[ty][tx] = Wk[(e0 + ty) * 256 + n0 + tx];
        else     sB[tx][ty] = Wo[(n0 + ty) * 256 + e0 + tx];
        __syncthreads();
#pragma unroll
        for (int e = 0; e < 16; ++e) acc += sA[e][tx] * sB[e][ty];
        __syncthreads();
    }
    const int k = k0 + tx, n = n0 + ty;
    const int r = k & 31, s = r >> 4, rr = r & 15;
    const int half = rr >> 3, tg = (rr & 7) >> 1, j = rr & 1;
    if (isA) {
        acc *= (1.0f / 16.0f);
        int kp = k >> 5;
        int nc = n >> 6, nn = n & 63, nt = nn >> 3, g = nn & 7, q = nt >> 1;
        int u32idx = ((s * 4 + q) * 32 + g * 4 + tg) * 4 + (nt & 1) * 2 + half;
        ((__nv_bfloat16*)g_Wa4)[((nc * 8 + kp) * 1024 + u32idx) * 2 + j] =
            __float2bfloat16(acc);
    } else {
        int dc = k >> 6, kp2 = (k >> 5) & 1;
        int nh = n >> 7, nn = n & 127, nt = nn >> 3, g = nn & 7, q = nt >> 1;
        int u32idx = ((s * 8 + q) * 32 + g * 4 + tg) * 4 + (nt & 1) * 2 + half;
        ((__nv_bfloat16*)g_Wb4)[((nh * 8 + dc * 2 + kp2) * 2048 + u32idx) * 2 + j] =
            __float2bfloat16(acc);
    }
}

// ---------------------- softmax (sig folded) --------------------------------
__device__ __forceinline__ void softmax_sig(const float* s0, const float* s1,
                                            float* As, float sig, int g, int tg) {
    int c0 = 2 * tg, c1 = 2 * tg + 1, c2 = 8 + 2 * tg, c3 = 9 + 2 * tg;
    bool v0 = c0 < 13, v1 = c1 < 13, v2 = c2 < 13, v3 = c3 < 13;
    const float NEG = -1e30f;
    float m0 = fmaxf(fmaxf(v0 ? s0[0] : NEG, v1 ? s0[1] : NEG),
                     fmaxf(v2 ? s1[0] : NEG, v3 ? s1[1] : NEG));
    float m1 = fmaxf(fmaxf(v0 ? s0[2] : NEG, v1 ? s0[3] : NEG),
                     fmaxf(v2 ? s1[2] : NEG, v3 ? s1[3] : NEG));
    m0 = fmaxf(m0, __shfl_xor_sync(0xffffffffu, m0, 1));
    m0 = fmaxf(m0, __shfl_xor_sync(0xffffffffu, m0, 2));
    m1 = fmaxf(m1, __shfl_xor_sync(0xffffffffu, m1, 1));
    m1 = fmaxf(m1, __shfl_xor_sync(0xffffffffu, m1, 2));
    float e00 = v0 ? __expf(s0[0] - m0) : 0.f;
    float e01 = v1 ? __expf(s0[1] - m0) : 0.f;
    float e02 = v2 ? __expf(s1[0] - m0) : 0.f;
    float e03 = v3 ? __expf(s1[1] - m0) : 0.f;
    float e10 = v0 ? __expf(s0[2] - m1) : 0.f;
    float e11 = v1 ? __expf(s0[3] - m1) : 0.f;
    float e12 = v2 ? __expf(s1[2] - m1) : 0.f;
    float e13 = v3 ? __expf(s1[3] - m1) : 0.f;
    float d0 = e00 + e01 + e02 + e03;
    float d1 = e10 + e11 + e12 + e13;
    d0 += __shfl_xor_sync(0xffffffffu, d0, 1);
    d0 += __shfl_xor_sync(0xffffffffu, d0, 2);
    d1 += __shfl_xor_sync(0xffffffffu, d1, 1);
    d1 += __shfl_xor_sync(0xffffffffu, d1, 2);
    float r0 = sig / d0, r1 = sig / d1;
    As[g * SAT + c0]       = f2tff(e00 * r0);
    As[g * SAT + c1]       = f2tff(e01 * r0);
    As[g * SAT + c2]       = f2tff(e02 * r0);
    As[g * SAT + c3]       = f2tff(e03 * r0);
    As[(g + 8) * SAT + c0] = f2tff(e10 * r1);
    As[(g + 8) * SAT + c1] = f2tff(e11 * r1);
    As[(g + 8) * SAT + c2] = f2tff(e12 * r1);
    As[(g + 8) * SAT + c3] = f2tff(e13 * r1);
}

// phase-1 mma block: one 32-row K panel against both tokens' bf16 X
__device__ __forceinline__ void p1_block(float (*ya0)[4], float (*ya1)[4],
                                         const uint32_t* Xb0, const uint32_t* Xb1,
                                         const uint4* v, int kp,
                                         int g, int tg, bool gok) {
#pragma unroll
    for (int s = 0; s < 2; ++s) {
        int kc2 = kp * 16 + s * 8;
        uint32_t a00 = Xb0[g * XBR + kc2 + tg];
        uint32_t a01 = gok ? Xb0[(g + 8) * XBR + kc2 + tg] : 0u;
        uint32_t a02 = Xb0[g * XBR + kc2 + 4 + tg];
        uint32_t a03 = gok ? Xb0[(g + 8) * XBR + kc2 + 4 + tg] : 0u;
        uint32_t a10 = Xb1[g * XBR + kc2 + tg];
        uint32_t a11 = gok ? Xb1[(g + 8) * XBR + kc2 + tg] : 0u;
        uint32_t a12 = Xb1[g * XBR + kc2 + 4 + tg];
        uint32_t a13 = gok ? Xb1[(g + 8) * XBR + kc2 + 4 + tg] : 0u;
#pragma unroll
        for (int q = 0; q < 4; ++q) {
            uint4 vv = v[s * 4 + q];
            mmab(ya0[2 * q],     a00, a01, a02, a03, vv.x, vv.y);
            mmab(ya0[2 * q + 1], a00, a01, a02, a03, vv.z, vv.w);
            mmab(ya1[2 * q],     a10, a11, a12, a13, vv.x, vv.y);
            mmab(ya1[2 * q + 1], a10, a11, a12, a13, vv.z, vv.w);
        }
    }
}

// phase-2 mma half-panel: 8 weight frag vectors vs packed Z frags at t0
__device__ __forceinline__ void p2_block(float (*ra0)[4], float (*ra1)[4],
                                         const uint32_t* zp0, const uint32_t* zp1,
                                         const uint4* v, int t0) {
    uint32_t a00 = zp0[2 * t0], a01 = zp0[2 * t0 + 1];
    uint32_t a02 = zp0[2 * t0 + 2], a03 = zp0[2 * t0 + 3];
    uint32_t a10 = zp1[2 * t0], a11 = zp1[2 * t0 + 1];
    uint32_t a12 = zp1[2 * t0 + 2], a13 = zp1[2 * t0 + 3];
#pragma unroll
    for (int q = 0; q < 8; ++q) {
        uint4 vv = v[q];
        mmab(ra0[2 * q],     a00, a01, a02, a03, vv.x, vv.y);
        mmab(ra0[2 * q + 1], a00, a01, a02, a03, vv.z, vv.w);
        mmab(ra1[2 * q],     a10, a11, a12, a13, vv.x, vv.y);
        mmab(ra1[2 * q + 1], a10, a11, a12, a13, vv.z, vv.w);
    }
}

__device__ __forceinline__ void pf_wb(uint4* dst, int st, int s, int nhf, int lane) {
    const uint4* gp = g_Wb4 + (nhf * 8 + st) * 512 + s * 256;
#pragma unroll
    for (int i = 0; i < 8; ++i) dst[i] = __ldg(gp + i * 32 + lane);
}

// -------------------------------- main --------------------------------------
__global__ void __launch_bounds__(THREADS, 2)
lc_main(const float* __restrict__ hsrc, const float* __restrict__ Wlat,
        const float* __restrict__ gate, float* __restrict__ out) {
    extern __shared__ float smem[];
    const int tid = threadIdx.x;
    const int w = tid >> 5, lane = tid & 31;
    const int g = lane >> 2, tg = lane & 3;
    const int tp = w >> 1, nhf = w & 1;
    const long tokbase = (long)blockIdx.x * 4;
    const bool gok = (g < 5);

    float* Xs0 = smem + SM_X + (2 * tp) * XTOK;      // tf32-preconverted X
    float* Xs1 = Xs0 + XTOK;
    float* Cb = smem + SM_C + w * 1088;
    float* As0 = smem + SM_A + (2 * tp) * ATOK;
    float* As1 = As0 + ATOK;
    float* Wls = smem + SM_W;
    uint32_t* XbBase = (uint32_t*)(smem + SM_XB);
    const uint32_t* Xb0 = XbBase + (2 * tp) * XBTOK;
    const uint32_t* Xb1 = Xb0 + XBTOK;

    uint4 v[8], vn[8];        // phase-1 prefetch buffers
    uint4 vA[8], vB[8];       // phase-2 prefetch buffers

    // preload first phase-1 panel (hidden by X load + barrier)
    {
        const uint4* gp0 = g_Wa4 + (2 * nhf * 8) * 256;
#pragma unroll
        for (int i = 0; i < 8; ++i) v[i] = __ldg(gp0 + i * 32 + lane);
    }

    // ---- load X: warp w loads token w; writes tf32 + packed-bf16 copies ----
    {
        const float* src = hsrc + (tokbase + w) * 3328;
        float* dst = smem + SM_X + w * XTOK;
        uint32_t* bdst = XbBase + w * XBTOK;
        for (int i = lane; i < 832; i += 32) {
            int row = i >> 6, c4 = (i & 63) << 2;
            float4 vv = *(const float4*)(src + row * 256 + c4);
            float4 tv;
            tv.x = f2tff(vv.x); tv.y = f2tff(vv.y);
            tv.z = f2tff(vv.z); tv.w = f2tff(vv.w);
            *(float4*)(dst + row * SXR + c4) = tv;
            uint2 bp;
            bp.x = pkr(vv.x, vv.y);
            bp.y = pkr(vv.z, vv.w);
            *(uint2*)(bdst + row * XBR + (c4 >> 1)) = bp;
        }
    }
    for (int idx = tid; idx < 256; idx += THREADS) {
        int p = idx >> 4, r = idx & 15;
        Wls[idx] = (p < 13 && r < 13) ? f2tff(Wlat[p * 13 + r]) : 0.f;
    }
    float sig;
    { float gv = gate[0]; sig = 1.f / (1.f + __expf(-gv)); }
    __syncthreads();

    // =========== phase 1: Y = X Wa (bf16, half's nc), S partial ===========
    float sa[4] = {0, 0, 0, 0}, sb[4] = {0, 0, 0, 0};
    float sc[4] = {0, 0, 0, 0}, sd[4] = {0, 0, 0, 0};

    for (int ncl = 0; ncl < 2; ++ncl) {
        const int nc = 2 * nhf + ncl;
        const uint4* gp = g_Wa4 + (nc * 8) * 256;
        float ya0[8][4], ya1[8][4];
#pragma unroll
        for (int i = 0; i < 8; ++i)
#pragma unroll
            for (int j = 0; j < 4; ++j) { ya0[i][j] = 0.f; ya1[i][j] = 0.f; }

#pragma unroll
        for (int kpp = 0; kpp < 4; ++kpp) {
            const int kpA = 2 * kpp, kpB = 2 * kpp + 1;
#pragma unroll
            for (int i = 0; i < 8; ++i) vn[i] = __ldg(gp + kpB * 256 + i * 32 + lane);
            p1_block(ya0, ya1, Xb0, Xb1, v, kpA, g, tg, gok);
            if (kpp < 3) {
#pragma unroll
                for (int i = 0; i < 8; ++i)
                    v[i] = __ldg(gp + (kpB + 1) * 256 + i * 32 + lane);
            } else if (ncl == 0) {
                const uint4* gpn = g_Wa4 + ((2 * nhf + 1) * 8) * 256;
#pragma unroll
                for (int i = 0; i < 8; ++i) v[i] = __ldg(gpn + i * 32 + lane);
            } else {
                pf_wb(vA, 0, 0, nhf, lane);   // phase-2 (st=0, s=0)
            }
            p1_block(ya0, ya1, Xb0, Xb1, vn, kpB, g, tg, gok);
        }

        // flush: Y -> Cb (tf32), S += Y * X^T  (sequential tokens, warp-private Cb)
        __syncwarp();
#pragma unroll
        for (int nt = 0; nt < 8; ++nt) {
            int c = nt * 8 + 2 * tg;
            *(float2*)(Cb + g * SCB + c) = make_float2(f2tff(ya0[nt][0]), f2tff(ya0[nt][1]));
            *(float2*)(Cb + (g + 8) * SCB + c) = make_float2(f2tff(ya0[nt][2]), f2tff(ya0[nt][3]));
        }
        __syncwarp();
#pragma unroll
        for (int ks = 0; ks < 8; ++ks) {
            int xc = nc * 64 + ks * 8;
            uint32_t a0 = __float_as_uint(Cb[g * SCB + ks * 8 + tg]);
            uint32_t a1 = __float_as_uint(Cb[(g + 8) * SCB + ks * 8 + tg]);
            uint32_t a2 = __float_as_uint(Cb[g * SCB + ks * 8 + tg + 4]);
            uint32_t a3 = __float_as_uint(Cb[(g + 8) * SCB + ks * 8 + tg + 4]);
            uint32_t b0 = __float_as_uint(Xs0[g * SXR + xc + tg]);
            uint32_t b1 = __float_as_uint(Xs0[g * SXR + xc + tg + 4]);
            mma8(sa, a0, a1, a2, a3, b0, b1);
            uint32_t c0 = gok ? __float_as_uint(Xs0[(g + 8) * SXR + xc + tg]) : 0u;
            uint32_t c1 = gok ? __float_as_uint(Xs0[(g + 8) * SXR + xc + tg + 4]) : 0u;
            mma8(sb, a0, a1, a2, a3, c0, c1);
        }
        __syncwarp();
#pragma unroll
        for (int nt = 0; nt < 8; ++nt) {
            int c = nt * 8 + 2 * tg;
            *(float2*)(Cb + g * SCB + c) = make_float2(f2tff(ya1[nt][0]), f2tff(ya1[nt][1]));
            *(float2*)(Cb + (g + 8) * SCB + c) = make_float2(f2tff(ya1[nt][2]), f2tff(ya1[nt][3]));
        }
        __syncwarp();
#pragma unroll
        for (int ks = 0; ks < 8; ++ks) {
            int xc = nc * 64 + ks * 8;
            uint32_t a0 = __float_as_uint(Cb[g * SCB + ks * 8 + tg]);
            uint32_t a1 = __float_as_uint(Cb[(g + 8) * SCB + ks * 8 + tg]);
            uint32_t a2 = __float_as_uint(Cb[g * SCB + ks * 8 + tg + 4]);
            uint32_t a3 = __float_as_uint(Cb[(g + 8) * SCB + ks * 8 + tg + 4]);
            uint32_t b0 = __float_as_uint(Xs1[g * SXR + xc + tg]);
            uint32_t b1 = __float_as_uint(Xs1[g * SXR + xc + tg + 4]);
            mma8(sc, a0, a1, a2, a3, b0, b1);
            uint32_t c0 = gok ? __float_as_uint(Xs1[(g + 8) * SXR + xc + tg]) : 0u;
            uint32_t c1 = gok ? __float_as_uint(Xs1[(g + 8) * SXR + xc + tg + 4]) : 0u;
            mma8(sd, a0, a1, a2, a3, c0, c1);
        }
        __syncwarp();
    }

    // ---------- S cross-half reduction + softmax (vA load in flight) --------
    __syncthreads();
    {
        float* my = smem + SM_C + (w * 32 + lane) * 16;
#pragma unroll
        for (int i = 0; i < 4; ++i) {
            my[i] = sa[i]; my[4 + i] = sb[i]; my[8 + i] = sc[i]; my[12 + i] = sd[i];
        }
    }
    __syncthreads();
    if (nhf == 0) {
        const float* ot = smem + SM_C + ((w ^ 1) * 32 + lane) * 16;
#pragma unroll
        for (int i = 0; i < 4; ++i) {
            sa[i] += ot[i]; sb[i] += ot[4 + i]; sc[i] += ot[8 + i]; sd[i] += ot[12 + i];
        }
        softmax_sig(sa, sb, As0, sig, g, tg);
        softmax_sig(sc, sd, As1, sig, g, tg);
    }
    __syncthreads();   // As visible to both halves

    // ===== phase 2: Z = (sig*A) X (tf32, regs), R_half = Z Wb (bf16) =====
    float ra0[16][4], ra1[16][4];
#pragma unroll
    for (int i = 0; i < 16; ++i)
#pragma unroll
        for (int j = 0; j < 4; ++j) { ra0[i][j] = 0.f; ra1[i][j] = 0.f; }

    for (int dc = 0; dc < 4; ++dc) {
        // Zchunk per token (registers), then pack to bf16x2 frags
        uint32_t zp0[16], zp1[16];
        {
            float za0[8][4], za1[8][4];
#pragma unroll
            for (int tok = 0; tok < 2; ++tok) {
                const float* Asx = tok ? As1 : As0;
                const float* Xsx = tok ? Xs1 : Xs0;
                float (*za)[4] = tok ? za1 : za0;
#pragma unroll
                for (int i = 0; i < 8; ++i)
#pragma unroll
                    for (int j = 0; j < 4; ++j) za[i][j] = 0.f;
#pragma unroll
                for (int ks = 0; ks < 2; ++ks) {
                    uint32_t a0 = __float_as_uint(Asx[g * SAT + ks * 8 + tg]);
                    uint32_t a1 = __float_as_uint(Asx[(g + 8) * SAT + ks * 8 + tg]);
                    uint32_t a2 = __float_as_uint(Asx[g * SAT + ks * 8 + tg + 4]);
                    uint32_t a3 = __float_as_uint(Asx[(g + 8) * SAT + ks * 8 + tg + 4]);
                    int r0w = ks * 8 + tg;
                    int r1w = ks * 8 + tg + 4;
                    bool rok = r1w < 13;
#pragma unroll
                    for (int nt = 0; nt < 8; ++nt) {
                        int xc = dc * 64 + nt * 8 + g;
                        uint32_t b0 = __float_as_uint(Xsx[r0w * SXR + xc]);
                        uint32_t b1 = rok ? __float_as_uint(Xsx[r1w * SXR + xc]) : 0u;
                        mma8(za[nt], a0, a1, a2, a3, b0, b1);
                    }
                }
            }
#pragma unroll
            for (int t = 0; t < 8; ++t) {
                zp0[2 * t]     = pkr(za0[t][0], za0[t][1]);
                zp0[2 * t + 1] = pkr(za0[t][2], za0[t][3]);
                zp1[2 * t]     = pkr(za1[t][0], za1[t][1]);
                zp1[2 * t + 1] = pkr(za1[t][2], za1[t][3]);
            }
        }

        const int st0 = dc * 2;
        pf_wb(vB, st0, 1, nhf, lane);
        p2_block(ra0, ra1, zp0, zp1, vA, 0);         // (kp2=0, s=0)
        pf_wb(vA, st0 + 1, 0, nhf, lane);
        p2_block(ra0, ra1, zp0, zp1, vB, 2);         // (0, 1)
        pf_wb(vB, st0 + 1, 1, nhf, lane);
        p2_block(ra0, ra1, zp0, zp1, vA, 4);         // (1, 0)
        if (dc < 3) pf_wb(vA, st0 + 2, 0, nhf, lane);
        p2_block(ra0, ra1, zp0, zp1, vB, 6);         // (1, 1)
    }

    // ---- epilogue: residual via tf32 mma folded into ra, then store ----
    {
        uint32_t wl[2][4];
#pragma unroll
        for (int ks = 0; ks < 2; ++ks) {
            int k0 = ks * 8 + tg, k1 = ks * 8 + tg + 4;
            wl[ks][0] = __float_as_uint(Wls[k0 * 16 + g]);
            wl[ks][1] = __float_as_uint(Wls[k0 * 16 + g + 8]);
            wl[ks][2] = __float_as_uint(Wls[k1 * 16 + g]);
            wl[ks][3] = __float_as_uint(Wls[k1 * 16 + g + 8]);
        }
#pragma unroll
        for (int nt = 0; nt < 16; ++nt) {
            int cn = nhf * 128 + nt * 8 + g;
#pragma unroll
            for (int ks = 0; ks < 2; ++ks) {
                int r0w = ks * 8 + tg;
                int r1w = ks * 8 + tg + 4;
                bool rok = r1w < 13;
                uint32_t b0 = __float_as_uint(Xs0[r0w * SXR + cn]);
                uint32_t b1 = rok ? __float_as_uint(Xs0[r1w * SXR + cn]) : 0u;
                mma8(ra0[nt], wl[ks][0], wl[ks][1], wl[ks][2], wl[ks][3], b0, b1);
                b0 = __float_as_uint(Xs1[r0w * SXR + cn]);
                b1 = rok ? __float_as_uint(Xs1[r1w * SXR + cn]) : 0u;
                mma8(ra1[nt], wl[ks][0], wl[ks][1], wl[ks][2], wl[ks][3], b0, b1);
            }
        }
    }
    const long obase0 = (tokbase + 2 * tp) * 3328;
#pragma unroll
    for (int nt = 0; nt < 16; ++nt) {
        int c = nhf * 128 + nt * 8 + 2 * tg;
        *(float2*)(out + obase0 + g * 256 + c) = make_float2(ra0[nt][0], ra0[nt][1]);
        *(float2*)(out + obase0 + 3328 + g * 256 + c) = make_float2(ra1[nt][0], ra1[nt][1]);
        if (gok) {
            *(float2*)(out + obase0 + (g + 8) * 256 + c) = make_float2(ra0[nt][2], ra0[nt][3]);
            *(float2*)(out + obase0 + 3328 + (g + 8) * 256 + c) = make_float2(ra1[nt][2], ra1[nt][3]);
        }
    }
}

// ------------------------------ launch --------------------------------------
extern "C" void kernel_launch(void* const* d_in, const int* in_sizes, int n_in,
                              void* d_out, int out_size) {
    const float* h    = (const float*)d_in[0];
    const float* Wq   = (const float*)d_in[1];
    const float* Wk   = (const float*)d_in[2];
    const float* Wv   = (const float*)d_in[3];
    const float* Wo   = (const float*)d_in[4];
    const float* Wlat = (const float*)d_in[5];
    const float* gate = (const float*)d_in[6];
    float* out = (float*)d_out;

    static bool attr_done = false;
    if (!attr_done) {
        cudaFuncSetAttribute(lc_main, cudaFuncAttributeMaxDynamicSharedMemorySize, SMEM_BYTES);
        attr_done = true;
    }

    lc_setup<<<dim3(16, 16, 2), dim3(16, 16)>>>(Wq, Wk, Wv, Wo);
    lc_main<<<4096, THREADS, SMEM_BYTES>>>(h, Wlat, gate, out);
}

// round 17
// speedup vs baseline: 1.9388x; 1.0077x over previous
#include <cuda_runtime.h>
#include <cuda_bf16.h>
#include <cstdint>

// out = Wlat^T X  +  sigmoid(gate) * softmax(X Wa X^T) X Wb
//   Wa[k][n] = sum_e Wq[e,k] Wk[e,n] / 16    (bf16 fragment-packed, g_Wa4)
//   Wb[k][n] = sum_e Wo[n,e] Wv[e,k]         (bf16 fragment-packed, g_Wb4)
// 128 thr/CTA, 2 CTA/SM, 4 tokens/CTA. Warp = (token-pair tp, N-half nhf).
// Weight fragments read from GMEM via LDG.128 with register double-buffer
// prefetch; same-nhf warp pairs LOCKSTEPPED via named barriers so the
// second reader hits L1D. Output stored with __stcs (evict-first) to keep
// weight lines cached. X pre-converted at load: tf32 copy (Xs) + bf16x2
// copy (Xb). Big GEMMs bf16 m16n8k16; S, Z, residual tf32 m16n8k8.

#define THREADS 128
#define SXR 260        // X tf32 smem row stride
#define XTOK 3380      // 13*260
#define XBR 132        // X bf16 copy row stride in uint32
#define XBTOK 1716     // 13*132 uint32 per token
#define SCB 68         // phase-1 chunk buffer stride (per-warp)
#define SAT 20         // attn stride
#define ATOK 320       // 16*20

#define SM_X 0                 // 4*3380 = 13520 floats
#define SM_C 13520             // 4*1088 = 4352
#define SM_A 17872             // 4*320 = 1280
#define SM_W 19152             // 256
#define SM_XB 19408            // 4*1716 = 6864
#define SMEM_FLOATS 26272
#define SMEM_BYTES (SMEM_FLOATS * 4)   // 105088 -> 2 CTAs/SM

#define PAIR_BAR(nhf) asm volatile("bar.sync %0, %1;" :: "r"(1 + (nhf)), "r"(64) : "memory")

__device__ uint4 g_Wa4[32 * 256];
__device__ uint4 g_Wb4[16 * 512];

__device__ __forceinline__ uint32_t f2tf(float x) {
    uint32_t r;
    asm("cvt.rna.tf32.f32 %0, %1;" : "=r"(r) : "f"(x));
    return r;
}
__device__ __forceinline__ float f2tff(float x) {
    return __uint_as_float(f2tf(x));
}
__device__ __forceinline__ uint32_t pkr(float lo, float hi) {
    uint32_t r;
    asm("cvt.rn.bf16x2.f32 %0, %1, %2;" : "=r"(r) : "f"(hi), "f"(lo));
    return r;
}

__device__ __forceinline__ void mma8(float* d,
                                     uint32_t a0, uint32_t a1, uint32_t a2, uint32_t a3,
                                     uint32_t b0, uint32_t b1) {
    asm volatile(
        "mma.sync.aligned.m16n8k8.row.col.f32.tf32.tf32.f32 "
        "{%0,%1,%2,%3},{%4,%5,%6,%7},{%8,%9},{%0,%1,%2,%3};\n"
        : "+f"(d[0]), "+f"(d[1]), "+f"(d[2]), "+f"(d[3])
        : "r"(a0), "r"(a1), "r"(a2), "r"(a3), "r"(b0), "r"(b1));
}
__device__ __forceinline__ void mmab(float* d,
                                     uint32_t a0, uint32_t a1, uint32_t a2, uint32_t a3,
                                     uint32_t b0, uint32_t b1) {
    asm volatile(
        "mma.sync.aligned.m16n8k16.row.col.f32.bf16.bf16.f32 "
        "{%0,%1,%2,%3},{%4,%5,%6,%7},{%8,%9},{%0,%1,%2,%3};\n"
        : "+f"(d[0]), "+f"(d[1]), "+f"(d[2]), "+f"(d[3])
        : "r"(a0), "r"(a1), "r"(a2), "r"(a3), "r"(b0), "r"(b1));
}

// ------------------------------- setup --------------------------------------
__global__ void lc_setup(const float* __restrict__ Wq, const float* __restrict__ Wk,
                         const float* __restrict__ Wv, const float* __restrict__ Wo) {
    __shared__ float sA[16][17], sB[16][17];
    const int tx = threadIdx.x, ty = threadIdx.y;
    const int k0 = blockIdx.x * 16, n0 = blockIdx.y * 16;
    const bool isA = (blockIdx.z == 0);
    float acc = 0.f;
    for (int e0 = 0; e0 < 256; e0 += 16) {
        const float* Mp = isA ? Wq : Wv;
        sA[ty][tx] = Mp[(e0 + ty) * 256 + k0 + tx];
        if (isA) sB[ty][tx] = Wk[(e0 + ty) * 256 + n0 + tx];
        else     sB[tx][ty] = Wo[(n0 + ty) * 256 + e0 + tx];
        __syncthreads();
#pragma unroll
        for (int e = 0; e < 16; ++e) acc += sA[e][tx] * sB[e][ty];
        __syncthreads();
    }
    const int k = k0 + tx, n = n0 + ty;
    const int r = k & 31, s = r >> 4, rr = r & 15;
    const int half = rr >> 3, tg = (rr & 7) >> 1, j = rr & 1;
    if (isA) {
        acc *= (1.0f / 16.0f);
        int kp = k >> 5;
        int nc = n >> 6, nn = n & 63, nt = nn >> 3, g = nn & 7, q = nt >> 1;
        int u32idx = ((s * 4 + q) * 32 + g * 4 + tg) * 4 + (nt & 1) * 2 + half;
        ((__nv_bfloat16*)g_Wa4)[((nc * 8 + kp) * 1024 + u32idx) * 2 + j] =
            __float2bfloat16(acc);
    } else {
        int dc = k >> 6, kp2 = (k >> 5) & 1;
        int nh = n >> 7, nn = n & 127, nt = nn >> 3, g = nn & 7, q = nt >> 1;
        int u32idx = ((s * 8 + q) * 32 + g * 4 + tg) * 4 + (nt & 1) * 2 + half;
        ((__nv_bfloat16*)g_Wb4)[((nh * 8 + dc * 2 + kp2) * 2048 + u32idx) * 2 + j] =
            __float2bfloat16(acc);
    }
}

// ---------------------- softmax (sig folded) --------------------------------
__device__ __forceinline__ void softmax_sig(const float* s0, const float* s1,
                                            float* As, float sig, int g, int tg) {
    int c0 = 2 * tg, c1 = 2 * tg + 1, c2 = 8 + 2 * tg, c3 = 9 + 2 * tg;
    bool v0 = c0 < 13, v1 = c1 < 13, v2 = c2 < 13, v3 = c3 < 13;
    const float NEG = -1e30f;
    float m0 = fmaxf(fmaxf(v0 ? s0[0] : NEG, v1 ? s0[1] : NEG),
                     fmaxf(v2 ? s1[0] : NEG, v3 ? s1[1] : NEG));
    float m1 = fmaxf(fmaxf(v0 ? s0[2] : NEG, v1 ? s0[3] : NEG),
                     fmaxf(v2 ? s1[2] : NEG, v3 ? s1[3] : NEG));
    m0 = fmaxf(m0, __shfl_xor_sync(0xffffffffu, m0, 1));
    m0 = fmaxf(m0, __shfl_xor_sync(0xffffffffu, m0, 2));
    m1 = fmaxf(m1, __shfl_xor_sync(0xffffffffu, m1, 1));
    m1 = fmaxf(m1, __shfl_xor_sync(0xffffffffu, m1, 2));
    float e00 = v0 ? __expf(s0[0] - m0) : 0.f;
    float e01 = v1 ? __expf(s0[1] - m0) : 0.f;
    float e02 = v2 ? __expf(s1[0] - m0) : 0.f;
    float e03 = v3 ? __expf(s1[1] - m0) : 0.f;
    float e10 = v0 ? __expf(s0[2] - m1) : 0.f;
    float e11 = v1 ? __expf(s0[3] - m1) : 0.f;
    float e12 = v2 ? __expf(s1[2] - m1) : 0.f;
    float e13 = v3 ? __expf(s1[3] - m1) : 0.f;
    float d0 = e00 + e01 + e02 + e03;
    float d1 = e10 + e11 + e12 + e13;
    d0 += __shfl_xor_sync(0xffffffffu, d0, 1);
    d0 += __shfl_xor_sync(0xffffffffu, d0, 2);
    d1 += __shfl_xor_sync(0xffffffffu, d1, 1);
    d1 += __shfl_xor_sync(0xffffffffu, d1, 2);
    float r0 = sig / d0, r1 = sig / d1;
    As[g * SAT + c0]       = f2tff(e00 * r0);
    As[g * SAT + c1]       = f2tff(e01 * r0);
    As[g * SAT + c2]       = f2tff(e02 * r0);
    As[g * SAT + c3]       = f2tff(e03 * r0);
    As[(g + 8) * SAT + c0] = f2tff(e10 * r1);
    As[(g + 8) * SAT + c1] = f2tff(e11 * r1);
    As[(g + 8) * SAT + c2] = f2tff(e12 * r1);
    As[(g + 8) * SAT + c3] = f2tff(e13 * r1);
}

// phase-1 mma block: one 32-row K panel against both tokens' bf16 X
__device__ __forceinline__ void p1_block(float (*ya0)[4], float (*ya1)[4],
                                         const uint32_t* Xb0, const uint32_t* Xb1,
                                         const uint4* v, int kp,
                                         int g, int tg, bool gok) {
#pragma unroll
    for (int s = 0; s < 2; ++s) {
        int kc2 = kp * 16 + s * 8;
        uint32_t a00 = Xb0[g * XBR + kc2 + tg];
        uint32_t a01 = gok ? Xb0[(g + 8) * XBR + kc2 + tg] : 0u;
        uint32_t a02 = Xb0[g * XBR + kc2 + 4 + tg];
        uint32_t a03 = gok ? Xb0[(g + 8) * XBR + kc2 + 4 + tg] : 0u;
        uint32_t a10 = Xb1[g * XBR + kc2 + tg];
        uint32_t a11 = gok ? Xb1[(g + 8) * XBR + kc2 + tg] : 0u;
        uint32_t a12 = Xb1[g * XBR + kc2 + 4 + tg];
        uint32_t a13 = gok ? Xb1[(g + 8) * XBR + kc2 + 4 + tg] : 0u;
#pragma unroll
        for (int q = 0; q < 4; ++q) {
            uint4 vv = v[s * 4 + q];
            mmab(ya0[2 * q],     a00, a01, a02, a03, vv.x, vv.y);
            mmab(ya0[2 * q + 1], a00, a01, a02, a03, vv.z, vv.w);
            mmab(ya1[2 * q],     a10, a11, a12, a13, vv.x, vv.y);
            mmab(ya1[2 * q + 1], a10, a11, a12, a13, vv.z, vv.w);
        }
    }
}

// phase-2 mma half-panel: 8 weight frag vectors vs packed Z frags at t0
__device__ __forceinline__ void p2_block(float (*ra0)[4], float (*ra1)[4],
                                         const uint32_t* zp0, const uint32_t* zp1,
                                         const uint4* v, int t0) {
    uint32_t a00 = zp0[2 * t0], a01 = zp0[2 * t0 + 1];
    uint32_t a02 = zp0[2 * t0 + 2], a03 = zp0[2 * t0 + 3];
    uint32_t a10 = zp1[2 * t0], a11 = zp1[2 * t0 + 1];
    uint32_t a12 = zp1[2 * t0 + 2], a13 = zp1[2 * t0 + 3];
#pragma unroll
    for (int q = 0; q < 8; ++q) {
        uint4 vv = v[q];
        mmab(ra0[2 * q],     a00, a01, a02, a03, vv.x, vv.y);
        mmab(ra0[2 * q + 1], a00, a01, a02, a03, vv.z, vv.w);
        mmab(ra1[2 * q],     a10, a11, a12, a13, vv.x, vv.y);
        mmab(ra1[2 * q + 1], a10, a11, a12, a13, vv.z, vv.w);
    }
}

__device__ __forceinline__ void pf_wb(uint4* dst, int st, int s, int nhf, int lane) {
    const uint4* gp = g_Wb4 + (nhf * 8 + st) * 512 + s * 256;
#pragma unroll
    for (int i = 0; i < 8; ++i) dst[i] = __ldg(gp + i * 32 + lane);
}

// -------------------------------- main --------------------------------------
__global__ void __launch_bounds__(THREADS, 2)
lc_main(const float* __restrict__ hsrc, const float* __restrict__ Wlat,
        const float* __restrict__ gate, float* __restrict__ out) {
    extern __shared__ float smem[];
    const int tid = threadIdx.x;
    const int w = tid >> 5, lane = tid & 31;
    const int g = lane >> 2, tg = lane & 3;
    const int tp = w >> 1, nhf = w & 1;
    const long tokbase = (long)blockIdx.x * 4;
    const bool gok = (g < 5);

    float* Xs0 = smem + SM_X + (2 * tp) * XTOK;      // tf32-preconverted X
    float* Xs1 = Xs0 + XTOK;
    float* Cb = smem + SM_C + w * 1088;
    float* As0 = smem + SM_A + (2 * tp) * ATOK;
    float* As1 = As0 + ATOK;
    float* Wls = smem + SM_W;
    uint32_t* XbBase = (uint32_t*)(smem + SM_XB);
    const uint32_t* Xb0 = XbBase + (2 * tp) * XBTOK;
    const uint32_t* Xb1 = Xb0 + XBTOK;

    uint4 v[8], vn[8];        // phase-1 prefetch buffers
    uint4 vA[8], vB[8];       // phase-2 prefetch buffers

    // preload first phase-1 panel (hidden by X load + barrier)
    {
        const uint4* gp0 = g_Wa4 + (2 * nhf * 8) * 256;
#pragma unroll
        for (int i = 0; i < 8; ++i) v[i] = __ldg(gp0 + i * 32 + lane);
    }

    // ---- load X: warp w loads token w; writes tf32 + packed-bf16 copies ----
    {
        const float* src = hsrc + (tokbase + w) * 3328;
        float* dst = smem + SM_X + w * XTOK;
        uint32_t* bdst = XbBase + w * XBTOK;
        for (int i = lane; i < 832; i += 32) {
            int row = i >> 6, c4 = (i & 63) << 2;
            float4 vv = *(const float4*)(src + row * 256 + c4);
            float4 tv;
            tv.x = f2tff(vv.x); tv.y = f2tff(vv.y);
            tv.z = f2tff(vv.z); tv.w = f2tff(vv.w);
            *(float4*)(dst + row * SXR + c4) = tv;
            uint2 bp;
            bp.x = pkr(vv.x, vv.y);
            bp.y = pkr(vv.z, vv.w);
            *(uint2*)(bdst + row * XBR + (c4 >> 1)) = bp;
        }
    }
    for (int idx = tid; idx < 256; idx += THREADS) {
        int p = idx >> 4, r = idx & 15;
        Wls[idx] = (p < 13 && r < 13) ? f2tff(Wlat[p * 13 + r]) : 0.f;
    }
    float sig;
    { float gv = gate[0]; sig = 1.f / (1.f + __expf(-gv)); }
    __syncthreads();

    // =========== phase 1: Y = X Wa (bf16, half's nc), S partial ===========
    float sa[4] = {0, 0, 0, 0}, sb[4] = {0, 0, 0, 0};
    float sc[4] = {0, 0, 0, 0}, sd[4] = {0, 0, 0, 0};

    for (int ncl = 0; ncl < 2; ++ncl) {
        const int nc = 2 * nhf + ncl;
        const uint4* gp = g_Wa4 + (nc * 8) * 256;
        float ya0[8][4], ya1[8][4];
#pragma unroll
        for (int i = 0; i < 8; ++i)
#pragma unroll
            for (int j = 0; j < 4; ++j) { ya0[i][j] = 0.f; ya1[i][j] = 0.f; }

#pragma unroll
        for (int kpp = 0; kpp < 4; ++kpp) {
            PAIR_BAR(nhf);   // lockstep same-nhf warp pair -> partner LDG hits L1
            const int kpA = 2 * kpp, kpB = 2 * kpp + 1;
#pragma unroll
            for (int i = 0; i < 8; ++i) vn[i] = __ldg(gp + kpB * 256 + i * 32 + lane);
            p1_block(ya0, ya1, Xb0, Xb1, v, kpA, g, tg, gok);
            if (kpp < 3) {
#pragma unroll
                for (int i = 0; i < 8; ++i)
                    v[i] = __ldg(gp + (kpB + 1) * 256 + i * 32 + lane);
            } else if (ncl == 0) {
                const uint4* gpn = g_Wa4 + ((2 * nhf + 1) * 8) * 256;
#pragma unroll
                for (int i = 0; i < 8; ++i) v[i] = __ldg(gpn + i * 32 + lane);
            } else {
                pf_wb(vA, 0, 0, nhf, lane);   // phase-2 (st=0, s=0)
            }
            p1_block(ya0, ya1, Xb0, Xb1, vn, kpB, g, tg, gok);
        }

        // flush: Y -> Cb (tf32), S += Y * X^T  (sequential tokens, warp-private Cb)
        __syncwarp();
#pragma unroll
        for (int nt = 0; nt < 8; ++nt) {
            int c = nt * 8 + 2 * tg;
            *(float2*)(Cb + g * SCB + c) = make_float2(f2tff(ya0[nt][0]), f2tff(ya0[nt][1]));
            *(float2*)(Cb + (g + 8) * SCB + c) = make_float2(f2tff(ya0[nt][2]), f2tff(ya0[nt][3]));
        }
        __syncwarp();
#pragma unroll
        for (int ks = 0; ks < 8; ++ks) {
            int xc = nc * 64 + ks * 8;
            uint32_t a0 = __float_as_uint(Cb[g * SCB + ks * 8 + tg]);
            uint32_t a1 = __float_as_uint(Cb[(g + 8) * SCB + ks * 8 + tg]);
            uint32_t a2 = __float_as_uint(Cb[g * SCB + ks * 8 + tg + 4]);
            uint32_t a3 = __float_as_uint(Cb[(g + 8) * SCB + ks * 8 + tg + 4]);
            uint32_t b0 = __float_as_uint(Xs0[g * SXR + xc + tg]);
            uint32_t b1 = __float_as_uint(Xs0[g * SXR + xc + tg + 4]);
            mma8(sa, a0, a1, a2, a3, b0, b1);
            uint32_t c0 = gok ? __float_as_uint(Xs0[(g + 8) * SXR + xc + tg]) : 0u;
            uint32_t c1 = gok ? __float_as_uint(Xs0[(g + 8) * SXR + xc + tg + 4]) : 0u;
            mma8(sb, a0, a1, a2, a3, c0, c1);
        }
        __syncwarp();
#pragma unroll
        for (int nt = 0; nt < 8; ++nt) {
            int c = nt * 8 + 2 * tg;
            *(float2*)(Cb + g * SCB + c) = make_float2(f2tff(ya1[nt][0]), f2tff(ya1[nt][1]));
            *(float2*)(Cb + (g + 8) * SCB + c) = make_float2(f2tff(ya1[nt][2]), f2tff(ya1[nt][3]));
        }
        __syncwarp();
#pragma unroll
        for (int ks = 0; ks < 8; ++ks) {
            int xc = nc * 64 + ks * 8;
            uint32_t a0 = __float_as_uint(Cb[g * SCB + ks * 8 + tg]);
            uint32_t a1 = __float_as_uint(Cb[(g + 8) * SCB + ks * 8 + tg]);
            uint32_t a2 = __float_as_uint(Cb[g * SCB + ks * 8 + tg + 4]);
            uint32_t a3 = __float_as_uint(Cb[(g + 8) * SCB + ks * 8 + tg + 4]);
            uint32_t b0 = __float_as_uint(Xs1[g * SXR + xc + tg]);
            uint32_t b1 = __float_as_uint(Xs1[g * SXR + xc + tg + 4]);
            mma8(sc, a0, a1, a2, a3, b0, b1);
            uint32_t c0 = gok ? __float_as_uint(Xs1[(g + 8) * SXR + xc + tg]) : 0u;
            uint32_t c1 = gok ? __float_as_uint(Xs1[(g + 8) * SXR + xc + tg + 4]) : 0u;
            mma8(sd, a0, a1, a2, a3, c0, c1);
        }
        __syncwarp();
    }

    // ---------- S cross-half reduction + softmax (vA load in flight) --------
    __syncthreads();
    {
        float* my = smem + SM_C + (w * 32 + lane) * 16;
#pragma unroll
        for (int i = 0; i < 4; ++i) {
            my[i] = sa[i]; my[4 + i] = sb[i]; my[8 + i] = sc[i]; my[12 + i] = sd[i];
        }
    }
    __syncthreads();
    if (nhf == 0) {
        const float* ot = smem + SM_C + ((w ^ 1) * 32 + lane) * 16;
#pragma unroll
        for (int i = 0; i < 4; ++i) {
            sa[i] += ot[i]; sb[i] += ot[4 + i]; sc[i] += ot[8 + i]; sd[i] += ot[12 + i];
        }
        softmax_sig(sa, sb, As0, sig, g, tg);
        softmax_sig(sc, sd, As1, sig, g, tg);
    }
    __syncthreads();   // As visible to both halves

    // ===== phase 2: Z = (sig*A) X (tf32, regs), R_half = Z Wb (bf16) =====
    float ra0[16][4], ra1[16][4];
#pragma unroll
    for (int i = 0; i < 16; ++i)
#pragma unroll
        for (int j = 0; j < 4; ++j) { ra0[i][j] = 0.f; ra1[i][j] = 0.f; }

    for (int dc = 0; dc < 4; ++dc) {
        // Zchunk per token (registers), then pack to bf16x2 frags
        uint32_t zp0[16], zp1[16];
        {
            float za0[8][4], za1[8][4];
#pragma unroll
            for (int tok = 0; tok < 2; ++tok) {
                const float* Asx = tok ? As1 : As0;
                const float* Xsx = tok ? Xs1 : Xs0;
                float (*za)[4] = tok ? za1 : za0;
#pragma unroll
                for (int i = 0; i < 8; ++i)
#pragma unroll
                    for (int j = 0; j < 4; ++j) za[i][j] = 0.f;
#pragma unroll
                for (int ks = 0; ks < 2; ++ks) {
                    uint32_t a0 = __float_as_uint(Asx[g * SAT + ks * 8 + tg]);
                    uint32_t a1 = __float_as_uint(Asx[(g + 8) * SAT + ks * 8 + tg]);
                    uint32_t a2 = __float_as_uint(Asx[g * SAT + ks * 8 + tg + 4]);
                    uint32_t a3 = __float_as_uint(Asx[(g + 8) * SAT + ks * 8 + tg + 4]);
                    int r0w = ks * 8 + tg;
                    int r1w = ks * 8 + tg + 4;
                    bool rok = r1w < 13;
#pragma unroll
                    for (int nt = 0; nt < 8; ++nt) {
                        int xc = dc * 64 + nt * 8 + g;
                        uint32_t b0 = __float_as_uint(Xsx[r0w * SXR + xc]);
                        uint32_t b1 = rok ? __float_as_uint(Xsx[r1w * SXR + xc]) : 0u;
                        mma8(za[nt], a0, a1, a2, a3, b0, b1);
                    }
                }
            }
#pragma unroll
            for (int t = 0; t < 8; ++t) {
                zp0[2 * t]     = pkr(za0[t][0], za0[t][1]);
                zp0[2 * t + 1] = pkr(za0[t][2], za0[t][3]);
                zp1[2 * t]     = pkr(za1[t][0], za1[t][1]);
                zp1[2 * t + 1] = pkr(za1[t][2], za1[t][3]);
            }
        }

        PAIR_BAR(nhf);   // lockstep same-nhf pair for the Wb LDG stream
        const int st0 = dc * 2;
        pf_wb(vB, st0, 1, nhf, lane);
        p2_block(ra0, ra1, zp0, zp1, vA, 0);         // (kp2=0, s=0)
        pf_wb(vA, st0 + 1, 0, nhf, lane);
        p2_block(ra0, ra1, zp0, zp1, vB, 2);         // (0, 1)
        pf_wb(vB, st0 + 1, 1, nhf, lane);
        p2_block(ra0, ra1, zp0, zp1, vA, 4);         // (1, 0)
        if (dc < 3) pf_wb(vA, st0 + 2, 0, nhf, lane);
        p2_block(ra0, ra1, zp0, zp1, vB, 6);         // (1, 1)
    }

    // ---- epilogue: residual via tf32 mma folded into ra, then store ----
    {
        uint32_t wl[2][4];
#pragma unroll
        for (int ks = 0; ks < 2; ++ks) {
            int k0 = ks * 8 + tg, k1 = ks * 8 + tg + 4;
            wl[ks][0] = __float_as_uint(Wls[k0 * 16 + g]);
            wl[ks][1] = __float_as_uint(Wls[k0 * 16 + g + 8]);
            wl[ks][2] = __float_as_uint(Wls[k1 * 16 + g]);
            wl[ks][3] = __float_as_uint(Wls[k1 * 16 + g + 8]);
        }
#pragma unroll
        for (int nt = 0; nt < 16; ++nt) {
            int cn = nhf * 128 + nt * 8 + g;
#pragma unroll
            for (int ks = 0; ks < 2; ++ks) {
                int r0w = ks * 8 + tg;
                int r1w = ks * 8 + tg + 4;
                bool rok = r1w < 13;
                uint32_t b0 = __float_as_uint(Xs0[r0w * SXR + cn]);
                uint32_t b1 = rok ? __float_as_uint(Xs0[r1w * SXR + cn]) : 0u;
                mma8(ra0[nt], wl[ks][0], wl[ks][1], wl[ks][2], wl[ks][3], b0, b1);
                b0 = __float_as_uint(Xs1[r0w * SXR + cn]);
                b1 = rok ? __float_as_uint(Xs1[r1w * SXR + cn]) : 0u;
                mma8(ra1[nt], wl[ks][0], wl[ks][1], wl[ks][2], wl[ks][3], b0, b1);
            }
        }
    }
    const long obase0 = (tokbase + 2 * tp) * 3328;
#pragma unroll
    for (int nt = 0; nt < 16; ++nt) {
        int c = nhf * 128 + nt * 8 + 2 * tg;
        __stcs((float2*)(out + obase0 + g * 256 + c), make_float2(ra0[nt][0], ra0[nt][1]));
        __stcs((float2*)(out + obase0 + 3328 + g * 256 + c), make_float2(ra1[nt][0], ra1[nt][1]));
        if (gok) {
            __stcs((float2*)(out + obase0 + (g + 8) * 256 + c), make_float2(ra0[nt][2], ra0[nt][3]));
            __stcs((float2*)(out + obase0 + 3328 + (g + 8) * 256 + c), make_float2(ra1[nt][2], ra1[nt][3]));
        }
    }
}

// ------------------------------ launch --------------------------------------
extern "C" void kernel_launch(void* const* d_in, const int* in_sizes, int n_in,
                              void* d_out, int out_size) {
    const float* h    = (const float*)d_in[0];
    const float* Wq   = (const float*)d_in[1];
    const float* Wk   = (const float*)d_in[2];
    const float* Wv   = (const float*)d_in[3];
    const float* Wo   = (const float*)d_in[4];
    const float* Wlat = (const float*)d_in[5];
    const float* gate = (const float*)d_in[6];
    float* out = (float*)d_out;

    static bool attr_done = false;
    if (!attr_done) {
        cudaFuncSetAttribute(lc_main, cudaFuncAttributeMaxDynamicSharedMemorySize, SMEM_BYTES);
        attr_done = true;
    }

    lc_setup<<<dim3(16, 16, 2), dim3(16, 16)>>>(Wq, Wk, Wv, Wo);
    lc_main<<<4096, THREADS, SMEM_BYTES>>>(h, Wlat, gate, out);
}